// round 5
// baseline (speedup 1.0000x reference)
#include <cuda_runtime.h>
#include <mma.h>
#include <math.h>
#include <float.h>

using namespace nvcuda;

#define BB 2
#define NN 2048
#define CC 128
#define KK 16
#define BN (BB*NN)
#define PP (BB*NN*KK)
#define EPSF 1e-6f
#define BNEPS 1e-5f

// ---------------- scratch pool ----------------
constexpr long F_SRCD   = 0;
constexpr long F_DSTD   = F_SRCD   + (long)BN*CC;
constexpr long F_NSQS   = F_DSTD   + (long)BN*CC;
constexpr long F_NSQD   = F_NSQS   + BN;
constexpr long F_NRMS   = F_NSQD   + BN;
constexpr long F_NRMD   = F_NRMS   + BN;
constexpr long F_MAXDS  = F_NRMD   + BN;
constexpr long F_MAXSD  = F_MAXDS  + BN;
constexpr long F_NRM2S  = F_MAXSD  + BN;
constexpr long F_NRM2D  = F_NRM2S  + BN;
constexpr long F_SDC    = F_NRM2D  + BN;
constexpr long F_DSC    = F_SDC    + PP;
constexpr long F_SDN    = F_DSC    + PP;
constexpr long F_DSN    = F_SDN    + PP;
constexpr long F_STATS  = F_DSN    + PP;
constexpr long F_STATQ  = F_STATS  + 256;
constexpr long F_SC     = F_STATQ  + 256;
constexpr long F_SH     = F_SC     + 256;
constexpr long F_W2P    = F_SH     + 256;          // padded c2_W0 [128][144]
constexpr long F_IDX    = F_W2P    + 128*144;      // int
constexpr long F_SIDX   = F_IDX    + PP;
constexpr long F_DIDX   = F_SIDX   + PP;
constexpr long F_ATT    = F_DIDX   + PP;
constexpr long F_MB1    = F_ATT    + (long)BN*256;
constexpr long F_MB2    = F_MB1    + (long)BN*256;
constexpr long F_SRCNBR = F_MB2    + (long)BN*256;
constexpr long F_DSTNBR = F_SRCNBR + (long)BN*CC;
constexpr long F_INNER  = F_DSTNBR + (long)BN*CC;
constexpr long F_F      = F_INNER  + (long)BB*NN*NN;
constexpr long F_Y0     = F_F      + (long)PP*272;
constexpr long F_Y1     = F_Y0     + (long)PP*256;
constexpr long F_END    = F_Y1     + (long)PP*256;

__device__ __align__(128) float g_pool[F_END];

__device__ __forceinline__ void atomicMaxF(float* a, float v) {
    if (!(v < 0.f)) atomicMax((int*)a, __float_as_int(v));
    else            atomicMin((unsigned int*)a, __float_as_uint(v));
}

__global__ void k_fill(float* __restrict__ p, float v, int n) {
    int i = blockIdx.x * blockDim.x + threadIdx.x;
    if (i < n) p[i] = v;
}

__global__ void k_pad_w(const float* __restrict__ W, float* __restrict__ Wp) {
    int o = blockIdx.x; int k = threadIdx.x; // 144 threads
    Wp[o * 144 + k] = (k < 132) ? W[o * 132 + k] : 0.f;
}

// [B,C,N] -> [B,N,C] plus |.|^2 and |.|
__global__ void k_transpose_norm(const float* __restrict__ desc, float* __restrict__ dmat,
                                 float* __restrict__ nsq, float* __restrict__ nrm) {
    int bn = blockIdx.x; int b = bn >> 11; int n = bn & (NN - 1);
    int c = threadIdx.x;
    float v = desc[((long)b*CC + c)*NN + n];
    dmat[(long)bn*CC + c] = v;
    float s = v * v;
    #pragma unroll
    for (int o = 16; o > 0; o >>= 1) s += __shfl_down_sync(0xffffffffu, s, o);
    __shared__ float ps[4];
    if ((c & 31) == 0) ps[c >> 5] = s;
    __syncthreads();
    if (c == 0) { float t = ps[0]+ps[1]+ps[2]+ps[3]; nsq[bn] = t; nrm[bn] = sqrtf(t); }
}

__global__ void k_rownorm(const float* __restrict__ dmat, float* __restrict__ nrm) {
    int bn = blockIdx.x; int c = threadIdx.x;
    float v = dmat[(long)bn*CC + c];
    float s = v * v;
    #pragma unroll
    for (int o = 16; o > 0; o >>= 1) s += __shfl_down_sync(0xffffffffu, s, o);
    __shared__ float ps[4];
    if ((c & 31) == 0) ps[c >> 5] = s;
    __syncthreads();
    if (c == 0) nrm[bn] = sqrtf(ps[0]+ps[1]+ps[2]+ps[3]);
}

// ---------------- fp32 SIMT GEMM (KNN/cosine inner products only) ----------------
#define BT 128
#define GKS 8
#define SPAD 4

__global__ __launch_bounds__(256)
void k_gemm(const float* __restrict__ A, const float* __restrict__ Bm,
            float* __restrict__ Cm, int P, int O, int Kd,
            long sA, long sB, long sC) {
    A  += (long)blockIdx.z * sA;
    Bm += (long)blockIdx.z * sB;
    Cm += (long)blockIdx.z * sC;
    __shared__ __align__(16) float As[2][GKS][BT + SPAD];
    __shared__ __align__(16) float Bs[2][GKS][BT + SPAD];
    const int tx = threadIdx.x, ty = threadIdx.y;
    const int tid = ty * 16 + tx;
    const int rowBase = blockIdx.y * BT;
    const int colBase = blockIdx.x * BT;
    const int lr = tid >> 1;
    const int lk = (tid & 1) * 4;
    const float* Aptr = A  + (long)(rowBase + lr) * Kd + lk;
    const float* Bptr = Bm + (long)(colBase + lr) * Kd + lk;
    float acc[8][8] = {};
    const int nk = Kd / GKS;
    {
        float4 av = *reinterpret_cast<const float4*>(Aptr);
        float4 bv = *reinterpret_cast<const float4*>(Bptr);
        As[0][lk+0][lr] = av.x; As[0][lk+1][lr] = av.y;
        As[0][lk+2][lr] = av.z; As[0][lk+3][lr] = av.w;
        Bs[0][lk+0][lr] = bv.x; Bs[0][lk+1][lr] = bv.y;
        Bs[0][lk+2][lr] = bv.z; Bs[0][lk+3][lr] = bv.w;
    }
    __syncthreads();
    for (int kt = 0; kt < nk; kt++) {
        const int cur = kt & 1;
        float4 av2, bv2;
        const bool more = (kt + 1 < nk);
        if (more) {
            av2 = *reinterpret_cast<const float4*>(Aptr + (kt+1)*GKS);
            bv2 = *reinterpret_cast<const float4*>(Bptr + (kt+1)*GKS);
        }
        #pragma unroll
        for (int kk = 0; kk < GKS; kk++) {
            float4 a0 = *reinterpret_cast<const float4*>(&As[cur][kk][ty*4]);
            float4 a1 = *reinterpret_cast<const float4*>(&As[cur][kk][ty*4+64]);
            float4 b0 = *reinterpret_cast<const float4*>(&Bs[cur][kk][tx*4]);
            float4 b1 = *reinterpret_cast<const float4*>(&Bs[cur][kk][tx*4+64]);
            float a[8] = {a0.x,a0.y,a0.z,a0.w,a1.x,a1.y,a1.z,a1.w};
            float b[8] = {b0.x,b0.y,b0.z,b0.w,b1.x,b1.y,b1.z,b1.w};
            #pragma unroll
            for (int i = 0; i < 8; i++)
                #pragma unroll
                for (int j = 0; j < 8; j++)
                    acc[i][j] += a[i] * b[j];
        }
        if (more) {
            const int nb = cur ^ 1;
            As[nb][lk+0][lr] = av2.x; As[nb][lk+1][lr] = av2.y;
            As[nb][lk+2][lr] = av2.z; As[nb][lk+3][lr] = av2.w;
            Bs[nb][lk+0][lr] = bv2.x; Bs[nb][lk+1][lr] = bv2.y;
            Bs[nb][lk+2][lr] = bv2.z; Bs[nb][lk+3][lr] = bv2.w;
        }
        __syncthreads();
    }
    #pragma unroll
    for (int i = 0; i < 8; i++) {
        long r = rowBase + ty*4 + ((i < 4) ? i : 64 + i - 4);
        float4 v0 = {acc[i][0], acc[i][1], acc[i][2], acc[i][3]};
        float4 v1 = {acc[i][4], acc[i][5], acc[i][6], acc[i][7]};
        *reinterpret_cast<float4*>(&Cm[r * O + colBase + tx*4])      = v0;
        *reinterpret_cast<float4*>(&Cm[r * O + colBase + tx*4 + 64]) = v1;
    }
}

// ---------------- TF32 TC GEMM v2: 128x128 tile, double-buffered ----------------
// 8 warps as 4(M) x 2(N); warp tile 32x64 = 2x4 wmma m16n16k8.
// tf32 conversion happens once at staging. Requires P%128==0, O%128==0, Kd%16==0.
#define TCM 128
#define TCN 128
#define ALD 20
#define CLD 132
#define TC_DSM 67584   // max(40960 staging, 128*132*4 C staging)

extern __shared__ float dsm[];

__global__ __launch_bounds__(256)
void k_gemm_tc(const float* __restrict__ A, const float* __restrict__ Bm,
               float* __restrict__ Cm, int P, int O, int Kd,
               const float* __restrict__ scA, const float* __restrict__ shA,
               float* __restrict__ statS, float* __restrict__ statQ) {
    float* Asb[2] = { dsm,                dsm + TCM*ALD };
    float* Bsb[2] = { dsm + 2*TCM*ALD,    dsm + 3*TCM*ALD };
    float* Csm = dsm;
    __shared__ float cs[TCN], cq[TCN];

    const int tid = threadIdx.x;
    const int wid = tid >> 5;
    const int wm = wid & 3;
    const int wn = wid >> 2;
    const long rowBase = (long)blockIdx.y * TCM;
    const int colBase = blockIdx.x * TCN;
    const bool aff = (scA != nullptr);
    const bool stats = (statS != nullptr);
    if (stats && tid < TCN) { cs[tid] = 0.f; cq[tid] = 0.f; }

    // staging coords: 2 float4 per thread per matrix
    const int m0 = tid >> 2;            // e=0 row (0..63)
    const int kq = (tid & 3) * 4;

    wmma::fragment<wmma::accumulator, 16, 16, 8, float> c[2][4];
    #pragma unroll
    for (int i = 0; i < 2; i++)
        #pragma unroll
        for (int j = 0; j < 4; j++)
            wmma::fill_fragment(c[i][j], 0.f);

    const int nk = Kd / 16;

    auto loadA = [&](int k0, float4* pa) {
        #pragma unroll
        for (int e = 0; e < 2; e++) {
            int m = m0 + e * 64;
            float4 v = *reinterpret_cast<const float4*>(&A[(rowBase + m) * Kd + k0 + kq]);
            if (aff) {
                int gk = k0 + kq;
                v.x = fmaxf(v.x * scA[gk+0] + shA[gk+0], 0.f);
                v.y = fmaxf(v.y * scA[gk+1] + shA[gk+1], 0.f);
                v.z = fmaxf(v.z * scA[gk+2] + shA[gk+2], 0.f);
                v.w = fmaxf(v.w * scA[gk+3] + shA[gk+3], 0.f);
            }
            pa[e] = v;
        }
    };
    auto loadB = [&](int k0, float4* pb) {
        #pragma unroll
        for (int e = 0; e < 2; e++) {
            int m = m0 + e * 64;
            pb[e] = *reinterpret_cast<const float4*>(&Bm[(long)(colBase + m) * Kd + k0 + kq]);
        }
    };
    auto stage = [&](int buf, const float4* pa, const float4* pb) {
        #pragma unroll
        for (int e = 0; e < 2; e++) {
            int m = m0 + e * 64;
            float4 v = pa[e];
            v.x = wmma::__float_to_tf32(v.x); v.y = wmma::__float_to_tf32(v.y);
            v.z = wmma::__float_to_tf32(v.z); v.w = wmma::__float_to_tf32(v.w);
            *reinterpret_cast<float4*>(&Asb[buf][m * ALD + kq]) = v;
            float4 w = pb[e];
            w.x = wmma::__float_to_tf32(w.x); w.y = wmma::__float_to_tf32(w.y);
            w.z = wmma::__float_to_tf32(w.z); w.w = wmma::__float_to_tf32(w.w);
            *reinterpret_cast<float4*>(&Bsb[buf][m * ALD + kq]) = w;
        }
    };

    {
        float4 pa[2], pb[2];
        loadA(0, pa); loadB(0, pb);
        stage(0, pa, pb);
    }
    __syncthreads();

    for (int kc = 0; kc < nk; kc++) {
        const int cur = kc & 1;
        const bool more = (kc + 1 < nk);
        float4 pa[2], pb[2];
        if (more) { loadA((kc+1)*16, pa); loadB((kc+1)*16, pb); }
        #pragma unroll
        for (int ks = 0; ks < 2; ks++) {
            wmma::fragment<wmma::matrix_a, 16, 16, 8, wmma::precision::tf32, wmma::row_major> a[2];
            wmma::fragment<wmma::matrix_b, 16, 16, 8, wmma::precision::tf32, wmma::col_major> b[4];
            #pragma unroll
            for (int i = 0; i < 2; i++)
                wmma::load_matrix_sync(a[i], &Asb[cur][(wm*32 + i*16) * ALD + ks*8], ALD);
            #pragma unroll
            for (int j = 0; j < 4; j++)
                wmma::load_matrix_sync(b[j], &Bsb[cur][(wn*64 + j*16) * ALD + ks*8], ALD);
            #pragma unroll
            for (int i = 0; i < 2; i++)
                #pragma unroll
                for (int j = 0; j < 4; j++)
                    wmma::mma_sync(c[i][j], a[i], b[j], c[i][j]);
        }
        if (more) stage(cur ^ 1, pa, pb);
        __syncthreads();
    }

    // C through smem for coalesced store + stats
    #pragma unroll
    for (int i = 0; i < 2; i++)
        #pragma unroll
        for (int j = 0; j < 4; j++)
            wmma::store_matrix_sync(&Csm[(wm*32 + i*16) * CLD + wn*64 + j*16], c[i][j],
                                    CLD, wmma::mem_row_major);
    __syncthreads();

    const int ccol = tid & 127;
    const int r0 = tid >> 7;           // 0 or 1
    float s = 0.f, q = 0.f;
    #pragma unroll 8
    for (int it = 0; it < 64; it++) {
        int r = r0 + it * 2;
        float v = Csm[r * CLD + ccol];
        Cm[(rowBase + r) * O + colBase + ccol] = v;
        s += v; q += v * v;
    }
    if (stats) {
        atomicAdd(&cs[ccol], s);
        atomicAdd(&cq[ccol], q);
        __syncthreads();
        if (tid < TCN) {
            atomicAdd(&statS[colBase + tid], cs[tid]);
            atomicAdd(&statQ[colBase + tid], cq[tid]);
        }
    }
}

__global__ void k_finalize(const float* __restrict__ statSin, const float* __restrict__ statQin,
                           const float* __restrict__ g, const float* __restrict__ bb,
                           float* __restrict__ sc, float* __restrict__ sh, int O, float invP) {
    int o = blockIdx.x * blockDim.x + threadIdx.x;
    if (o < O) {
        float mu  = statSin[o] * invP;
        float var = fmaxf(statQin[o] * invP - mu * mu, 0.f);
        float s   = g[o] * rsqrtf(var + BNEPS);
        sc[o] = s;
        sh[o] = bb[o] - mu * s;
        ((float*)statSin)[o] = 0.f;
        ((float*)statQin)[o] = 0.f;
    }
}

// row maxes of cosine matrix
__global__ void k_rowmax(const float* __restrict__ inner, const float* __restrict__ nrmS,
                         const float* __restrict__ nrmD, float* __restrict__ maxDS) {
    int b = blockIdx.y, n = blockIdx.x;
    const float* row = inner + (long)b*NN*NN + (long)n*NN;
    float ns = nrmS[b*NN + n];
    float mx = -3.4e38f;
    for (int m = threadIdx.x; m < NN; m += 256)
        mx = fmaxf(mx, row[m] / (nrmD[b*NN + m] * ns + EPSF));
    #pragma unroll
    for (int o = 16; o > 0; o >>= 1) mx = fmaxf(mx, __shfl_down_sync(0xffffffffu, mx, o));
    __shared__ float ps[8];
    if ((threadIdx.x & 31) == 0) ps[threadIdx.x >> 5] = mx;
    __syncthreads();
    if (threadIdx.x == 0) {
        float r = ps[0];
        #pragma unroll
        for (int i = 1; i < 8; i++) r = fmaxf(r, ps[i]);
        maxDS[b*NN + n] = r;
    }
}

// col maxes, chunked over n
__global__ void k_colmax(const float* __restrict__ inner, const float* __restrict__ nrmS,
                         const float* __restrict__ nrmD, float* __restrict__ maxSD) {
    int b = blockIdx.z;
    int m = blockIdx.x * 256 + threadIdx.x;
    int n0 = blockIdx.y * 128;
    float nd = nrmD[b*NN + m];
    float mx = -3.4e38f;
    for (int n = n0; n < n0 + 128; n++)
        mx = fmaxf(mx, inner[(long)b*NN*NN + (long)n*NN + m] / (nd * nrmS[b*NN + n] + EPSF));
    atomicMaxF(&maxSD[b*NN + m], mx);
}

// top-16 smallest from shared d2[NN], 256 threads
__device__ void select_topk(float* d2, int* outIdx) {
    __shared__ float rv[8];
    __shared__ int   ri[8];
    int tid = threadIdx.x, lane = tid & 31, w = tid >> 5;
    for (int kk = 0; kk < KK; kk++) {
        float best = 3.4e38f; int bi = 0;
        for (int m = tid; m < NN; m += 256) {
            float v = d2[m];
            if (v < best) { best = v; bi = m; }
        }
        #pragma unroll
        for (int o = 16; o > 0; o >>= 1) {
            float ov = __shfl_down_sync(0xffffffffu, best, o);
            int   oi = __shfl_down_sync(0xffffffffu, bi, o);
            if (ov < best || (ov == best && oi < bi)) { best = ov; bi = oi; }
        }
        if (lane == 0) { rv[w] = best; ri[w] = bi; }
        __syncthreads();
        if (tid == 0) {
            float bv = rv[0]; int bj = ri[0];
            #pragma unroll
            for (int i = 1; i < 8; i++)
                if (rv[i] < bv || (rv[i] == bv && ri[i] < bj)) { bv = rv[i]; bj = ri[i]; }
            outIdx[kk] = bj;
            d2[bj] = 3.4e38f;
        }
        __syncthreads();
    }
}

__global__ void k_knn_desc(const float* __restrict__ inner, const float* __restrict__ nsqS,
                           const float* __restrict__ nsqD, int* __restrict__ idxOut) {
    int n = blockIdx.x, b = blockIdx.y;
    __shared__ float d2[NN];
    const float* row = inner + (long)b*NN*NN + (long)n*NN;
    float q = nsqS[b*NN + n];
    for (int m = threadIdx.x; m < NN; m += 256) d2[m] = q + nsqD[b*NN + m] - 2.f * row[m];
    __syncthreads();
    select_topk(d2, idxOut + ((long)b*NN + n) * KK);
}

__global__ void k_knn_xyz(const float* __restrict__ xyz, int* __restrict__ idxOut) {
    int n = blockIdx.x, b = blockIdx.y;
    __shared__ float d2[NN];
    long base = (long)b * NN * 3;
    float qx = xyz[base + (long)n*3], qy = xyz[base + (long)n*3+1], qz = xyz[base + (long)n*3+2];
    float qq = qx*qx + qy*qy + qz*qz;
    for (int m = threadIdx.x; m < NN; m += 256) {
        float rx = xyz[base + (long)m*3], ry = xyz[base + (long)m*3+1], rz = xyz[base + (long)m*3+2];
        d2[m] = qq + rx*rx + ry*ry + rz*rz - 2.f*(qx*rx + qy*ry + qz*rz);
    }
    __syncthreads();
    select_topk(d2, idxOut + ((long)b*NN + n) * KK);
}

__global__ void k_simgather(const float* __restrict__ inner, const float* __restrict__ nrmS,
                            const float* __restrict__ nrmD, const float* __restrict__ maxDS,
                            const float* __restrict__ maxSD, const int* __restrict__ idx,
                            float* __restrict__ outSD, float* __restrict__ outDS) {
    int t = blockIdx.x * 256 + threadIdx.x;
    if (t >= PP) return;
    int b = t / (NN * KK);
    int n = (t / KK) & (NN - 1);
    int m = idx[t];
    float v  = inner[(long)b*NN*NN + (long)n*NN + m];
    float cs = v / (nrmD[b*NN + m] * nrmS[b*NN + n] + EPSF);
    outSD[t] = cs / (maxDS[b*NN + n] + EPSF);
    outDS[t] = cs / (maxSD[b*NN + m] + EPSF);
}

// nbr conv input: [knn_feats(C), rela(3), dist(1), pad(8)] stride 144
__global__ void k_build_nbr_f(const float* __restrict__ xyz, const float* __restrict__ dmat,
                              const int* __restrict__ idx, float* __restrict__ f) {
    int p = blockIdx.x;
    int n = (p / KK) & (NN - 1);
    int b = p / (NN * KK);
    int m = idx[p];
    const float* dr = dmat + ((long)b*NN + m) * CC;
    float* fo = f + (long)p * 144;
    int tid = threadIdx.x;
    fo[tid] = dr[tid];
    if (tid == 0) {
        long qb = ((long)b*NN + n) * 3, rb = ((long)b*NN + m) * 3;
        float rx = xyz[rb]-xyz[qb], ry = xyz[rb+1]-xyz[qb+1], rz = xyz[rb+2]-xyz[qb+2];
        fo[128] = rx; fo[129] = ry; fo[130] = rz; fo[131] = sqrtf(rx*rx+ry*ry+rz*rz);
        #pragma unroll
        for (int z = 132; z < 144; z++) fo[z] = 0.f;
    }
}

__global__ void k_nbr_final(const float* __restrict__ yraw, const float* __restrict__ sc,
                            const float* __restrict__ sh, const int* __restrict__ idx,
                            const float* __restrict__ dmat, float* __restrict__ outN) {
    int bn = blockIdx.x, tid = threadIdx.x; // 256
    __shared__ float fe[KK][CC];
    __shared__ float mk[KK], wgt[KK];
    __shared__ int sid[KK];
    if (tid < KK) sid[tid] = idx[(long)bn*KK + tid];
    for (int t = tid; t < KK * CC; t += 256) {
        int k = t >> 7, c = t & 127;
        float v = yraw[((long)bn*KK + k) * CC + c];
        fe[k][c] = fmaxf(v * sc[c] + sh[c], 0.f);
    }
    __syncthreads();
    int w = tid >> 5, lane = tid & 31;
    for (int kk = w; kk < KK; kk += 8) {
        float mx = -3.4e38f;
        for (int c = lane; c < CC; c += 32) mx = fmaxf(mx, fe[kk][c]);
        #pragma unroll
        for (int o = 16; o > 0; o >>= 1) mx = fmaxf(mx, __shfl_down_sync(0xffffffffu, mx, o));
        if (lane == 0) mk[kk] = mx;
    }
    __syncthreads();
    if (tid == 0) {
        float m = -3.4e38f;
        for (int k = 0; k < KK; k++) m = fmaxf(m, mk[k]);
        float s = 0.f;
        for (int k = 0; k < KK; k++) { float e = expf(mk[k]-m); wgt[k] = e; s += e; }
        float r = 1.f / s;
        for (int k = 0; k < KK; k++) wgt[k] *= r;
    }
    __syncthreads();
    if (tid < CC) {
        int b = bn >> 11;
        float a = 0.f;
        #pragma unroll
        for (int k = 0; k < KK; k++) a += wgt[k] * dmat[((long)b*NN + sid[k]) * CC + tid];
        outN[(long)bn*CC + tid] = a;
    }
}

// main feats build (272 ch)
__global__ void k_build_feats(const float* __restrict__ src_xyz, const float* __restrict__ dst_xyz,
                              const float* __restrict__ srcd, const float* __restrict__ dstd,
                              const float* __restrict__ srcw, const float* __restrict__ dstw,
                              const float* __restrict__ sdc, const float* __restrict__ dsc,
                              const float* __restrict__ sdn, const float* __restrict__ dsn,
                              const int* __restrict__ idx, float* __restrict__ feats) {
    int p = blockIdx.x;
    int n = (p / KK) & (NN - 1);
    int b = p / (NN * KK);
    int m = idx[p];
    float* fo = feats + (long)p * 272;
    int tid = threadIdx.x;
    fo[10 + tid]  = srcd[((long)b*NN + n) * CC + tid];
    fo[138 + tid] = dstd[((long)b*NN + m) * CC + tid];
    if (tid == 0) {
        long qb = ((long)b*NN + n) * 3, rb = ((long)b*NN + m) * 3;
        float sx = src_xyz[qb], sy = src_xyz[qb+1], sz = src_xyz[qb+2];
        float kx = dst_xyz[rb], ky = dst_xyz[rb+1], kz = dst_xyz[rb+2];
        float rx = kx-sx, ry = ky-sy, rz = kz-sz;
        fo[0]=rx; fo[1]=ry; fo[2]=rz; fo[3]=sqrtf(rx*rx+ry*ry+rz*rz);
        fo[4]=sx; fo[5]=sy; fo[6]=sz; fo[7]=kx; fo[8]=ky; fo[9]=kz;
        fo[266]=srcw[b*NN+n]; fo[267]=dstw[b*NN+m];
        fo[268]=sdc[p]; fo[269]=dsc[p]; fo[270]=sdn[p]; fo[271]=dsn[p];
    }
}

__global__ void k_attention(const float* __restrict__ yraw, const float* __restrict__ sc,
                            const float* __restrict__ sh, const int* __restrict__ idx,
                            const float* __restrict__ dst_xyz,
                            float* __restrict__ outC, float* __restrict__ att) {
    int bn = blockIdx.x, tid = threadIdx.x; // 256
    __shared__ float fe[KK][256];
    __shared__ float mk[KK], wgt[KK];
    __shared__ int sid[KK];
    if (tid < KK) sid[tid] = idx[(long)bn*KK + tid];
    float s = sc[tid], h = sh[tid];
    #pragma unroll
    for (int k = 0; k < KK; k++) {
        float v = yraw[((long)bn*KK + k) * 256 + tid];
        fe[k][tid] = fmaxf(v * s + h, 0.f);
    }
    __syncthreads();
    int w = tid >> 5, lane = tid & 31;
    for (int kk = w; kk < KK; kk += 8) {
        float mx = -3.4e38f;
        for (int c = lane; c < 256; c += 32) mx = fmaxf(mx, fe[kk][c]);
        #pragma unroll
        for (int o = 16; o > 0; o >>= 1) mx = fmaxf(mx, __shfl_down_sync(0xffffffffu, mx, o));
        if (lane == 0) mk[kk] = mx;
    }
    __syncthreads();
    if (tid == 0) {
        float m = -3.4e38f;
        for (int k = 0; k < KK; k++) m = fmaxf(m, mk[k]);
        float ssum = 0.f;
        for (int k = 0; k < KK; k++) { float e = expf(mk[k]-m); wgt[k] = e; ssum += e; }
        float r = 1.f / ssum;
        for (int k = 0; k < KK; k++) wgt[k] *= r;
    }
    __syncthreads();
    float a = 0.f;
    #pragma unroll
    for (int k = 0; k < KK; k++) a += wgt[k] * fe[k][tid];
    att[(long)bn * 256 + tid] = a;
    if (tid < 3) {
        int b = bn >> 11;
        float cg = 0.f;
        #pragma unroll
        for (int k = 0; k < KK; k++)
            cg += wgt[k] * dst_xyz[((long)b*NN + sid[k]) * 3 + tid];
        outC[(long)bn * 3 + tid] = cg;
    }
}

__global__ void k_mlp3(const float* __restrict__ yraw, const float* __restrict__ sc,
                       const float* __restrict__ sh, const float* __restrict__ w3,
                       const float* __restrict__ b3, float* __restrict__ outw) {
    int bn = blockIdx.x, tid = threadIdx.x; // 256
    float v = fmaxf(yraw[(long)bn*256 + tid] * sc[tid] + sh[tid], 0.f) * w3[tid];
    #pragma unroll
    for (int o = 16; o > 0; o >>= 1) v += __shfl_down_sync(0xffffffffu, v, o);
    __shared__ float ps[8];
    if ((tid & 31) == 0) ps[tid >> 5] = v;
    __syncthreads();
    if (tid == 0) {
        float s2 = 0.f;
        #pragma unroll
        for (int i = 0; i < 8; i++) s2 += ps[i];
        outw[bn] = 1.f / (1.f + expf(-(s2 + b3[0])));
    }
}

// ---------------- host side ----------------
static void conv_bn(const float* A, const float* W, float* Y, int P, int O, int Kd,
                    bool aff, const float* g, const float* bb,
                    float* statS, float* sc, float* sh) {
    k_gemm_tc<<<dim3(O/TCN, P/TCM), 256, TC_DSM>>>(A, W, Y, P, O, Kd,
        aff ? sc : nullptr, aff ? sh : nullptr, statS, statS + 256);
    k_finalize<<<1, 256>>>(statS, statS + 256, g, bb, sc, sh, O, 1.f / (float)P);
}

extern "C" void kernel_launch(void* const* d_in, const int* in_sizes, int n_in,
                              void* d_out, int out_size) {
    const float* src_xyz  = (const float*)d_in[0];
    const float* src_desc = (const float*)d_in[1];
    const float* dst_xyz  = (const float*)d_in[2];
    const float* dst_desc = (const float*)d_in[3];
    const float* src_w    = (const float*)d_in[4];
    const float* dst_w    = (const float*)d_in[5];
    const float* c1_W0 = (const float*)d_in[6];
    const float* c1_W  = (const float*)d_in[7];
    const float* c1_g  = (const float*)d_in[8];
    const float* c1_b  = (const float*)d_in[9];
    const float* c2_W0 = (const float*)d_in[10];
    const float* c2_W  = (const float*)d_in[11];
    const float* c2_g  = (const float*)d_in[12];
    const float* c2_b  = (const float*)d_in[13];
    const float* m1_W  = (const float*)d_in[14];
    const float* m1_g  = (const float*)d_in[16];
    const float* m1_b  = (const float*)d_in[17];
    const float* m2_W  = (const float*)d_in[18];
    const float* m2_g  = (const float*)d_in[20];
    const float* m2_b  = (const float*)d_in[21];
    const float* m3_W  = (const float*)d_in[22];
    const float* m3_b  = (const float*)d_in[23];

    cudaFuncSetAttribute(k_gemm_tc, cudaFuncAttributeMaxDynamicSharedMemorySize, TC_DSM);

    float* base = nullptr;
    cudaGetSymbolAddress((void**)&base, g_pool);
    float* srcd   = base + F_SRCD;
    float* dstd   = base + F_DSTD;
    float* nsqS   = base + F_NSQS;
    float* nsqD   = base + F_NSQD;
    float* nrmS   = base + F_NRMS;
    float* nrmD   = base + F_NRMD;
    float* maxDS  = base + F_MAXDS;
    float* maxSD  = base + F_MAXSD;
    float* nrm2S  = base + F_NRM2S;
    float* nrm2D  = base + F_NRM2D;
    float* sdc    = base + F_SDC;
    float* dsc    = base + F_DSC;
    float* sdn    = base + F_SDN;
    float* dsn    = base + F_DSN;
    float* statS  = base + F_STATS;
    float* sc     = base + F_SC;
    float* sh     = base + F_SH;
    float* w2p    = base + F_W2P;
    int*   idx    = (int*)(base + F_IDX);
    int*   sidx   = (int*)(base + F_SIDX);
    int*   didx   = (int*)(base + F_DIDX);
    float* att    = base + F_ATT;
    float* mb1    = base + F_MB1;
    float* mb2    = base + F_MB2;
    float* srcnbr = base + F_SRCNBR;
    float* dstnbr = base + F_DSTNBR;
    float* inner  = base + F_INNER;
    float* fbuf   = base + F_F;
    float* y0     = base + F_Y0;
    float* y1     = base + F_Y1;
    float* outC   = (float*)d_out;
    float* outW   = (float*)d_out + (long)BB*NN*3;

    k_fill<<<2, 256>>>(statS, 0.f, 512);
    k_pad_w<<<128, 144>>>(c2_W0, w2p);

    // A: transpose + norms
    k_transpose_norm<<<BN, 128>>>(src_desc, srcd, nsqS, nrmS);
    k_transpose_norm<<<BN, 128>>>(dst_desc, dstd, nsqD, nrmD);

    // inner = src . dst (fp32, feeds KNN selection) + cos maxes + sims
    k_gemm<<<dim3(NN/BT, NN/BT, 2), dim3(16, 16)>>>(srcd, dstd, inner, NN, NN, CC,
        (long)NN*CC, (long)NN*CC, (long)NN*NN);
    k_fill<<<32, 256>>>(maxDS, -3.4e38f, 2*BN);
    k_rowmax<<<dim3(NN, BB), 256>>>(inner, nrmS, nrmD, maxDS);
    k_colmax<<<dim3(8, 16, 2), 256>>>(inner, nrmS, nrmD, maxSD);
    k_knn_desc<<<dim3(NN, BB), 256>>>(inner, nsqS, nsqD, idx);
    k_simgather<<<PP/256, 256>>>(inner, nrmS, nrmD, maxDS, maxSD, idx, sdc, dsc);

    // B: neighborhood descriptors
    k_knn_xyz<<<dim3(NN, BB), 256>>>(src_xyz, sidx);
    k_knn_xyz<<<dim3(NN, BB), 256>>>(dst_xyz, didx);
    const float* c2W1 = c2_W;
    const float* c2W2 = c2_W + CC*CC;
    for (int cloud = 0; cloud < 2; cloud++) {
        const float* xyz  = cloud ? dst_xyz : src_xyz;
        const float* dmat = cloud ? dstd : srcd;
        int* kidx         = cloud ? didx : sidx;
        float* outN       = cloud ? dstnbr : srcnbr;
        k_build_nbr_f<<<PP, 128>>>(xyz, dmat, kidx, fbuf);
        conv_bn(fbuf, w2p,  y0, PP, CC, 144, false, c2_g,        c2_b,        statS, sc, sh);
        conv_bn(y0,   c2W1, y1, PP, CC, CC,  true,  c2_g + CC,   c2_b + CC,   statS, sc, sh);
        conv_bn(y1,   c2W2, y0, PP, CC, CC,  true,  c2_g + 2*CC, c2_b + 2*CC, statS, sc, sh);
        k_nbr_final<<<BN, 256>>>(y0, sc, sh, kidx, dmat, outN);
    }

    // nbr cosine sims (fp32 inner)
    k_rownorm<<<BN, 128>>>(srcnbr, nrm2S);
    k_rownorm<<<BN, 128>>>(dstnbr, nrm2D);
    k_gemm<<<dim3(NN/BT, NN/BT, 2), dim3(16, 16)>>>(srcnbr, dstnbr, inner, NN, NN, CC,
        (long)NN*CC, (long)NN*CC, (long)NN*NN);
    k_fill<<<32, 256>>>(maxDS, -3.4e38f, 2*BN);
    k_rowmax<<<dim3(NN, BB), 256>>>(inner, nrm2S, nrm2D, maxDS);
    k_colmax<<<dim3(8, 16, 2), 256>>>(inner, nrm2S, nrm2D, maxSD);
    k_simgather<<<PP/256, 256>>>(inner, nrm2S, nrm2D, maxDS, maxSD, idx, sdn, dsn);

    // C: main feature conv + attention
    k_build_feats<<<PP, 128>>>(src_xyz, dst_xyz, srcd, dstd, src_w, dst_w,
                               sdc, dsc, sdn, dsn, idx, fbuf);
    const float* c1W1 = c1_W;
    const float* c1W2 = c1_W + 256*256;
    conv_bn(fbuf, c1_W0, y0, PP, 256, 272, false, c1_g,        c1_b,        statS, sc, sh);
    conv_bn(y0,   c1W1,  y1, PP, 256, 256, true,  c1_g + 256,  c1_b + 256,  statS, sc, sh);
    conv_bn(y1,   c1W2,  y0, PP, 256, 256, true,  c1_g + 512,  c1_b + 512,  statS, sc, sh);
    k_attention<<<BN, 256>>>(y0, sc, sh, idx, dst_xyz, outC, att);

    // D: MLP head
    conv_bn(att, m1_W, mb1, BN, 256, 256, false, m1_g, m1_b, statS, sc, sh);
    conv_bn(mb1, m2_W, mb2, BN, 256, 256, true,  m2_g, m2_b, statS, sc, sh);
    k_mlp3<<<BN, 256>>>(mb2, sc, sh, m3_W, m3_b, outW);
}

// round 6
// speedup vs baseline: 1.0978x; 1.0978x over previous
#include <cuda_runtime.h>
#include <mma.h>
#include <math.h>
#include <float.h>

using namespace nvcuda;

#define BB 2
#define NN 2048
#define CC 128
#define KK 16
#define BN (BB*NN)
#define PP (BB*NN*KK)
#define EPSF 1e-6f
#define BNEPS 1e-5f

// ---------------- scratch pool ----------------
constexpr long F_SRCD   = 0;
constexpr long F_DSTD   = F_SRCD   + (long)BN*CC;
constexpr long F_NSQS   = F_DSTD   + (long)BN*CC;
constexpr long F_NSQD   = F_NSQS   + BN;
constexpr long F_NRMS   = F_NSQD   + BN;
constexpr long F_NRMD   = F_NRMS   + BN;
constexpr long F_MAXDS  = F_NRMD   + BN;
constexpr long F_MAXSD  = F_MAXDS  + BN;
constexpr long F_NRM2S  = F_MAXSD  + BN;
constexpr long F_NRM2D  = F_NRM2S  + BN;
constexpr long F_SDC    = F_NRM2D  + BN;
constexpr long F_DSC    = F_SDC    + PP;
constexpr long F_SDN    = F_DSC    + PP;
constexpr long F_DSN    = F_SDN    + PP;
constexpr long F_STATS  = F_DSN    + PP;
constexpr long F_STATQ  = F_STATS  + 256;
constexpr long F_SC     = F_STATQ  + 256;
constexpr long F_SH     = F_SC     + 256;
constexpr long F_W2P    = F_SH     + 256;          // padded c2_W0 [128][144]
constexpr long F_IDX    = F_W2P    + 128*144;      // int
constexpr long F_SIDX   = F_IDX    + PP;
constexpr long F_DIDX   = F_SIDX   + PP;
constexpr long F_ATT    = F_DIDX   + PP;
constexpr long F_MB1    = F_ATT    + (long)BN*256;
constexpr long F_MB2    = F_MB1    + (long)BN*256;
constexpr long F_SRCNBR = F_MB2    + (long)BN*256;
constexpr long F_DSTNBR = F_SRCNBR + (long)BN*CC;
constexpr long F_INNER  = F_DSTNBR + (long)BN*CC;
constexpr long F_F      = F_INNER  + (long)BB*NN*NN;
constexpr long F_Y0     = F_F      + (long)PP*272;
constexpr long F_Y1     = F_Y0     + (long)PP*256;
constexpr long F_END    = F_Y1     + (long)PP*256;

__device__ __align__(128) float g_pool[F_END];

__device__ __forceinline__ void atomicMaxF(float* a, float v) {
    if (!(v < 0.f)) atomicMax((int*)a, __float_as_int(v));
    else            atomicMin((unsigned int*)a, __float_as_uint(v));
}

__global__ void k_fill(float* __restrict__ p, float v, int n) {
    int i = blockIdx.x * blockDim.x + threadIdx.x;
    if (i < n) p[i] = v;
}

__global__ void k_pad_w(const float* __restrict__ W, float* __restrict__ Wp) {
    int o = blockIdx.x; int k = threadIdx.x; // 144 threads
    Wp[o * 144 + k] = (k < 132) ? W[o * 132 + k] : 0.f;
}

// [B,C,N] -> [B,N,C] plus |.|^2 and |.|
__global__ void k_transpose_norm(const float* __restrict__ desc, float* __restrict__ dmat,
                                 float* __restrict__ nsq, float* __restrict__ nrm) {
    int bn = blockIdx.x; int b = bn >> 11; int n = bn & (NN - 1);
    int c = threadIdx.x;
    float v = desc[((long)b*CC + c)*NN + n];
    dmat[(long)bn*CC + c] = v;
    float s = v * v;
    #pragma unroll
    for (int o = 16; o > 0; o >>= 1) s += __shfl_down_sync(0xffffffffu, s, o);
    __shared__ float ps[4];
    if ((c & 31) == 0) ps[c >> 5] = s;
    __syncthreads();
    if (c == 0) { float t = ps[0]+ps[1]+ps[2]+ps[3]; nsq[bn] = t; nrm[bn] = sqrtf(t); }
}

__global__ void k_rownorm(const float* __restrict__ dmat, float* __restrict__ nrm) {
    int bn = blockIdx.x; int c = threadIdx.x;
    float v = dmat[(long)bn*CC + c];
    float s = v * v;
    #pragma unroll
    for (int o = 16; o > 0; o >>= 1) s += __shfl_down_sync(0xffffffffu, s, o);
    __shared__ float ps[4];
    if ((c & 31) == 0) ps[c >> 5] = s;
    __syncthreads();
    if (c == 0) nrm[bn] = sqrtf(ps[0]+ps[1]+ps[2]+ps[3]);
}

// ---------------- fp32 SIMT GEMM (KNN/cosine inner products only) ----------------
#define BT 128
#define GKS 8
#define SPAD 4

__global__ __launch_bounds__(256)
void k_gemm(const float* __restrict__ A, const float* __restrict__ Bm,
            float* __restrict__ Cm, int P, int O, int Kd,
            long sA, long sB, long sC) {
    A  += (long)blockIdx.z * sA;
    Bm += (long)blockIdx.z * sB;
    Cm += (long)blockIdx.z * sC;
    __shared__ __align__(16) float As[2][GKS][BT + SPAD];
    __shared__ __align__(16) float Bs[2][GKS][BT + SPAD];
    const int tx = threadIdx.x, ty = threadIdx.y;
    const int tid = ty * 16 + tx;
    const int rowBase = blockIdx.y * BT;
    const int colBase = blockIdx.x * BT;
    const int lr = tid >> 1;
    const int lk = (tid & 1) * 4;
    const float* Aptr = A  + (long)(rowBase + lr) * Kd + lk;
    const float* Bptr = Bm + (long)(colBase + lr) * Kd + lk;
    float acc[8][8] = {};
    const int nk = Kd / GKS;
    {
        float4 av = *reinterpret_cast<const float4*>(Aptr);
        float4 bv = *reinterpret_cast<const float4*>(Bptr);
        As[0][lk+0][lr] = av.x; As[0][lk+1][lr] = av.y;
        As[0][lk+2][lr] = av.z; As[0][lk+3][lr] = av.w;
        Bs[0][lk+0][lr] = bv.x; Bs[0][lk+1][lr] = bv.y;
        Bs[0][lk+2][lr] = bv.z; Bs[0][lk+3][lr] = bv.w;
    }
    __syncthreads();
    for (int kt = 0; kt < nk; kt++) {
        const int cur = kt & 1;
        float4 av2, bv2;
        const bool more = (kt + 1 < nk);
        if (more) {
            av2 = *reinterpret_cast<const float4*>(Aptr + (kt+1)*GKS);
            bv2 = *reinterpret_cast<const float4*>(Bptr + (kt+1)*GKS);
        }
        #pragma unroll
        for (int kk = 0; kk < GKS; kk++) {
            float4 a0 = *reinterpret_cast<const float4*>(&As[cur][kk][ty*4]);
            float4 a1 = *reinterpret_cast<const float4*>(&As[cur][kk][ty*4+64]);
            float4 b0 = *reinterpret_cast<const float4*>(&Bs[cur][kk][tx*4]);
            float4 b1 = *reinterpret_cast<const float4*>(&Bs[cur][kk][tx*4+64]);
            float a[8] = {a0.x,a0.y,a0.z,a0.w,a1.x,a1.y,a1.z,a1.w};
            float b[8] = {b0.x,b0.y,b0.z,b0.w,b1.x,b1.y,b1.z,b1.w};
            #pragma unroll
            for (int i = 0; i < 8; i++)
                #pragma unroll
                for (int j = 0; j < 8; j++)
                    acc[i][j] += a[i] * b[j];
        }
        if (more) {
            const int nb = cur ^ 1;
            As[nb][lk+0][lr] = av2.x; As[nb][lk+1][lr] = av2.y;
            As[nb][lk+2][lr] = av2.z; As[nb][lk+3][lr] = av2.w;
            Bs[nb][lk+0][lr] = bv2.x; Bs[nb][lk+1][lr] = bv2.y;
            Bs[nb][lk+2][lr] = bv2.z; Bs[nb][lk+3][lr] = bv2.w;
        }
        __syncthreads();
    }
    #pragma unroll
    for (int i = 0; i < 8; i++) {
        long r = rowBase + ty*4 + ((i < 4) ? i : 64 + i - 4);
        float4 v0 = {acc[i][0], acc[i][1], acc[i][2], acc[i][3]};
        float4 v1 = {acc[i][4], acc[i][5], acc[i][6], acc[i][7]};
        *reinterpret_cast<float4*>(&Cm[r * O + colBase + tx*4])      = v0;
        *reinterpret_cast<float4*>(&Cm[r * O + colBase + tx*4 + 64]) = v1;
    }
}

// ---------------- TF32 TC GEMM (v1 shape + double buffer + staged tf32) ----------------
// 128x64 block tile, 8 warps (4M x 2N), warp tile 32x32 (2x2 wmma m16n16k8).
// Static smem union: staging 2*(128+64)*20*4 = 30720 B, C staging 128*68*4 = 34816 B.
// Requires P%128==0, O%64==0, Kd%16==0.
#define TCM 128
#define TCN 64
#define ALD 20
#define CLD 68

__global__ __launch_bounds__(256)
void k_gemm_tc(const float* __restrict__ A, const float* __restrict__ Bm,
               float* __restrict__ Cm, int P, int O, int Kd,
               const float* __restrict__ scA, const float* __restrict__ shA,
               float* __restrict__ statS, float* __restrict__ statQ) {
    __shared__ __align__(16) float smem[TCM * CLD];   // 34816 B union
    float* Asb[2] = { smem,                       smem + TCM*ALD };
    float* Bsb[2] = { smem + 2*TCM*ALD,           smem + 2*TCM*ALD + TCN*ALD };
    float* Csm = smem;
    __shared__ float cs[TCN], cq[TCN];

    const int tid = threadIdx.x;
    const int wid = tid >> 5;
    const int wm = wid & 3;           // 0..3 along M
    const int wn = wid >> 2;          // 0..1 along N
    const long rowBase = (long)blockIdx.y * TCM;
    const int colBase = blockIdx.x * TCN;
    const bool aff = (scA != nullptr);
    const bool stats = (statS != nullptr);
    if (stats && tid < TCN) { cs[tid] = 0.f; cq[tid] = 0.f; }

    const int ma = tid >> 2;          // A row base helper (two rows: lin>>2 for e*256+tid)
    const int kq = (tid & 3) * 4;

    wmma::fragment<wmma::accumulator, 16, 16, 8, float> c[2][2];
    #pragma unroll
    for (int i = 0; i < 2; i++)
        #pragma unroll
        for (int j = 0; j < 2; j++)
            wmma::fill_fragment(c[i][j], 0.f);

    const int nk = Kd / 16;

    auto loadA = [&](int k0, float4* pa) {
        #pragma unroll
        for (int e = 0; e < 2; e++) {
            int m = ma + e * 64;
            float4 v = *reinterpret_cast<const float4*>(&A[(rowBase + m) * Kd + k0 + kq]);
            if (aff) {
                int gk = k0 + kq;
                v.x = fmaxf(v.x * scA[gk+0] + shA[gk+0], 0.f);
                v.y = fmaxf(v.y * scA[gk+1] + shA[gk+1], 0.f);
                v.z = fmaxf(v.z * scA[gk+2] + shA[gk+2], 0.f);
                v.w = fmaxf(v.w * scA[gk+3] + shA[gk+3], 0.f);
            }
            pa[e] = v;
        }
    };
    auto loadB = [&](int k0, float4* pb) {
        int m = tid >> 2;
        if (m < TCN) { /* all 256 threads: m 0..63 */ }
        *pb = *reinterpret_cast<const float4*>(&Bm[(long)(colBase + (tid >> 2 & 63)) * Kd + k0 + kq]);
    };
    auto cvt4 = [](float4 v) {
        v.x = wmma::__float_to_tf32(v.x); v.y = wmma::__float_to_tf32(v.y);
        v.z = wmma::__float_to_tf32(v.z); v.w = wmma::__float_to_tf32(v.w);
        return v;
    };
    auto stage = [&](int buf, const float4* pa, const float4 pb) {
        #pragma unroll
        for (int e = 0; e < 2; e++) {
            int m = ma + e * 64;
            *reinterpret_cast<float4*>(&Asb[buf][m * ALD + kq]) = cvt4(pa[e]);
        }
        *reinterpret_cast<float4*>(&Bsb[buf][(tid >> 2 & 63) * ALD + kq]) = cvt4(pb);
    };

    {
        float4 pa[2], pb;
        loadA(0, pa); loadB(0, &pb);
        stage(0, pa, pb);
    }
    __syncthreads();

    for (int kc = 0; kc < nk; kc++) {
        const int cur = kc & 1;
        const bool more = (kc + 1 < nk);
        float4 pa[2], pb;
        if (more) { loadA((kc+1)*16, pa); loadB((kc+1)*16, &pb); }
        #pragma unroll
        for (int ks = 0; ks < 2; ks++) {
            wmma::fragment<wmma::matrix_a, 16, 16, 8, wmma::precision::tf32, wmma::row_major> a[2];
            wmma::fragment<wmma::matrix_b, 16, 16, 8, wmma::precision::tf32, wmma::col_major> b[2];
            #pragma unroll
            for (int i = 0; i < 2; i++)
                wmma::load_matrix_sync(a[i], &Asb[cur][(wm*32 + i*16) * ALD + ks*8], ALD);
            #pragma unroll
            for (int j = 0; j < 2; j++)
                wmma::load_matrix_sync(b[j], &Bsb[cur][(wn*32 + j*16) * ALD + ks*8], ALD);
            #pragma unroll
            for (int i = 0; i < 2; i++)
                #pragma unroll
                for (int j = 0; j < 2; j++)
                    wmma::mma_sync(c[i][j], a[i], b[j], c[i][j]);
        }
        if (more) stage(cur ^ 1, pa, pb);
        __syncthreads();
    }

    // C through smem for coalesced store + stats
    #pragma unroll
    for (int i = 0; i < 2; i++)
        #pragma unroll
        for (int j = 0; j < 2; j++)
            wmma::store_matrix_sync(&Csm[(wm*32 + i*16) * CLD + wn*32 + j*16], c[i][j],
                                    CLD, wmma::mem_row_major);
    __syncthreads();

    const int ccol = tid & 63;
    const int r0 = tid >> 6;          // 0..3
    float s = 0.f, q = 0.f;
    #pragma unroll 8
    for (int it = 0; it < 32; it++) {
        int r = r0 + it * 4;
        float v = Csm[r * CLD + ccol];
        Cm[(rowBase + r) * O + colBase + ccol] = v;
        s += v; q += v * v;
    }
    if (stats) {
        atomicAdd(&cs[ccol], s);
        atomicAdd(&cq[ccol], q);
        __syncthreads();
        if (tid < TCN) {
            atomicAdd(&statS[colBase + tid], cs[tid]);
            atomicAdd(&statQ[colBase + tid], cq[tid]);
        }
    }
}

__global__ void k_finalize(const float* __restrict__ statSin, const float* __restrict__ statQin,
                           const float* __restrict__ g, const float* __restrict__ bb,
                           float* __restrict__ sc, float* __restrict__ sh, int O, float invP) {
    int o = blockIdx.x * blockDim.x + threadIdx.x;
    if (o < O) {
        float mu  = statSin[o] * invP;
        float var = fmaxf(statQin[o] * invP - mu * mu, 0.f);
        float s   = g[o] * rsqrtf(var + BNEPS);
        sc[o] = s;
        sh[o] = bb[o] - mu * s;
        ((float*)statSin)[o] = 0.f;
        ((float*)statQin)[o] = 0.f;
    }
}

// row maxes of cosine matrix
__global__ void k_rowmax(const float* __restrict__ inner, const float* __restrict__ nrmS,
                         const float* __restrict__ nrmD, float* __restrict__ maxDS) {
    int b = blockIdx.y, n = blockIdx.x;
    const float* row = inner + (long)b*NN*NN + (long)n*NN;
    float ns = nrmS[b*NN + n];
    float mx = -3.4e38f;
    for (int m = threadIdx.x; m < NN; m += 256)
        mx = fmaxf(mx, row[m] / (nrmD[b*NN + m] * ns + EPSF));
    #pragma unroll
    for (int o = 16; o > 0; o >>= 1) mx = fmaxf(mx, __shfl_down_sync(0xffffffffu, mx, o));
    __shared__ float ps[8];
    if ((threadIdx.x & 31) == 0) ps[threadIdx.x >> 5] = mx;
    __syncthreads();
    if (threadIdx.x == 0) {
        float r = ps[0];
        #pragma unroll
        for (int i = 1; i < 8; i++) r = fmaxf(r, ps[i]);
        maxDS[b*NN + n] = r;
    }
}

// col maxes, chunked over n
__global__ void k_colmax(const float* __restrict__ inner, const float* __restrict__ nrmS,
                         const float* __restrict__ nrmD, float* __restrict__ maxSD) {
    int b = blockIdx.z;
    int m = blockIdx.x * 256 + threadIdx.x;
    int n0 = blockIdx.y * 128;
    float nd = nrmD[b*NN + m];
    float mx = -3.4e38f;
    for (int n = n0; n < n0 + 128; n++)
        mx = fmaxf(mx, inner[(long)b*NN*NN + (long)n*NN + m] / (nd * nrmS[b*NN + n] + EPSF));
    atomicMaxF(&maxSD[b*NN + m], mx);
}

// top-16 smallest from shared d2[NN], 256 threads
__device__ void select_topk(float* d2, int* outIdx) {
    __shared__ float rv[8];
    __shared__ int   ri[8];
    int tid = threadIdx.x, lane = tid & 31, w = tid >> 5;
    for (int kk = 0; kk < KK; kk++) {
        float best = 3.4e38f; int bi = 0;
        for (int m = tid; m < NN; m += 256) {
            float v = d2[m];
            if (v < best) { best = v; bi = m; }
        }
        #pragma unroll
        for (int o = 16; o > 0; o >>= 1) {
            float ov = __shfl_down_sync(0xffffffffu, best, o);
            int   oi = __shfl_down_sync(0xffffffffu, bi, o);
            if (ov < best || (ov == best && oi < bi)) { best = ov; bi = oi; }
        }
        if (lane == 0) { rv[w] = best; ri[w] = bi; }
        __syncthreads();
        if (tid == 0) {
            float bv = rv[0]; int bj = ri[0];
            #pragma unroll
            for (int i = 1; i < 8; i++)
                if (rv[i] < bv || (rv[i] == bv && ri[i] < bj)) { bv = rv[i]; bj = ri[i]; }
            outIdx[kk] = bj;
            d2[bj] = 3.4e38f;
        }
        __syncthreads();
    }
}

__global__ void k_knn_desc(const float* __restrict__ inner, const float* __restrict__ nsqS,
                           const float* __restrict__ nsqD, int* __restrict__ idxOut) {
    int n = blockIdx.x, b = blockIdx.y;
    __shared__ float d2[NN];
    const float* row = inner + (long)b*NN*NN + (long)n*NN;
    float q = nsqS[b*NN + n];
    for (int m = threadIdx.x; m < NN; m += 256) d2[m] = q + nsqD[b*NN + m] - 2.f * row[m];
    __syncthreads();
    select_topk(d2, idxOut + ((long)b*NN + n) * KK);
}

__global__ void k_knn_xyz(const float* __restrict__ xyz, int* __restrict__ idxOut) {
    int n = blockIdx.x, b = blockIdx.y;
    __shared__ float d2[NN];
    long base = (long)b * NN * 3;
    float qx = xyz[base + (long)n*3], qy = xyz[base + (long)n*3+1], qz = xyz[base + (long)n*3+2];
    float qq = qx*qx + qy*qy + qz*qz;
    for (int m = threadIdx.x; m < NN; m += 256) {
        float rx = xyz[base + (long)m*3], ry = xyz[base + (long)m*3+1], rz = xyz[base + (long)m*3+2];
        d2[m] = qq + rx*rx + ry*ry + rz*rz - 2.f*(qx*rx + qy*ry + qz*rz);
    }
    __syncthreads();
    select_topk(d2, idxOut + ((long)b*NN + n) * KK);
}

__global__ void k_simgather(const float* __restrict__ inner, const float* __restrict__ nrmS,
                            const float* __restrict__ nrmD, const float* __restrict__ maxDS,
                            const float* __restrict__ maxSD, const int* __restrict__ idx,
                            float* __restrict__ outSD, float* __restrict__ outDS) {
    int t = blockIdx.x * 256 + threadIdx.x;
    if (t >= PP) return;
    int b = t / (NN * KK);
    int n = (t / KK) & (NN - 1);
    int m = idx[t];
    float v  = inner[(long)b*NN*NN + (long)n*NN + m];
    float cs = v / (nrmD[b*NN + m] * nrmS[b*NN + n] + EPSF);
    outSD[t] = cs / (maxDS[b*NN + n] + EPSF);
    outDS[t] = cs / (maxSD[b*NN + m] + EPSF);
}

// nbr conv input: [knn_feats(C), rela(3), dist(1), pad(8)] stride 144
__global__ void k_build_nbr_f(const float* __restrict__ xyz, const float* __restrict__ dmat,
                              const int* __restrict__ idx, float* __restrict__ f) {
    int p = blockIdx.x;
    int n = (p / KK) & (NN - 1);
    int b = p / (NN * KK);
    int m = idx[p];
    const float* dr = dmat + ((long)b*NN + m) * CC;
    float* fo = f + (long)p * 144;
    int tid = threadIdx.x;
    fo[tid] = dr[tid];
    if (tid == 0) {
        long qb = ((long)b*NN + n) * 3, rb = ((long)b*NN + m) * 3;
        float rx = xyz[rb]-xyz[qb], ry = xyz[rb+1]-xyz[qb+1], rz = xyz[rb+2]-xyz[qb+2];
        fo[128] = rx; fo[129] = ry; fo[130] = rz; fo[131] = sqrtf(rx*rx+ry*ry+rz*rz);
        #pragma unroll
        for (int z = 132; z < 144; z++) fo[z] = 0.f;
    }
}

__global__ void k_nbr_final(const float* __restrict__ yraw, const float* __restrict__ sc,
                            const float* __restrict__ sh, const int* __restrict__ idx,
                            const float* __restrict__ dmat, float* __restrict__ outN) {
    int bn = blockIdx.x, tid = threadIdx.x; // 256
    __shared__ float fe[KK][CC];
    __shared__ float mk[KK], wgt[KK];
    __shared__ int sid[KK];
    if (tid < KK) sid[tid] = idx[(long)bn*KK + tid];
    for (int t = tid; t < KK * CC; t += 256) {
        int k = t >> 7, c = t & 127;
        float v = yraw[((long)bn*KK + k) * CC + c];
        fe[k][c] = fmaxf(v * sc[c] + sh[c], 0.f);
    }
    __syncthreads();
    int w = tid >> 5, lane = tid & 31;
    for (int kk = w; kk < KK; kk += 8) {
        float mx = -3.4e38f;
        for (int c = lane; c < CC; c += 32) mx = fmaxf(mx, fe[kk][c]);
        #pragma unroll
        for (int o = 16; o > 0; o >>= 1) mx = fmaxf(mx, __shfl_down_sync(0xffffffffu, mx, o));
        if (lane == 0) mk[kk] = mx;
    }
    __syncthreads();
    if (tid == 0) {
        float m = -3.4e38f;
        for (int k = 0; k < KK; k++) m = fmaxf(m, mk[k]);
        float s = 0.f;
        for (int k = 0; k < KK; k++) { float e = expf(mk[k]-m); wgt[k] = e; s += e; }
        float r = 1.f / s;
        for (int k = 0; k < KK; k++) wgt[k] *= r;
    }
    __syncthreads();
    if (tid < CC) {
        int b = bn >> 11;
        float a = 0.f;
        #pragma unroll
        for (int k = 0; k < KK; k++) a += wgt[k] * dmat[((long)b*NN + sid[k]) * CC + tid];
        outN[(long)bn*CC + tid] = a;
    }
}

// main feats build (272 ch)
__global__ void k_build_feats(const float* __restrict__ src_xyz, const float* __restrict__ dst_xyz,
                              const float* __restrict__ srcd, const float* __restrict__ dstd,
                              const float* __restrict__ srcw, const float* __restrict__ dstw,
                              const float* __restrict__ sdc, const float* __restrict__ dsc,
                              const float* __restrict__ sdn, const float* __restrict__ dsn,
                              const int* __restrict__ idx, float* __restrict__ feats) {
    int p = blockIdx.x;
    int n = (p / KK) & (NN - 1);
    int b = p / (NN * KK);
    int m = idx[p];
    float* fo = feats + (long)p * 272;
    int tid = threadIdx.x;
    fo[10 + tid]  = srcd[((long)b*NN + n) * CC + tid];
    fo[138 + tid] = dstd[((long)b*NN + m) * CC + tid];
    if (tid == 0) {
        long qb = ((long)b*NN + n) * 3, rb = ((long)b*NN + m) * 3;
        float sx = src_xyz[qb], sy = src_xyz[qb+1], sz = src_xyz[qb+2];
        float kx = dst_xyz[rb], ky = dst_xyz[rb+1], kz = dst_xyz[rb+2];
        float rx = kx-sx, ry = ky-sy, rz = kz-sz;
        fo[0]=rx; fo[1]=ry; fo[2]=rz; fo[3]=sqrtf(rx*rx+ry*ry+rz*rz);
        fo[4]=sx; fo[5]=sy; fo[6]=sz; fo[7]=kx; fo[8]=ky; fo[9]=kz;
        fo[266]=srcw[b*NN+n]; fo[267]=dstw[b*NN+m];
        fo[268]=sdc[p]; fo[269]=dsc[p]; fo[270]=sdn[p]; fo[271]=dsn[p];
    }
}

__global__ void k_attention(const float* __restrict__ yraw, const float* __restrict__ sc,
                            const float* __restrict__ sh, const int* __restrict__ idx,
                            const float* __restrict__ dst_xyz,
                            float* __restrict__ outC, float* __restrict__ att) {
    int bn = blockIdx.x, tid = threadIdx.x; // 256
    __shared__ float fe[KK][256];
    __shared__ float mk[KK], wgt[KK];
    __shared__ int sid[KK];
    if (tid < KK) sid[tid] = idx[(long)bn*KK + tid];
    float s = sc[tid], h = sh[tid];
    #pragma unroll
    for (int k = 0; k < KK; k++) {
        float v = yraw[((long)bn*KK + k) * 256 + tid];
        fe[k][tid] = fmaxf(v * s + h, 0.f);
    }
    __syncthreads();
    int w = tid >> 5, lane = tid & 31;
    for (int kk = w; kk < KK; kk += 8) {
        float mx = -3.4e38f;
        for (int c = lane; c < 256; c += 32) mx = fmaxf(mx, fe[kk][c]);
        #pragma unroll
        for (int o = 16; o > 0; o >>= 1) mx = fmaxf(mx, __shfl_down_sync(0xffffffffu, mx, o));
        if (lane == 0) mk[kk] = mx;
    }
    __syncthreads();
    if (tid == 0) {
        float m = -3.4e38f;
        for (int k = 0; k < KK; k++) m = fmaxf(m, mk[k]);
        float ssum = 0.f;
        for (int k = 0; k < KK; k++) { float e = expf(mk[k]-m); wgt[k] = e; ssum += e; }
        float r = 1.f / ssum;
        for (int k = 0; k < KK; k++) wgt[k] *= r;
    }
    __syncthreads();
    float a = 0.f;
    #pragma unroll
    for (int k = 0; k < KK; k++) a += wgt[k] * fe[k][tid];
    att[(long)bn * 256 + tid] = a;
    if (tid < 3) {
        int b = bn >> 11;
        float cg = 0.f;
        #pragma unroll
        for (int k = 0; k < KK; k++)
            cg += wgt[k] * dst_xyz[((long)b*NN + sid[k]) * 3 + tid];
        outC[(long)bn * 3 + tid] = cg;
    }
}

__global__ void k_mlp3(const float* __restrict__ yraw, const float* __restrict__ sc,
                       const float* __restrict__ sh, const float* __restrict__ w3,
                       const float* __restrict__ b3, float* __restrict__ outw) {
    int bn = blockIdx.x, tid = threadIdx.x; // 256
    float v = fmaxf(yraw[(long)bn*256 + tid] * sc[tid] + sh[tid], 0.f) * w3[tid];
    #pragma unroll
    for (int o = 16; o > 0; o >>= 1) v += __shfl_down_sync(0xffffffffu, v, o);
    __shared__ float ps[8];
    if ((tid & 31) == 0) ps[tid >> 5] = v;
    __syncthreads();
    if (tid == 0) {
        float s2 = 0.f;
        #pragma unroll
        for (int i = 0; i < 8; i++) s2 += ps[i];
        outw[bn] = 1.f / (1.f + expf(-(s2 + b3[0])));
    }
}

// ---------------- host side ----------------
static void conv_bn(const float* A, const float* W, float* Y, int P, int O, int Kd,
                    bool aff, const float* g, const float* bb,
                    float* statS, float* sc, float* sh) {
    k_gemm_tc<<<dim3(O/TCN, P/TCM), 256>>>(A, W, Y, P, O, Kd,
        aff ? sc : nullptr, aff ? sh : nullptr, statS, statS + 256);
    k_finalize<<<1, 256>>>(statS, statS + 256, g, bb, sc, sh, O, 1.f / (float)P);
}

extern "C" void kernel_launch(void* const* d_in, const int* in_sizes, int n_in,
                              void* d_out, int out_size) {
    const float* src_xyz  = (const float*)d_in[0];
    const float* src_desc = (const float*)d_in[1];
    const float* dst_xyz  = (const float*)d_in[2];
    const float* dst_desc = (const float*)d_in[3];
    const float* src_w    = (const float*)d_in[4];
    const float* dst_w    = (const float*)d_in[5];
    const float* c1_W0 = (const float*)d_in[6];
    const float* c1_W  = (const float*)d_in[7];
    const float* c1_g  = (const float*)d_in[8];
    const float* c1_b  = (const float*)d_in[9];
    const float* c2_W0 = (const float*)d_in[10];
    const float* c2_W  = (const float*)d_in[11];
    const float* c2_g  = (const float*)d_in[12];
    const float* c2_b  = (const float*)d_in[13];
    const float* m1_W  = (const float*)d_in[14];
    const float* m1_g  = (const float*)d_in[16];
    const float* m1_b  = (const float*)d_in[17];
    const float* m2_W  = (const float*)d_in[18];
    const float* m2_g  = (const float*)d_in[20];
    const float* m2_b  = (const float*)d_in[21];
    const float* m3_W  = (const float*)d_in[22];
    const float* m3_b  = (const float*)d_in[23];

    float* base = nullptr;
    cudaGetSymbolAddress((void**)&base, g_pool);
    float* srcd   = base + F_SRCD;
    float* dstd   = base + F_DSTD;
    float* nsqS   = base + F_NSQS;
    float* nsqD   = base + F_NSQD;
    float* nrmS   = base + F_NRMS;
    float* nrmD   = base + F_NRMD;
    float* maxDS  = base + F_MAXDS;
    float* maxSD  = base + F_MAXSD;
    float* nrm2S  = base + F_NRM2S;
    float* nrm2D  = base + F_NRM2D;
    float* sdc    = base + F_SDC;
    float* dsc    = base + F_DSC;
    float* sdn    = base + F_SDN;
    float* dsn    = base + F_DSN;
    float* statS  = base + F_STATS;
    float* sc     = base + F_SC;
    float* sh     = base + F_SH;
    float* w2p    = base + F_W2P;
    int*   idx    = (int*)(base + F_IDX);
    int*   sidx   = (int*)(base + F_SIDX);
    int*   didx   = (int*)(base + F_DIDX);
    float* att    = base + F_ATT;
    float* mb1    = base + F_MB1;
    float* mb2    = base + F_MB2;
    float* srcnbr = base + F_SRCNBR;
    float* dstnbr = base + F_DSTNBR;
    float* inner  = base + F_INNER;
    float* fbuf   = base + F_F;
    float* y0     = base + F_Y0;
    float* y1     = base + F_Y1;
    float* outC   = (float*)d_out;
    float* outW   = (float*)d_out + (long)BB*NN*3;

    k_fill<<<2, 256>>>(statS, 0.f, 512);
    k_pad_w<<<128, 144>>>(c2_W0, w2p);

    // A: transpose + norms
    k_transpose_norm<<<BN, 128>>>(src_desc, srcd, nsqS, nrmS);
    k_transpose_norm<<<BN, 128>>>(dst_desc, dstd, nsqD, nrmD);

    // inner = src . dst (fp32, feeds KNN selection) + cos maxes + sims
    k_gemm<<<dim3(NN/BT, NN/BT, 2), dim3(16, 16)>>>(srcd, dstd, inner, NN, NN, CC,
        (long)NN*CC, (long)NN*CC, (long)NN*NN);
    k_fill<<<32, 256>>>(maxDS, -3.4e38f, 2*BN);
    k_rowmax<<<dim3(NN, BB), 256>>>(inner, nrmS, nrmD, maxDS);
    k_colmax<<<dim3(8, 16, 2), 256>>>(inner, nrmS, nrmD, maxSD);
    k_knn_desc<<<dim3(NN, BB), 256>>>(inner, nsqS, nsqD, idx);
    k_simgather<<<PP/256, 256>>>(inner, nrmS, nrmD, maxDS, maxSD, idx, sdc, dsc);

    // B: neighborhood descriptors
    k_knn_xyz<<<dim3(NN, BB), 256>>>(src_xyz, sidx);
    k_knn_xyz<<<dim3(NN, BB), 256>>>(dst_xyz, didx);
    const float* c2W1 = c2_W;
    const float* c2W2 = c2_W + CC*CC;
    for (int cloud = 0; cloud < 2; cloud++) {
        const float* xyz  = cloud ? dst_xyz : src_xyz;
        const float* dmat = cloud ? dstd : srcd;
        int* kidx         = cloud ? didx : sidx;
        float* outN       = cloud ? dstnbr : srcnbr;
        k_build_nbr_f<<<PP, 128>>>(xyz, dmat, kidx, fbuf);
        conv_bn(fbuf, w2p,  y0, PP, CC, 144, false, c2_g,        c2_b,        statS, sc, sh);
        conv_bn(y0,   c2W1, y1, PP, CC, CC,  true,  c2_g + CC,   c2_b + CC,   statS, sc, sh);
        conv_bn(y1,   c2W2, y0, PP, CC, CC,  true,  c2_g + 2*CC, c2_b + 2*CC, statS, sc, sh);
        k_nbr_final<<<BN, 256>>>(y0, sc, sh, kidx, dmat, outN);
    }

    // nbr cosine sims (fp32 inner)
    k_rownorm<<<BN, 128>>>(srcnbr, nrm2S);
    k_rownorm<<<BN, 128>>>(dstnbr, nrm2D);
    k_gemm<<<dim3(NN/BT, NN/BT, 2), dim3(16, 16)>>>(srcnbr, dstnbr, inner, NN, NN, CC,
        (long)NN*CC, (long)NN*CC, (long)NN*NN);
    k_fill<<<32, 256>>>(maxDS, -3.4e38f, 2*BN);
    k_rowmax<<<dim3(NN, BB), 256>>>(inner, nrm2S, nrm2D, maxDS);
    k_colmax<<<dim3(8, 16, 2), 256>>>(inner, nrm2S, nrm2D, maxSD);
    k_simgather<<<PP/256, 256>>>(inner, nrm2S, nrm2D, maxDS, maxSD, idx, sdn, dsn);

    // C: main feature conv + attention
    k_build_feats<<<PP, 128>>>(src_xyz, dst_xyz, srcd, dstd, src_w, dst_w,
                               sdc, dsc, sdn, dsn, idx, fbuf);
    const float* c1W1 = c1_W;
    const float* c1W2 = c1_W + 256*256;
    conv_bn(fbuf, c1_W0, y0, PP, 256, 272, false, c1_g,        c1_b,        statS, sc, sh);
    conv_bn(y0,   c1W1,  y1, PP, 256, 256, true,  c1_g + 256,  c1_b + 256,  statS, sc, sh);
    conv_bn(y1,   c1W2,  y0, PP, 256, 256, true,  c1_g + 512,  c1_b + 512,  statS, sc, sh);
    k_attention<<<BN, 256>>>(y0, sc, sh, idx, dst_xyz, outC, att);

    // D: MLP head
    conv_bn(att, m1_W, mb1, BN, 256, 256, false, m1_g, m1_b, statS, sc, sh);
    conv_bn(mb1, m2_W, mb2, BN, 256, 256, true,  m2_g, m2_b, statS, sc, sh);
    k_mlp3<<<BN, 256>>>(mb2, sc, sh, m3_W, m3_b, outW);
}

// round 7
// speedup vs baseline: 1.1497x; 1.0473x over previous
#include <cuda_runtime.h>
#include <mma.h>
#include <math.h>
#include <float.h>

using namespace nvcuda;

#define BB 2
#define NN 2048
#define CC 128
#define KK 16
#define BN (BB*NN)
#define PP (BB*NN*KK)
#define EPSF 1e-6f
#define BNEPS 1e-5f

// ---------------- scratch pool ----------------
constexpr long F_SRCD   = 0;
constexpr long F_DSTD   = F_SRCD   + (long)BN*CC;
constexpr long F_NSQS   = F_DSTD   + (long)BN*CC;
constexpr long F_NSQD   = F_NSQS   + BN;
constexpr long F_NRMS   = F_NSQD   + BN;
constexpr long F_NRMD   = F_NRMS   + BN;
constexpr long F_MAXDS  = F_NRMD   + BN;
constexpr long F_MAXSD  = F_MAXDS  + BN;
constexpr long F_NRM2S  = F_MAXSD  + BN;
constexpr long F_NRM2D  = F_NRM2S  + BN;
constexpr long F_SDC    = F_NRM2D  + BN;
constexpr long F_DSC    = F_SDC    + PP;
constexpr long F_SDN    = F_DSC    + PP;
constexpr long F_DSN    = F_SDN    + PP;
constexpr long F_STATS  = F_DSN    + PP;
constexpr long F_STATQ  = F_STATS  + 256;
constexpr long F_SC     = F_STATQ  + 256;
constexpr long F_SH     = F_SC     + 256;
constexpr long F_W2P    = F_SH     + 256;          // padded c2_W0 [128][144]
constexpr long F_IDX    = F_W2P    + 128*144;      // int
constexpr long F_SIDX   = F_IDX    + PP;
constexpr long F_DIDX   = F_SIDX   + PP;
constexpr long F_ATT    = F_DIDX   + PP;
constexpr long F_MB1    = F_ATT    + (long)BN*256;
constexpr long F_MB2    = F_MB1    + (long)BN*256;
constexpr long F_SRCNBR = F_MB2    + (long)BN*256;
constexpr long F_DSTNBR = F_SRCNBR + (long)BN*CC;
constexpr long F_INNER  = F_DSTNBR + (long)BN*CC;
constexpr long F_F      = F_INNER  + (long)BB*NN*NN;
constexpr long F_Y0     = F_F      + (long)PP*272;
constexpr long F_Y1     = F_Y0     + (long)PP*256;
constexpr long F_END    = F_Y1     + (long)PP*256;

__device__ __align__(128) float g_pool[F_END];

__device__ __forceinline__ void atomicMaxF(float* a, float v) {
    if (!(v < 0.f)) atomicMax((int*)a, __float_as_int(v));
    else            atomicMin((unsigned int*)a, __float_as_uint(v));
}

__global__ void k_fill(float* __restrict__ p, float v, int n) {
    int i = blockIdx.x * blockDim.x + threadIdx.x;
    if (i < n) p[i] = v;
}

__global__ void k_pad_w(const float* __restrict__ W, float* __restrict__ Wp) {
    int o = blockIdx.x; int k = threadIdx.x; // 144 threads
    Wp[o * 144 + k] = (k < 132) ? W[o * 132 + k] : 0.f;
}

// [B,C,N] -> [B,N,C] plus |.|^2 and |.|
__global__ void k_transpose_norm(const float* __restrict__ desc, float* __restrict__ dmat,
                                 float* __restrict__ nsq, float* __restrict__ nrm) {
    int bn = blockIdx.x; int b = bn >> 11; int n = bn & (NN - 1);
    int c = threadIdx.x;
    float v = desc[((long)b*CC + c)*NN + n];
    dmat[(long)bn*CC + c] = v;
    float s = v * v;
    #pragma unroll
    for (int o = 16; o > 0; o >>= 1) s += __shfl_down_sync(0xffffffffu, s, o);
    __shared__ float ps[4];
    if ((c & 31) == 0) ps[c >> 5] = s;
    __syncthreads();
    if (c == 0) { float t = ps[0]+ps[1]+ps[2]+ps[3]; nsq[bn] = t; nrm[bn] = sqrtf(t); }
}

__global__ void k_rownorm(const float* __restrict__ dmat, float* __restrict__ nrm) {
    int bn = blockIdx.x; int c = threadIdx.x;
    float v = dmat[(long)bn*CC + c];
    float s = v * v;
    #pragma unroll
    for (int o = 16; o > 0; o >>= 1) s += __shfl_down_sync(0xffffffffu, s, o);
    __shared__ float ps[4];
    if ((c & 31) == 0) ps[c >> 5] = s;
    __syncthreads();
    if (c == 0) nrm[bn] = sqrtf(ps[0]+ps[1]+ps[2]+ps[3]);
}

// ---------------- split-tf32 inner GEMM + fused cosine maxes ----------------
// inner[b][n][m] = srcRow(n) . dstRow(m); also maxDS[n]=max_m cos, maxSD[m]=max_n cos.
// 128(rows n) x 64(cols m) tile, 8 warps 4Mx2N, warp tile 32x32.
// Split precision: v = hi + lo (both tf32); C += hi*hi + hi*lo + lo*hi  (~fp32 accurate).
#define SGM 128
#define SGN 64
#define SLD 20
#define SCLD 68

__global__ __launch_bounds__(256)
void k_gemm_sim(const float* __restrict__ A, const float* __restrict__ Bm,
                float* __restrict__ Cm,
                const float* __restrict__ nrmA, const float* __restrict__ nrmB,
                float* __restrict__ maxDS, float* __restrict__ maxSD) {
    const int b = blockIdx.z;
    A  += (long)b * NN * CC;
    Bm += (long)b * NN * CC;
    Cm += (long)b * NN * NN;

    __shared__ __align__(16) float smem[SGM * SCLD];  // union: staging / C staging
    float* Ahi = smem;                       // 128*20
    float* Alo = smem + SGM*SLD;             // 128*20
    float* Bhi = smem + 2*SGM*SLD;           // 64*20
    float* Blo = smem + 2*SGM*SLD + SGN*SLD; // 64*20  (total 7680 < 8704)
    float* Csm = smem;
    __shared__ float rns[SGM], rnd[SGN], rm[SGM], cmx[SGN];

    const int tid = threadIdx.x;
    const int lane = tid & 31;
    const int wid = tid >> 5;
    const int wm = wid & 3;
    const int wn = wid >> 2;
    const long rowBase = (long)blockIdx.y * SGM;
    const int colBase = blockIdx.x * SGN;

    if (tid < SGM) { rns[tid] = nrmA[b*NN + rowBase + tid]; rm[tid] = -3.4e38f; }
    if (tid < SGN) { rnd[tid] = nrmB[b*NN + colBase + tid]; cmx[tid] = -3.4e38f; }

    const int ma = tid >> 2;          // 0..63
    const int kq = (tid & 3) * 4;

    wmma::fragment<wmma::accumulator, 16, 16, 8, float> c[2][2];
    #pragma unroll
    for (int i = 0; i < 2; i++)
        #pragma unroll
        for (int j = 0; j < 2; j++)
            wmma::fill_fragment(c[i][j], 0.f);

    const int nk = CC / 16;
    for (int kc = 0; kc < nk; kc++) {
        const int k0 = kc * 16;
        // stage A rows (2 per thread) split hi/lo
        #pragma unroll
        for (int e = 0; e < 2; e++) {
            int m = ma + e * 64;
            float4 v = *reinterpret_cast<const float4*>(&A[(rowBase + m) * CC + k0 + kq]);
            float4 h, l;
            h.x = wmma::__float_to_tf32(v.x); l.x = wmma::__float_to_tf32(v.x - h.x);
            h.y = wmma::__float_to_tf32(v.y); l.y = wmma::__float_to_tf32(v.y - h.y);
            h.z = wmma::__float_to_tf32(v.z); l.z = wmma::__float_to_tf32(v.z - h.z);
            h.w = wmma::__float_to_tf32(v.w); l.w = wmma::__float_to_tf32(v.w - h.w);
            *reinterpret_cast<float4*>(&Ahi[m * SLD + kq]) = h;
            *reinterpret_cast<float4*>(&Alo[m * SLD + kq]) = l;
        }
        // stage B (1 float4 per thread)
        {
            int m = ma & 63;
            float4 v = *reinterpret_cast<const float4*>(&Bm[(long)(colBase + m) * CC + k0 + kq]);
            float4 h, l;
            h.x = wmma::__float_to_tf32(v.x); l.x = wmma::__float_to_tf32(v.x - h.x);
            h.y = wmma::__float_to_tf32(v.y); l.y = wmma::__float_to_tf32(v.y - h.y);
            h.z = wmma::__float_to_tf32(v.z); l.z = wmma::__float_to_tf32(v.z - h.z);
            h.w = wmma::__float_to_tf32(v.w); l.w = wmma::__float_to_tf32(v.w - h.w);
            *reinterpret_cast<float4*>(&Bhi[m * SLD + kq]) = h;
            *reinterpret_cast<float4*>(&Blo[m * SLD + kq]) = l;
        }
        __syncthreads();
        #pragma unroll
        for (int ks = 0; ks < 2; ks++) {
            wmma::fragment<wmma::matrix_a, 16, 16, 8, wmma::precision::tf32, wmma::row_major> ah[2], al[2];
            wmma::fragment<wmma::matrix_b, 16, 16, 8, wmma::precision::tf32, wmma::col_major> bh[2], bl[2];
            #pragma unroll
            for (int i = 0; i < 2; i++) {
                wmma::load_matrix_sync(ah[i], &Ahi[(wm*32 + i*16) * SLD + ks*8], SLD);
                wmma::load_matrix_sync(al[i], &Alo[(wm*32 + i*16) * SLD + ks*8], SLD);
            }
            #pragma unroll
            for (int j = 0; j < 2; j++) {
                wmma::load_matrix_sync(bh[j], &Bhi[(wn*32 + j*16) * SLD + ks*8], SLD);
                wmma::load_matrix_sync(bl[j], &Blo[(wn*32 + j*16) * SLD + ks*8], SLD);
            }
            #pragma unroll
            for (int i = 0; i < 2; i++)
                #pragma unroll
                for (int j = 0; j < 2; j++) {
                    wmma::mma_sync(c[i][j], ah[i], bh[j], c[i][j]);
                    wmma::mma_sync(c[i][j], ah[i], bl[j], c[i][j]);
                    wmma::mma_sync(c[i][j], al[i], bh[j], c[i][j]);
                }
        }
        __syncthreads();
    }

    // epilogue: store + fused cosine row/col maxes
    #pragma unroll
    for (int i = 0; i < 2; i++)
        #pragma unroll
        for (int j = 0; j < 2; j++)
            wmma::store_matrix_sync(&Csm[(wm*32 + i*16) * SCLD + wn*32 + j*16], c[i][j],
                                    SCLD, wmma::mem_row_major);
    __syncthreads();

    const int ccol = tid & 63;
    const int r0 = tid >> 6;          // 0..3
    const float nd = rnd[ccol];
    float colmax = -3.4e38f;
    #pragma unroll 8
    for (int it = 0; it < 32; it++) {
        int r = r0 + it * 4;
        float v = Csm[r * SCLD + ccol];
        Cm[(rowBase + r) * NN + colBase + ccol] = v;
        float csv = v / (nd * rns[r] + EPSF);
        colmax = fmaxf(colmax, csv);
        float wmx = csv;    // lanes in a warp share row r, span 32 cols
        #pragma unroll
        for (int o = 16; o > 0; o >>= 1) wmx = fmaxf(wmx, __shfl_down_sync(0xffffffffu, wmx, o));
        if (lane == 0) atomicMaxF(&rm[r], wmx);
    }
    atomicMaxF(&cmx[ccol], colmax);
    __syncthreads();
    if (tid < SGM) atomicMaxF(&maxDS[b*NN + rowBase + tid], rm[tid]);
    else if (tid < SGM + SGN) atomicMaxF(&maxSD[b*NN + colBase + (tid - SGM)], cmx[tid - SGM]);
}

// ---------------- TF32 TC GEMM (v1, the 1391us version): 128x64, single-buffered ----------------
#define TCM 128
#define TCN 64
#define ALD 20
#define CLD 68

__global__ __launch_bounds__(256)
void k_gemm_tc(const float* __restrict__ A, const float* __restrict__ Bm,
               float* __restrict__ Cm, int P, int O, int Kd,
               const float* __restrict__ scA, const float* __restrict__ shA,
               float* __restrict__ statS, float* __restrict__ statQ) {
    __shared__ __align__(16) float smem[TCM * CLD];   // union: As+Bs during loop, Csm after
    float* As = smem;                 // [128][ALD]
    float* Bs = smem + TCM * ALD;     // [64][ALD]
    float* Csm = smem;                // [128][CLD]
    __shared__ float cs[TCN], cq[TCN];

    const int tid = threadIdx.x;
    const int wid = tid >> 5;
    const int wm = wid & 3;           // 0..3 along M
    const int wn = wid >> 2;          // 0..1 along N
    const int rowBase = blockIdx.y * TCM;
    const int colBase = blockIdx.x * TCN;
    const bool aff = (scA != nullptr);
    const bool stats = (statS != nullptr);

    if (stats && tid < TCN) { cs[tid] = 0.f; cq[tid] = 0.f; }

    wmma::fragment<wmma::accumulator, 16, 16, 8, float> c[2][2];
    #pragma unroll
    for (int i = 0; i < 2; i++)
        #pragma unroll
        for (int j = 0; j < 2; j++)
            wmma::fill_fragment(c[i][j], 0.f);

    const int nk = Kd / 16;
    for (int kc = 0; kc < nk; kc++) {
        const int k0 = kc * 16;
        // stage A (128x16) with optional affine+ReLU: 2 float4 per thread
        #pragma unroll
        for (int e = 0; e < 2; e++) {
            int lin = e * 256 + tid;
            int m = lin >> 2;
            int kq = (lin & 3) * 4;
            float4 v = *reinterpret_cast<const float4*>(&A[(long)(rowBase + m) * Kd + k0 + kq]);
            if (aff) {
                int gk = k0 + kq;
                v.x = fmaxf(v.x * scA[gk+0] + shA[gk+0], 0.f);
                v.y = fmaxf(v.y * scA[gk+1] + shA[gk+1], 0.f);
                v.z = fmaxf(v.z * scA[gk+2] + shA[gk+2], 0.f);
                v.w = fmaxf(v.w * scA[gk+3] + shA[gk+3], 0.f);
            }
            *reinterpret_cast<float4*>(&As[m * ALD + kq]) = v;
        }
        // stage B (64x16): 1 float4 per thread
        {
            int m = tid >> 2;
            int kq = (tid & 3) * 4;
            float4 v = *reinterpret_cast<const float4*>(&Bm[(long)(colBase + m) * Kd + k0 + kq]);
            *reinterpret_cast<float4*>(&Bs[m * ALD + kq]) = v;
        }
        __syncthreads();
        #pragma unroll
        for (int ks = 0; ks < 2; ks++) {
            wmma::fragment<wmma::matrix_a, 16, 16, 8, wmma::precision::tf32, wmma::row_major> a[2];
            wmma::fragment<wmma::matrix_b, 16, 16, 8, wmma::precision::tf32, wmma::col_major> b[2];
            #pragma unroll
            for (int i = 0; i < 2; i++) {
                wmma::load_matrix_sync(a[i], &As[(wm*32 + i*16) * ALD + ks*8], ALD);
                #pragma unroll
                for (int t = 0; t < a[i].num_elements; t++)
                    a[i].x[t] = wmma::__float_to_tf32(a[i].x[t]);
            }
            #pragma unroll
            for (int j = 0; j < 2; j++) {
                wmma::load_matrix_sync(b[j], &Bs[(wn*32 + j*16) * ALD + ks*8], ALD);
                #pragma unroll
                for (int t = 0; t < b[j].num_elements; t++)
                    b[j].x[t] = wmma::__float_to_tf32(b[j].x[t]);
            }
            #pragma unroll
            for (int i = 0; i < 2; i++)
                #pragma unroll
                for (int j = 0; j < 2; j++)
                    wmma::mma_sync(c[i][j], a[i], b[j], c[i][j]);
        }
        __syncthreads();
    }

    // stage C to smem for coalesced store + stats
    #pragma unroll
    for (int i = 0; i < 2; i++)
        #pragma unroll
        for (int j = 0; j < 2; j++)
            wmma::store_matrix_sync(&Csm[(wm*32 + i*16) * CLD + wn*32 + j*16], c[i][j],
                                    CLD, wmma::mem_row_major);
    __syncthreads();

    const int ccol = tid & 63;
    const int r0 = tid >> 6;
    float s = 0.f, q = 0.f;
    #pragma unroll 8
    for (int it = 0; it < 32; it++) {
        int r = r0 + it * 4;
        float v = Csm[r * CLD + ccol];
        Cm[(long)(rowBase + r) * O + colBase + ccol] = v;
        s += v; q += v * v;
    }
    if (stats) {
        atomicAdd(&cs[ccol], s);
        atomicAdd(&cq[ccol], q);
        __syncthreads();
        if (tid < TCN) {
            atomicAdd(&statS[colBase + tid], cs[tid]);
            atomicAdd(&statQ[colBase + tid], cq[tid]);
        }
    }
}

__global__ void k_finalize(const float* __restrict__ statSin, const float* __restrict__ statQin,
                           const float* __restrict__ g, const float* __restrict__ bb,
                           float* __restrict__ sc, float* __restrict__ sh, int O, float invP) {
    int o = blockIdx.x * blockDim.x + threadIdx.x;
    if (o < O) {
        float mu  = statSin[o] * invP;
        float var = fmaxf(statQin[o] * invP - mu * mu, 0.f);
        float s   = g[o] * rsqrtf(var + BNEPS);
        sc[o] = s;
        sh[o] = bb[o] - mu * s;
        ((float*)statSin)[o] = 0.f;
        ((float*)statQin)[o] = 0.f;
    }
}

// top-16 smallest from shared d2[NN], 256 threads
__device__ void select_topk(float* d2, int* outIdx) {
    __shared__ float rv[8];
    __shared__ int   ri[8];
    int tid = threadIdx.x, lane = tid & 31, w = tid >> 5;
    for (int kk = 0; kk < KK; kk++) {
        float best = 3.4e38f; int bi = 0;
        for (int m = tid; m < NN; m += 256) {
            float v = d2[m];
            if (v < best) { best = v; bi = m; }
        }
        #pragma unroll
        for (int o = 16; o > 0; o >>= 1) {
            float ov = __shfl_down_sync(0xffffffffu, best, o);
            int   oi = __shfl_down_sync(0xffffffffu, bi, o);
            if (ov < best || (ov == best && oi < bi)) { best = ov; bi = oi; }
        }
        if (lane == 0) { rv[w] = best; ri[w] = bi; }
        __syncthreads();
        if (tid == 0) {
            float bv = rv[0]; int bj = ri[0];
            #pragma unroll
            for (int i = 1; i < 8; i++)
                if (rv[i] < bv || (rv[i] == bv && ri[i] < bj)) { bv = rv[i]; bj = ri[i]; }
            outIdx[kk] = bj;
            d2[bj] = 3.4e38f;
        }
        __syncthreads();
    }
}

__global__ void k_knn_desc(const float* __restrict__ inner, const float* __restrict__ nsqS,
                           const float* __restrict__ nsqD, int* __restrict__ idxOut) {
    int n = blockIdx.x, b = blockIdx.y;
    __shared__ float d2[NN];
    const float* row = inner + (long)b*NN*NN + (long)n*NN;
    float q = nsqS[b*NN + n];
    for (int m = threadIdx.x; m < NN; m += 256) d2[m] = q + nsqD[b*NN + m] - 2.f * row[m];
    __syncthreads();
    select_topk(d2, idxOut + ((long)b*NN + n) * KK);
}

__global__ void k_knn_xyz(const float* __restrict__ xyz, int* __restrict__ idxOut) {
    int n = blockIdx.x, b = blockIdx.y;
    __shared__ float d2[NN];
    long base = (long)b * NN * 3;
    float qx = xyz[base + (long)n*3], qy = xyz[base + (long)n*3+1], qz = xyz[base + (long)n*3+2];
    float qq = qx*qx + qy*qy + qz*qz;
    for (int m = threadIdx.x; m < NN; m += 256) {
        float rx = xyz[base + (long)m*3], ry = xyz[base + (long)m*3+1], rz = xyz[base + (long)m*3+2];
        d2[m] = qq + rx*rx + ry*ry + rz*rz - 2.f*(qx*rx + qy*ry + qz*rz);
    }
    __syncthreads();
    select_topk(d2, idxOut + ((long)b*NN + n) * KK);
}

__global__ void k_simgather(const float* __restrict__ inner, const float* __restrict__ nrmS,
                            const float* __restrict__ nrmD, const float* __restrict__ maxDS,
                            const float* __restrict__ maxSD, const int* __restrict__ idx,
                            float* __restrict__ outSD, float* __restrict__ outDS) {
    int t = blockIdx.x * 256 + threadIdx.x;
    if (t >= PP) return;
    int b = t / (NN * KK);
    int n = (t / KK) & (NN - 1);
    int m = idx[t];
    float v  = inner[(long)b*NN*NN + (long)n*NN + m];
    float cs = v / (nrmD[b*NN + m] * nrmS[b*NN + n] + EPSF);
    outSD[t] = cs / (maxDS[b*NN + n] + EPSF);
    outDS[t] = cs / (maxSD[b*NN + m] + EPSF);
}

// nbr conv input: [knn_feats(C), rela(3), dist(1), pad(8)] stride 144
__global__ void k_build_nbr_f(const float* __restrict__ xyz, const float* __restrict__ dmat,
                              const int* __restrict__ idx, float* __restrict__ f) {
    int p = blockIdx.x;
    int n = (p / KK) & (NN - 1);
    int b = p / (NN * KK);
    int m = idx[p];
    const float* dr = dmat + ((long)b*NN + m) * CC;
    float* fo = f + (long)p * 144;
    int tid = threadIdx.x;
    fo[tid] = dr[tid];
    if (tid == 0) {
        long qb = ((long)b*NN + n) * 3, rb = ((long)b*NN + m) * 3;
        float rx = xyz[rb]-xyz[qb], ry = xyz[rb+1]-xyz[qb+1], rz = xyz[rb+2]-xyz[qb+2];
        fo[128] = rx; fo[129] = ry; fo[130] = rz; fo[131] = sqrtf(rx*rx+ry*ry+rz*rz);
        #pragma unroll
        for (int z = 132; z < 144; z++) fo[z] = 0.f;
    }
}

__global__ void k_nbr_final(const float* __restrict__ yraw, const float* __restrict__ sc,
                            const float* __restrict__ sh, const int* __restrict__ idx,
                            const float* __restrict__ dmat, float* __restrict__ outN) {
    int bn = blockIdx.x, tid = threadIdx.x; // 256
    __shared__ float fe[KK][CC];
    __shared__ float mk[KK], wgt[KK];
    __shared__ int sid[KK];
    if (tid < KK) sid[tid] = idx[(long)bn*KK + tid];
    for (int t = tid; t < KK * CC; t += 256) {
        int k = t >> 7, c = t & 127;
        float v = yraw[((long)bn*KK + k) * CC + c];
        fe[k][c] = fmaxf(v * sc[c] + sh[c], 0.f);
    }
    __syncthreads();
    int w = tid >> 5, lane = tid & 31;
    for (int kk = w; kk < KK; kk += 8) {
        float mx = -3.4e38f;
        for (int c = lane; c < CC; c += 32) mx = fmaxf(mx, fe[kk][c]);
        #pragma unroll
        for (int o = 16; o > 0; o >>= 1) mx = fmaxf(mx, __shfl_down_sync(0xffffffffu, mx, o));
        if (lane == 0) mk[kk] = mx;
    }
    __syncthreads();
    if (tid == 0) {
        float m = -3.4e38f;
        for (int k = 0; k < KK; k++) m = fmaxf(m, mk[k]);
        float s = 0.f;
        for (int k = 0; k < KK; k++) { float e = expf(mk[k]-m); wgt[k] = e; s += e; }
        float r = 1.f / s;
        for (int k = 0; k < KK; k++) wgt[k] *= r;
    }
    __syncthreads();
    if (tid < CC) {
        int b = bn >> 11;
        float a = 0.f;
        #pragma unroll
        for (int k = 0; k < KK; k++) a += wgt[k] * dmat[((long)b*NN + sid[k]) * CC + tid];
        outN[(long)bn*CC + tid] = a;
    }
}

// main feats build (272 ch)
__global__ void k_build_feats(const float* __restrict__ src_xyz, const float* __restrict__ dst_xyz,
                              const float* __restrict__ srcd, const float* __restrict__ dstd,
                              const float* __restrict__ srcw, const float* __restrict__ dstw,
                              const float* __restrict__ sdc, const float* __restrict__ dsc,
                              const float* __restrict__ sdn, const float* __restrict__ dsn,
                              const int* __restrict__ idx, float* __restrict__ feats) {
    int p = blockIdx.x;
    int n = (p / KK) & (NN - 1);
    int b = p / (NN * KK);
    int m = idx[p];
    float* fo = feats + (long)p * 272;
    int tid = threadIdx.x;
    fo[10 + tid]  = srcd[((long)b*NN + n) * CC + tid];
    fo[138 + tid] = dstd[((long)b*NN + m) * CC + tid];
    if (tid == 0) {
        long qb = ((long)b*NN + n) * 3, rb = ((long)b*NN + m) * 3;
        float sx = src_xyz[qb], sy = src_xyz[qb+1], sz = src_xyz[qb+2];
        float kx = dst_xyz[rb], ky = dst_xyz[rb+1], kz = dst_xyz[rb+2];
        float rx = kx-sx, ry = ky-sy, rz = kz-sz;
        fo[0]=rx; fo[1]=ry; fo[2]=rz; fo[3]=sqrtf(rx*rx+ry*ry+rz*rz);
        fo[4]=sx; fo[5]=sy; fo[6]=sz; fo[7]=kx; fo[8]=ky; fo[9]=kz;
        fo[266]=srcw[b*NN+n]; fo[267]=dstw[b*NN+m];
        fo[268]=sdc[p]; fo[269]=dsc[p]; fo[270]=sdn[p]; fo[271]=dsn[p];
    }
}

__global__ void k_attention(const float* __restrict__ yraw, const float* __restrict__ sc,
                            const float* __restrict__ sh, const int* __restrict__ idx,
                            const float* __restrict__ dst_xyz,
                            float* __restrict__ outC, float* __restrict__ att) {
    int bn = blockIdx.x, tid = threadIdx.x; // 256
    __shared__ float fe[KK][256];
    __shared__ float mk[KK], wgt[KK];
    __shared__ int sid[KK];
    if (tid < KK) sid[tid] = idx[(long)bn*KK + tid];
    float s = sc[tid], h = sh[tid];
    #pragma unroll
    for (int k = 0; k < KK; k++) {
        float v = yraw[((long)bn*KK + k) * 256 + tid];
        fe[k][tid] = fmaxf(v * s + h, 0.f);
    }
    __syncthreads();
    int w = tid >> 5, lane = tid & 31;
    for (int kk = w; kk < KK; kk += 8) {
        float mx = -3.4e38f;
        for (int c = lane; c < 256; c += 32) mx = fmaxf(mx, fe[kk][c]);
        #pragma unroll
        for (int o = 16; o > 0; o >>= 1) mx = fmaxf(mx, __shfl_down_sync(0xffffffffu, mx, o));
        if (lane == 0) mk[kk] = mx;
    }
    __syncthreads();
    if (tid == 0) {
        float m = -3.4e38f;
        for (int k = 0; k < KK; k++) m = fmaxf(m, mk[k]);
        float ssum = 0.f;
        for (int k = 0; k < KK; k++) { float e = expf(mk[k]-m); wgt[k] = e; ssum += e; }
        float r = 1.f / ssum;
        for (int k = 0; k < KK; k++) wgt[k] *= r;
    }
    __syncthreads();
    float a = 0.f;
    #pragma unroll
    for (int k = 0; k < KK; k++) a += wgt[k] * fe[k][tid];
    att[(long)bn * 256 + tid] = a;
    if (tid < 3) {
        int b = bn >> 11;
        float cg = 0.f;
        #pragma unroll
        for (int k = 0; k < KK; k++)
            cg += wgt[k] * dst_xyz[((long)b*NN + sid[k]) * 3 + tid];
        outC[(long)bn * 3 + tid] = cg;
    }
}

__global__ void k_mlp3(const float* __restrict__ yraw, const float* __restrict__ sc,
                       const float* __restrict__ sh, const float* __restrict__ w3,
                       const float* __restrict__ b3, float* __restrict__ outw) {
    int bn = blockIdx.x, tid = threadIdx.x; // 256
    float v = fmaxf(yraw[(long)bn*256 + tid] * sc[tid] + sh[tid], 0.f) * w3[tid];
    #pragma unroll
    for (int o = 16; o > 0; o >>= 1) v += __shfl_down_sync(0xffffffffu, v, o);
    __shared__ float ps[8];
    if ((tid & 31) == 0) ps[tid >> 5] = v;
    __syncthreads();
    if (tid == 0) {
        float s2 = 0.f;
        #pragma unroll
        for (int i = 0; i < 8; i++) s2 += ps[i];
        outw[bn] = 1.f / (1.f + expf(-(s2 + b3[0])));
    }
}

// ---------------- host side ----------------
static void conv_bn(const float* A, const float* W, float* Y, int P, int O, int Kd,
                    bool aff, const float* g, const float* bb,
                    float* statS, float* sc, float* sh) {
    k_gemm_tc<<<dim3(O/TCN, P/TCM), 256>>>(A, W, Y, P, O, Kd,
        aff ? sc : nullptr, aff ? sh : nullptr, statS, statS + 256);
    k_finalize<<<1, 256>>>(statS, statS + 256, g, bb, sc, sh, O, 1.f / (float)P);
}

extern "C" void kernel_launch(void* const* d_in, const int* in_sizes, int n_in,
                              void* d_out, int out_size) {
    const float* src_xyz  = (const float*)d_in[0];
    const float* src_desc = (const float*)d_in[1];
    const float* dst_xyz  = (const float*)d_in[2];
    const float* dst_desc = (const float*)d_in[3];
    const float* src_w    = (const float*)d_in[4];
    const float* dst_w    = (const float*)d_in[5];
    const float* c1_W0 = (const float*)d_in[6];
    const float* c1_W  = (const float*)d_in[7];
    const float* c1_g  = (const float*)d_in[8];
    const float* c1_b  = (const float*)d_in[9];
    const float* c2_W0 = (const float*)d_in[10];
    const float* c2_W  = (const float*)d_in[11];
    const float* c2_g  = (const float*)d_in[12];
    const float* c2_b  = (const float*)d_in[13];
    const float* m1_W  = (const float*)d_in[14];
    const float* m1_g  = (const float*)d_in[16];
    const float* m1_b  = (const float*)d_in[17];
    const float* m2_W  = (const float*)d_in[18];
    const float* m2_g  = (const float*)d_in[20];
    const float* m2_b  = (const float*)d_in[21];
    const float* m3_W  = (const float*)d_in[22];
    const float* m3_b  = (const float*)d_in[23];

    float* base = nullptr;
    cudaGetSymbolAddress((void**)&base, g_pool);
    float* srcd   = base + F_SRCD;
    float* dstd   = base + F_DSTD;
    float* nsqS   = base + F_NSQS;
    float* nsqD   = base + F_NSQD;
    float* nrmS   = base + F_NRMS;
    float* nrmD   = base + F_NRMD;
    float* maxDS  = base + F_MAXDS;
    float* maxSD  = base + F_MAXSD;
    float* nrm2S  = base + F_NRM2S;
    float* nrm2D  = base + F_NRM2D;
    float* sdc    = base + F_SDC;
    float* dsc    = base + F_DSC;
    float* sdn    = base + F_SDN;
    float* dsn    = base + F_DSN;
    float* statS  = base + F_STATS;
    float* sc     = base + F_SC;
    float* sh     = base + F_SH;
    float* w2p    = base + F_W2P;
    int*   idx    = (int*)(base + F_IDX);
    int*   sidx   = (int*)(base + F_SIDX);
    int*   didx   = (int*)(base + F_DIDX);
    float* att    = base + F_ATT;
    float* mb1    = base + F_MB1;
    float* mb2    = base + F_MB2;
    float* srcnbr = base + F_SRCNBR;
    float* dstnbr = base + F_DSTNBR;
    float* inner  = base + F_INNER;
    float* fbuf   = base + F_F;
    float* y0     = base + F_Y0;
    float* y1     = base + F_Y1;
    float* outC   = (float*)d_out;
    float* outW   = (float*)d_out + (long)BB*NN*3;

    k_fill<<<2, 256>>>(statS, 0.f, 512);
    k_pad_w<<<128, 144>>>(c2_W0, w2p);

    // A: transpose + norms
    k_transpose_norm<<<BN, 128>>>(src_desc, srcd, nsqS, nrmS);
    k_transpose_norm<<<BN, 128>>>(dst_desc, dstd, nsqD, nrmD);

    // inner = src . dst (split-tf32 TC, fp32-accurate) with fused cosine maxes
    k_fill<<<32, 256>>>(maxDS, -3.4e38f, 2*BN);
    k_gemm_sim<<<dim3(NN/SGN, NN/SGM, 2), 256>>>(srcd, dstd, inner, nrmS, nrmD, maxDS, maxSD);
    k_knn_desc<<<dim3(NN, BB), 256>>>(inner, nsqS, nsqD, idx);
    k_simgather<<<PP/256, 256>>>(inner, nrmS, nrmD, maxDS, maxSD, idx, sdc, dsc);

    // B: neighborhood descriptors
    k_knn_xyz<<<dim3(NN, BB), 256>>>(src_xyz, sidx);
    k_knn_xyz<<<dim3(NN, BB), 256>>>(dst_xyz, didx);
    const float* c2W1 = c2_W;
    const float* c2W2 = c2_W + CC*CC;
    for (int cloud = 0; cloud < 2; cloud++) {
        const float* xyz  = cloud ? dst_xyz : src_xyz;
        const float* dmat = cloud ? dstd : srcd;
        int* kidx         = cloud ? didx : sidx;
        float* outN       = cloud ? dstnbr : srcnbr;
        k_build_nbr_f<<<PP, 128>>>(xyz, dmat, kidx, fbuf);
        conv_bn(fbuf, w2p,  y0, PP, CC, 144, false, c2_g,        c2_b,        statS, sc, sh);
        conv_bn(y0,   c2W1, y1, PP, CC, CC,  true,  c2_g + CC,   c2_b + CC,   statS, sc, sh);
        conv_bn(y1,   c2W2, y0, PP, CC, CC,  true,  c2_g + 2*CC, c2_b + 2*CC, statS, sc, sh);
        k_nbr_final<<<BN, 256>>>(y0, sc, sh, kidx, dmat, outN);
    }

    // nbr cosine sims (split-tf32 TC inner with fused maxes)
    k_rownorm<<<BN, 128>>>(srcnbr, nrm2S);
    k_rownorm<<<BN, 128>>>(dstnbr, nrm2D);
    k_fill<<<32, 256>>>(maxDS, -3.4e38f, 2*BN);
    k_gemm_sim<<<dim3(NN/SGN, NN/SGM, 2), 256>>>(srcnbr, dstnbr, inner, nrm2S, nrm2D, maxDS, maxSD);
    k_simgather<<<PP/256, 256>>>(inner, nrm2S, nrm2D, maxDS, maxSD, idx, sdn, dsn);

    // C: main feature conv + attention
    k_build_feats<<<PP, 128>>>(src_xyz, dst_xyz, srcd, dstd, src_w, dst_w,
                               sdc, dsc, sdn, dsn, idx, fbuf);
    const float* c1W1 = c1_W;
    const float* c1W2 = c1_W + 256*256;
    conv_bn(fbuf, c1_W0, y0, PP, 256, 272, false, c1_g,        c1_b,        statS, sc, sh);
    conv_bn(y0,   c1W1,  y1, PP, 256, 256, true,  c1_g + 256,  c1_b + 256,  statS, sc, sh);
    conv_bn(y1,   c1W2,  y0, PP, 256, 256, true,  c1_g + 512,  c1_b + 512,  statS, sc, sh);
    k_attention<<<BN, 256>>>(y0, sc, sh, idx, dst_xyz, outC, att);

    // D: MLP head
    conv_bn(att, m1_W, mb1, BN, 256, 256, false, m1_g, m1_b, statS, sc, sh);
    conv_bn(mb1, m2_W, mb2, BN, 256, 256, true,  m2_g, m2_b, statS, sc, sh);
    k_mlp3<<<BN, 256>>>(mb2, sc, sh, m3_W, m3_b, outW);
}

// round 9
// speedup vs baseline: 1.1590x; 1.0081x over previous
#include <cuda_runtime.h>
#include <mma.h>
#include <math.h>
#include <float.h>

using namespace nvcuda;

#define BB 2
#define NN 2048
#define CC 128
#define KK 16
#define BN (BB*NN)
#define PP (BB*NN*KK)
#define EPSF 1e-6f
#define BNEPS 1e-5f

// ---------------- scratch pool ----------------
constexpr long F_SRCD   = 0;
constexpr long F_DSTD   = F_SRCD   + (long)BN*CC;   // contiguous with SRCD
constexpr long F_NSQS   = F_DSTD   + (long)BN*CC;
constexpr long F_NSQD   = F_NSQS   + BN;
constexpr long F_NRMS   = F_NSQD   + BN;
constexpr long F_NRMD   = F_NRMS   + BN;
constexpr long F_MAXDS  = F_NRMD   + BN;
constexpr long F_MAXSD  = F_MAXDS  + BN;
constexpr long F_NRM2S  = F_MAXSD  + BN;
constexpr long F_NRM2D  = F_NRM2S  + BN;
constexpr long F_SDC    = F_NRM2D  + BN;
constexpr long F_DSC    = F_SDC    + PP;
constexpr long F_SDN    = F_DSC    + PP;
constexpr long F_DSN    = F_SDN    + PP;
constexpr long F_STATS  = F_DSN    + PP;
constexpr long F_STATQ  = F_STATS  + 256;
constexpr long F_SC     = F_STATQ  + 256;
constexpr long F_SH     = F_SC     + 256;
constexpr long F_W2P    = F_SH     + 256;          // padded c2_W0 [128][144]
constexpr long F_IDX    = F_W2P    + 128*144;      // int
constexpr long F_SIDX   = F_IDX    + PP;           // sidx then didx contiguous
constexpr long F_DIDX   = F_SIDX   + PP;
constexpr long F_ATT    = F_DIDX   + PP;
constexpr long F_MB1    = F_ATT    + (long)BN*256;
constexpr long F_MB2    = F_MB1    + (long)BN*256;
constexpr long F_SRCNBR = F_MB2    + (long)BN*256;  // srcnbr then dstnbr contiguous
constexpr long F_DSTNBR = F_SRCNBR + (long)BN*CC;
constexpr long F_INNER  = F_DSTNBR + (long)BN*CC;
constexpr long F_F      = F_INNER  + (long)BB*NN*NN;
// F region must hold BOTH uses: main feats PP*272 = 17,825,792 floats AND
// batched nbr feats 2*PP*144 = 18,874,368 floats. Take the max (prev round
// under-sized this -> overflow into Y0 -> rel_err 7.7e-3).
constexpr long F_FSZ    = (long)2*PP*144;           // 18,874,368 > PP*272
constexpr long F_Y0     = F_F      + F_FSZ;         // also 2PP*128 view (= PP*256 exactly)
constexpr long F_Y1     = F_Y0     + (long)PP*256;
constexpr long F_END    = F_Y1     + (long)PP*256;

__device__ __align__(128) float g_pool[F_END];

__device__ __forceinline__ void atomicMaxF(float* a, float v) {
    if (!(v < 0.f)) atomicMax((int*)a, __float_as_int(v));
    else            atomicMin((unsigned int*)a, __float_as_uint(v));
}

__global__ void k_fill(float* __restrict__ p, float v, int n) {
    int i = blockIdx.x * blockDim.x + threadIdx.x;
    if (i < n) p[i] = v;
}

__global__ void k_pad_w(const float* __restrict__ W, float* __restrict__ Wp) {
    int o = blockIdx.x; int k = threadIdx.x; // 144 threads
    Wp[o * 144 + k] = (k < 132) ? W[o * 132 + k] : 0.f;
}

// both clouds: [B,C,N] -> [B,N,C] plus |.|^2 and |.|   (grid.y = cloud)
__global__ void k_transpose_norm(const float* __restrict__ descS, const float* __restrict__ descD,
                                 float* __restrict__ dmatAll, float* __restrict__ nsqAll,
                                 float* __restrict__ nrmAll) {
    int cloud = blockIdx.y;
    const float* desc = cloud ? descD : descS;
    float* dmat = dmatAll + (long)cloud*BN*CC;
    float* nsq  = nsqAll  + cloud*BN;
    float* nrm  = nrmAll  + cloud*BN;
    int bn = blockIdx.x; int b = bn >> 11; int n = bn & (NN - 1);
    int c = threadIdx.x;
    float v = desc[((long)b*CC + c)*NN + n];
    dmat[(long)bn*CC + c] = v;
    float s = v * v;
    #pragma unroll
    for (int o = 16; o > 0; o >>= 1) s += __shfl_down_sync(0xffffffffu, s, o);
    __shared__ float ps[4];
    if ((c & 31) == 0) ps[c >> 5] = s;
    __syncthreads();
    if (c == 0) { float t = ps[0]+ps[1]+ps[2]+ps[3]; nsq[bn] = t; nrm[bn] = sqrtf(t); }
}

__global__ void k_rownorm(const float* __restrict__ dmat, float* __restrict__ nrm) {
    int bn = blockIdx.x; int c = threadIdx.x;
    float v = dmat[(long)bn*CC + c];
    float s = v * v;
    #pragma unroll
    for (int o = 16; o > 0; o >>= 1) s += __shfl_down_sync(0xffffffffu, s, o);
    __shared__ float ps[4];
    if ((c & 31) == 0) ps[c >> 5] = s;
    __syncthreads();
    if (c == 0) nrm[bn] = sqrtf(ps[0]+ps[1]+ps[2]+ps[3]);
}

// ---------------- split-tf32 inner GEMM + fused cosine maxes ----------------
#define SGM 128
#define SGN 64
#define SLD 20
#define SCLD 68

__global__ __launch_bounds__(256)
void k_gemm_sim(const float* __restrict__ A, const float* __restrict__ Bm,
                float* __restrict__ Cm,
                const float* __restrict__ nrmA, const float* __restrict__ nrmB,
                float* __restrict__ maxDS, float* __restrict__ maxSD) {
    const int b = blockIdx.z;
    A  += (long)b * NN * CC;
    Bm += (long)b * NN * CC;
    Cm += (long)b * NN * NN;

    __shared__ __align__(16) float smem[SGM * SCLD];
    float* Ahi = smem;
    float* Alo = smem + SGM*SLD;
    float* Bhi = smem + 2*SGM*SLD;
    float* Blo = smem + 2*SGM*SLD + SGN*SLD;
    float* Csm = smem;
    __shared__ float rns[SGM], rnd[SGN], rm[SGM], cmx[SGN];

    const int tid = threadIdx.x;
    const int lane = tid & 31;
    const int wid = tid >> 5;
    const int wm = wid & 3;
    const int wn = wid >> 2;
    const long rowBase = (long)blockIdx.y * SGM;
    const int colBase = blockIdx.x * SGN;

    if (tid < SGM) { rns[tid] = nrmA[b*NN + rowBase + tid]; rm[tid] = -3.4e38f; }
    if (tid < SGN) { rnd[tid] = nrmB[b*NN + colBase + tid]; cmx[tid] = -3.4e38f; }

    const int ma = tid >> 2;
    const int kq = (tid & 3) * 4;

    wmma::fragment<wmma::accumulator, 16, 16, 8, float> c[2][2];
    #pragma unroll
    for (int i = 0; i < 2; i++)
        #pragma unroll
        for (int j = 0; j < 2; j++)
            wmma::fill_fragment(c[i][j], 0.f);

    const int nk = CC / 16;
    for (int kc = 0; kc < nk; kc++) {
        const int k0 = kc * 16;
        #pragma unroll
        for (int e = 0; e < 2; e++) {
            int m = ma + e * 64;
            float4 v = *reinterpret_cast<const float4*>(&A[(rowBase + m) * CC + k0 + kq]);
            float4 h, l;
            h.x = wmma::__float_to_tf32(v.x); l.x = wmma::__float_to_tf32(v.x - h.x);
            h.y = wmma::__float_to_tf32(v.y); l.y = wmma::__float_to_tf32(v.y - h.y);
            h.z = wmma::__float_to_tf32(v.z); l.z = wmma::__float_to_tf32(v.z - h.z);
            h.w = wmma::__float_to_tf32(v.w); l.w = wmma::__float_to_tf32(v.w - h.w);
            *reinterpret_cast<float4*>(&Ahi[m * SLD + kq]) = h;
            *reinterpret_cast<float4*>(&Alo[m * SLD + kq]) = l;
        }
        {
            int m = ma & 63;
            float4 v = *reinterpret_cast<const float4*>(&Bm[(long)(colBase + m) * CC + k0 + kq]);
            float4 h, l;
            h.x = wmma::__float_to_tf32(v.x); l.x = wmma::__float_to_tf32(v.x - h.x);
            h.y = wmma::__float_to_tf32(v.y); l.y = wmma::__float_to_tf32(v.y - h.y);
            h.z = wmma::__float_to_tf32(v.z); l.z = wmma::__float_to_tf32(v.z - h.z);
            h.w = wmma::__float_to_tf32(v.w); l.w = wmma::__float_to_tf32(v.w - h.w);
            *reinterpret_cast<float4*>(&Bhi[m * SLD + kq]) = h;
            *reinterpret_cast<float4*>(&Blo[m * SLD + kq]) = l;
        }
        __syncthreads();
        #pragma unroll
        for (int ks = 0; ks < 2; ks++) {
            wmma::fragment<wmma::matrix_a, 16, 16, 8, wmma::precision::tf32, wmma::row_major> ah[2], al[2];
            wmma::fragment<wmma::matrix_b, 16, 16, 8, wmma::precision::tf32, wmma::col_major> bh[2], bl[2];
            #pragma unroll
            for (int i = 0; i < 2; i++) {
                wmma::load_matrix_sync(ah[i], &Ahi[(wm*32 + i*16) * SLD + ks*8], SLD);
                wmma::load_matrix_sync(al[i], &Alo[(wm*32 + i*16) * SLD + ks*8], SLD);
            }
            #pragma unroll
            for (int j = 0; j < 2; j++) {
                wmma::load_matrix_sync(bh[j], &Bhi[(wn*32 + j*16) * SLD + ks*8], SLD);
                wmma::load_matrix_sync(bl[j], &Blo[(wn*32 + j*16) * SLD + ks*8], SLD);
            }
            #pragma unroll
            for (int i = 0; i < 2; i++)
                #pragma unroll
                for (int j = 0; j < 2; j++) {
                    wmma::mma_sync(c[i][j], ah[i], bh[j], c[i][j]);
                    wmma::mma_sync(c[i][j], ah[i], bl[j], c[i][j]);
                    wmma::mma_sync(c[i][j], al[i], bh[j], c[i][j]);
                }
        }
        __syncthreads();
    }

    #pragma unroll
    for (int i = 0; i < 2; i++)
        #pragma unroll
        for (int j = 0; j < 2; j++)
            wmma::store_matrix_sync(&Csm[(wm*32 + i*16) * SCLD + wn*32 + j*16], c[i][j],
                                    SCLD, wmma::mem_row_major);
    __syncthreads();

    const int ccol = tid & 63;
    const int r0 = tid >> 6;
    const float nd = rnd[ccol];
    float colmax = -3.4e38f;
    #pragma unroll 8
    for (int it = 0; it < 32; it++) {
        int r = r0 + it * 4;
        float v = Csm[r * SCLD + ccol];
        Cm[(rowBase + r) * NN + colBase + ccol] = v;
        float csv = v / (nd * rns[r] + EPSF);
        colmax = fmaxf(colmax, csv);
        float wmx = csv;
        #pragma unroll
        for (int o = 16; o > 0; o >>= 1) wmx = fmaxf(wmx, __shfl_down_sync(0xffffffffu, wmx, o));
        if (lane == 0) atomicMaxF(&rm[r], wmx);
    }
    atomicMaxF(&cmx[ccol], colmax);
    __syncthreads();
    if (tid < SGM) atomicMaxF(&maxDS[b*NN + rowBase + tid], rm[tid]);
    else if (tid < SGM + SGN) atomicMaxF(&maxSD[b*NN + colBase + (tid - SGM)], cmx[tid - SGM]);
}

// ---------------- TF32 TC GEMM: 128x64, single-buffered, dual-cloud stats ----------------
#define TCM 128
#define TCN 64
#define ALD 20
#define CLD 68

__global__ __launch_bounds__(256)
void k_gemm_tc(const float* __restrict__ A, const float* __restrict__ Bm,
               float* __restrict__ Cm, int P, int O, int Kd,
               const float* __restrict__ scA, const float* __restrict__ shA,
               float* __restrict__ statS, float* __restrict__ statQ, int splitRows) {
    __shared__ __align__(16) float smem[TCM * CLD];
    float* As = smem;
    float* Bs = smem + TCM * ALD;
    float* Csm = smem;
    __shared__ float cs[TCN], cq[TCN];

    const int tid = threadIdx.x;
    const int wid = tid >> 5;
    const int wm = wid & 3;
    const int wn = wid >> 2;
    const int rowBase = blockIdx.y * TCM;
    const int colBase = blockIdx.x * TCN;
    const bool aff = (scA != nullptr);
    const bool stats = (statS != nullptr);
    const int cloudA = (splitRows > 0 && rowBase >= splitRows) ? 1 : 0;
    const int affOff = cloudA * Kd;
    const int statOff = cloudA * O;

    if (stats && tid < TCN) { cs[tid] = 0.f; cq[tid] = 0.f; }

    wmma::fragment<wmma::accumulator, 16, 16, 8, float> c[2][2];
    #pragma unroll
    for (int i = 0; i < 2; i++)
        #pragma unroll
        for (int j = 0; j < 2; j++)
            wmma::fill_fragment(c[i][j], 0.f);

    const int nk = Kd / 16;
    for (int kc = 0; kc < nk; kc++) {
        const int k0 = kc * 16;
        #pragma unroll
        for (int e = 0; e < 2; e++) {
            int lin = e * 256 + tid;
            int m = lin >> 2;
            int kq = (lin & 3) * 4;
            float4 v = *reinterpret_cast<const float4*>(&A[(long)(rowBase + m) * Kd + k0 + kq]);
            if (aff) {
                int gk = affOff + k0 + kq;
                v.x = fmaxf(v.x * scA[gk+0] + shA[gk+0], 0.f);
                v.y = fmaxf(v.y * scA[gk+1] + shA[gk+1], 0.f);
                v.z = fmaxf(v.z * scA[gk+2] + shA[gk+2], 0.f);
                v.w = fmaxf(v.w * scA[gk+3] + shA[gk+3], 0.f);
            }
            *reinterpret_cast<float4*>(&As[m * ALD + kq]) = v;
        }
        {
            int m = tid >> 2;
            int kq = (tid & 3) * 4;
            float4 v = *reinterpret_cast<const float4*>(&Bm[(long)(colBase + m) * Kd + k0 + kq]);
            *reinterpret_cast<float4*>(&Bs[m * ALD + kq]) = v;
        }
        __syncthreads();
        #pragma unroll
        for (int ks = 0; ks < 2; ks++) {
            wmma::fragment<wmma::matrix_a, 16, 16, 8, wmma::precision::tf32, wmma::row_major> a[2];
            wmma::fragment<wmma::matrix_b, 16, 16, 8, wmma::precision::tf32, wmma::col_major> b[2];
            #pragma unroll
            for (int i = 0; i < 2; i++) {
                wmma::load_matrix_sync(a[i], &As[(wm*32 + i*16) * ALD + ks*8], ALD);
                #pragma unroll
                for (int t = 0; t < a[i].num_elements; t++)
                    a[i].x[t] = wmma::__float_to_tf32(a[i].x[t]);
            }
            #pragma unroll
            for (int j = 0; j < 2; j++) {
                wmma::load_matrix_sync(b[j], &Bs[(wn*32 + j*16) * ALD + ks*8], ALD);
                #pragma unroll
                for (int t = 0; t < b[j].num_elements; t++)
                    b[j].x[t] = wmma::__float_to_tf32(b[j].x[t]);
            }
            #pragma unroll
            for (int i = 0; i < 2; i++)
                #pragma unroll
                for (int j = 0; j < 2; j++)
                    wmma::mma_sync(c[i][j], a[i], b[j], c[i][j]);
        }
        __syncthreads();
    }

    #pragma unroll
    for (int i = 0; i < 2; i++)
        #pragma unroll
        for (int j = 0; j < 2; j++)
            wmma::store_matrix_sync(&Csm[(wm*32 + i*16) * CLD + wn*32 + j*16], c[i][j],
                                    CLD, wmma::mem_row_major);
    __syncthreads();

    const int ccol = tid & 63;
    const int r0 = tid >> 6;
    float s = 0.f, q = 0.f;
    #pragma unroll 8
    for (int it = 0; it < 32; it++) {
        int r = r0 + it * 4;
        float v = Csm[r * CLD + ccol];
        Cm[(long)(rowBase + r) * O + colBase + ccol] = v;
        s += v; q += v * v;
    }
    if (stats) {
        atomicAdd(&cs[ccol], s);
        atomicAdd(&cq[ccol], q);
        __syncthreads();
        if (tid < TCN) {
            atomicAdd(&statS[statOff + colBase + tid], cs[tid]);
            atomicAdd(&statQ[statOff + colBase + tid], cq[tid]);
        }
    }
}

// finalize: O_total outputs, channel params indexed (o % chanMod)
__global__ void k_finalize(float* __restrict__ statS, float* __restrict__ statQ,
                           const float* __restrict__ g, const float* __restrict__ bb,
                           float* __restrict__ sc, float* __restrict__ sh,
                           int O_total, int chanMod, float invP) {
    int o = blockIdx.x * blockDim.x + threadIdx.x;
    if (o < O_total) {
        int ch = o % chanMod;
        float mu  = statS[o] * invP;
        float var = fmaxf(statQ[o] * invP - mu * mu, 0.f);
        float s   = g[ch] * rsqrtf(var + BNEPS);
        sc[o] = s;
        sh[o] = bb[ch] - mu * s;
        statS[o] = 0.f;
        statQ[o] = 0.f;
    }
}

// top-16 smallest from shared d2[NN], 256 threads
__device__ void select_topk(float* d2, int* outIdx) {
    __shared__ float rv[8];
    __shared__ int   ri[8];
    int tid = threadIdx.x, lane = tid & 31, w = tid >> 5;
    for (int kk = 0; kk < KK; kk++) {
        float best = 3.4e38f; int bi = 0;
        for (int m = tid; m < NN; m += 256) {
            float v = d2[m];
            if (v < best) { best = v; bi = m; }
        }
        #pragma unroll
        for (int o = 16; o > 0; o >>= 1) {
            float ov = __shfl_down_sync(0xffffffffu, best, o);
            int   oi = __shfl_down_sync(0xffffffffu, bi, o);
            if (ov < best || (ov == best && oi < bi)) { best = ov; bi = oi; }
        }
        if (lane == 0) { rv[w] = best; ri[w] = bi; }
        __syncthreads();
        if (tid == 0) {
            float bv = rv[0]; int bj = ri[0];
            #pragma unroll
            for (int i = 1; i < 8; i++)
                if (rv[i] < bv || (rv[i] == bv && ri[i] < bj)) { bv = rv[i]; bj = ri[i]; }
            outIdx[kk] = bj;
            d2[bj] = 3.4e38f;
        }
        __syncthreads();
    }
}

__global__ void k_knn_desc(const float* __restrict__ inner, const float* __restrict__ nsqS,
                           const float* __restrict__ nsqD, int* __restrict__ idxOut) {
    int n = blockIdx.x, b = blockIdx.y;
    __shared__ float d2[NN];
    const float* row = inner + (long)b*NN*NN + (long)n*NN;
    float q = nsqS[b*NN + n];
    for (int m = threadIdx.x; m < NN; m += 256) d2[m] = q + nsqD[b*NN + m] - 2.f * row[m];
    __syncthreads();
    select_topk(d2, idxOut + ((long)b*NN + n) * KK);
}

// both clouds: grid.z = cloud
__global__ void k_knn_xyz(const float* __restrict__ xyzS, const float* __restrict__ xyzD,
                          int* __restrict__ idxAll) {
    int n = blockIdx.x, b = blockIdx.y, cloud = blockIdx.z;
    const float* xyz = cloud ? xyzD : xyzS;
    int* idxOut = idxAll + (long)cloud*PP;
    __shared__ float d2[NN];
    long base = (long)b * NN * 3;
    float qx = xyz[base + (long)n*3], qy = xyz[base + (long)n*3+1], qz = xyz[base + (long)n*3+2];
    float qq = qx*qx + qy*qy + qz*qz;
    for (int m = threadIdx.x; m < NN; m += 256) {
        float rx = xyz[base + (long)m*3], ry = xyz[base + (long)m*3+1], rz = xyz[base + (long)m*3+2];
        d2[m] = qq + rx*rx + ry*ry + rz*rz - 2.f*(qx*rx + qy*ry + qz*rz);
    }
    __syncthreads();
    select_topk(d2, idxOut + ((long)b*NN + n) * KK);
}

__global__ void k_simgather(const float* __restrict__ inner, const float* __restrict__ nrmS,
                            const float* __restrict__ nrmD, const float* __restrict__ maxDS,
                            const float* __restrict__ maxSD, const int* __restrict__ idx,
                            float* __restrict__ outSD, float* __restrict__ outDS) {
    int t = blockIdx.x * 256 + threadIdx.x;
    if (t >= PP) return;
    int b = t / (NN * KK);
    int n = (t / KK) & (NN - 1);
    int m = idx[t];
    float v  = inner[(long)b*NN*NN + (long)n*NN + m];
    float cs = v / (nrmD[b*NN + m] * nrmS[b*NN + n] + EPSF);
    outSD[t] = cs / (maxDS[b*NN + n] + EPSF);
    outDS[t] = cs / (maxSD[b*NN + m] + EPSF);
}

// both clouds: nbr conv input [knn_feats(C), rela(3), dist(1), pad(8)] stride 144
__global__ void k_build_nbr_f(const float* __restrict__ xyzS, const float* __restrict__ xyzD,
                              const float* __restrict__ dmatAll, const int* __restrict__ idxAll,
                              float* __restrict__ f) {
    int p = blockIdx.x;                 // 0 .. 2PP-1
    int cloud = p >= PP;
    int pl = p - cloud * PP;
    const float* xyz = cloud ? xyzD : xyzS;
    const float* dmatC = dmatAll + (long)cloud*BN*CC;
    int n = (pl / KK) & (NN - 1);
    int b = pl / (NN * KK);
    int m = idxAll[p];
    const float* dr = dmatC + ((long)b*NN + m) * CC;
    float* fo = f + (long)p * 144;
    int tid = threadIdx.x;
    fo[tid] = dr[tid];
    if (tid == 0) {
        long qb = ((long)b*NN + n) * 3, rb = ((long)b*NN + m) * 3;
        float rx = xyz[rb]-xyz[qb], ry = xyz[rb+1]-xyz[qb+1], rz = xyz[rb+2]-xyz[qb+2];
        fo[128] = rx; fo[129] = ry; fo[130] = rz; fo[131] = sqrtf(rx*rx+ry*ry+rz*rz);
        #pragma unroll
        for (int z = 132; z < 144; z++) fo[z] = 0.f;
    }
}

// both clouds: grid 2*BN
__global__ void k_nbr_final(const float* __restrict__ yraw, const float* __restrict__ sc,
                            const float* __restrict__ sh, const int* __restrict__ idxAll,
                            const float* __restrict__ dmatAll, float* __restrict__ outAll) {
    int gblk = blockIdx.x;
    int cloud = gblk >= BN;
    int bn = gblk - cloud * BN;
    const float* y = yraw + (long)cloud*PP*CC;
    const float* scc = sc + cloud*CC;
    const float* shc = sh + cloud*CC;
    const int* idx = idxAll + (long)cloud*PP;
    const float* dmat = dmatAll + (long)cloud*BN*CC;
    float* outN = outAll + (long)cloud*BN*CC;
    int tid = threadIdx.x; // 256
    __shared__ float fe[KK][CC];
    __shared__ float mk[KK], wgt[KK];
    __shared__ int sid[KK];
    if (tid < KK) sid[tid] = idx[(long)bn*KK + tid];
    for (int t = tid; t < KK * CC; t += 256) {
        int k = t >> 7, c = t & 127;
        float v = y[((long)bn*KK + k) * CC + c];
        fe[k][c] = fmaxf(v * scc[c] + shc[c], 0.f);
    }
    __syncthreads();
    int w = tid >> 5, lane = tid & 31;
    for (int kk = w; kk < KK; kk += 8) {
        float mx = -3.4e38f;
        for (int c = lane; c < CC; c += 32) mx = fmaxf(mx, fe[kk][c]);
        #pragma unroll
        for (int o = 16; o > 0; o >>= 1) mx = fmaxf(mx, __shfl_down_sync(0xffffffffu, mx, o));
        if (lane == 0) mk[kk] = mx;
    }
    __syncthreads();
    if (tid == 0) {
        float m = -3.4e38f;
        for (int k = 0; k < KK; k++) m = fmaxf(m, mk[k]);
        float s = 0.f;
        for (int k = 0; k < KK; k++) { float e = expf(mk[k]-m); wgt[k] = e; s += e; }
        float r = 1.f / s;
        for (int k = 0; k < KK; k++) wgt[k] *= r;
    }
    __syncthreads();
    if (tid < CC) {
        int b = bn >> 11;
        float a = 0.f;
        #pragma unroll
        for (int k = 0; k < KK; k++) a += wgt[k] * dmat[((long)b*NN + sid[k]) * CC + tid];
        outN[(long)bn*CC + tid] = a;
    }
}

// main feats build (272 ch)
__global__ void k_build_feats(const float* __restrict__ src_xyz, const float* __restrict__ dst_xyz,
                              const float* __restrict__ srcd, const float* __restrict__ dstd,
                              const float* __restrict__ srcw, const float* __restrict__ dstw,
                              const float* __restrict__ sdc, const float* __restrict__ dsc,
                              const float* __restrict__ sdn, const float* __restrict__ dsn,
                              const int* __restrict__ idx, float* __restrict__ feats) {
    int p = blockIdx.x;
    int n = (p / KK) & (NN - 1);
    int b = p / (NN * KK);
    int m = idx[p];
    float* fo = feats + (long)p * 272;
    int tid = threadIdx.x;
    fo[10 + tid]  = srcd[((long)b*NN + n) * CC + tid];
    fo[138 + tid] = dstd[((long)b*NN + m) * CC + tid];
    if (tid == 0) {
        long qb = ((long)b*NN + n) * 3, rb = ((long)b*NN + m) * 3;
        float sx = src_xyz[qb], sy = src_xyz[qb+1], sz = src_xyz[qb+2];
        float kx = dst_xyz[rb], ky = dst_xyz[rb+1], kz = dst_xyz[rb+2];
        float rx = kx-sx, ry = ky-sy, rz = kz-sz;
        fo[0]=rx; fo[1]=ry; fo[2]=rz; fo[3]=sqrtf(rx*rx+ry*ry+rz*rz);
        fo[4]=sx; fo[5]=sy; fo[6]=sz; fo[7]=kx; fo[8]=ky; fo[9]=kz;
        fo[266]=srcw[b*NN+n]; fo[267]=dstw[b*NN+m];
        fo[268]=sdc[p]; fo[269]=dsc[p]; fo[270]=sdn[p]; fo[271]=dsn[p];
    }
}

__global__ void k_attention(const float* __restrict__ yraw, const float* __restrict__ sc,
                            const float* __restrict__ sh, const int* __restrict__ idx,
                            const float* __restrict__ dst_xyz,
                            float* __restrict__ outC, float* __restrict__ att) {
    int bn = blockIdx.x, tid = threadIdx.x; // 256
    __shared__ float fe[KK][256];
    __shared__ float mk[KK], wgt[KK];
    __shared__ int sid[KK];
    if (tid < KK) sid[tid] = idx[(long)bn*KK + tid];
    float s = sc[tid], h = sh[tid];
    #pragma unroll
    for (int k = 0; k < KK; k++) {
        float v = yraw[((long)bn*KK + k) * 256 + tid];
        fe[k][tid] = fmaxf(v * s + h, 0.f);
    }
    __syncthreads();
    int w = tid >> 5, lane = tid & 31;
    for (int kk = w; kk < KK; kk += 8) {
        float mx = -3.4e38f;
        for (int c = lane; c < 256; c += 32) mx = fmaxf(mx, fe[kk][c]);
        #pragma unroll
        for (int o = 16; o > 0; o >>= 1) mx = fmaxf(mx, __shfl_down_sync(0xffffffffu, mx, o));
        if (lane == 0) mk[kk] = mx;
    }
    __syncthreads();
    if (tid == 0) {
        float m = -3.4e38f;
        for (int k = 0; k < KK; k++) m = fmaxf(m, mk[k]);
        float ssum = 0.f;
        for (int k = 0; k < KK; k++) { float e = expf(mk[k]-m); wgt[k] = e; ssum += e; }
        float r = 1.f / ssum;
        for (int k = 0; k < KK; k++) wgt[k] *= r;
    }
    __syncthreads();
    float a = 0.f;
    #pragma unroll
    for (int k = 0; k < KK; k++) a += wgt[k] * fe[k][tid];
    att[(long)bn * 256 + tid] = a;
    if (tid < 3) {
        int b = bn >> 11;
        float cg = 0.f;
        #pragma unroll
        for (int k = 0; k < KK; k++)
            cg += wgt[k] * dst_xyz[((long)b*NN + sid[k]) * 3 + tid];
        outC[(long)bn * 3 + tid] = cg;
    }
}

__global__ void k_mlp3(const float* __restrict__ yraw, const float* __restrict__ sc,
                       const float* __restrict__ sh, const float* __restrict__ w3,
                       const float* __restrict__ b3, float* __restrict__ outw) {
    int bn = blockIdx.x, tid = threadIdx.x; // 256
    float v = fmaxf(yraw[(long)bn*256 + tid] * sc[tid] + sh[tid], 0.f) * w3[tid];
    #pragma unroll
    for (int o = 16; o > 0; o >>= 1) v += __shfl_down_sync(0xffffffffu, v, o);
    __shared__ float ps[8];
    if ((tid & 31) == 0) ps[tid >> 5] = v;
    __syncthreads();
    if (tid == 0) {
        float s2 = 0.f;
        #pragma unroll
        for (int i = 0; i < 8; i++) s2 += ps[i];
        outw[bn] = 1.f / (1.f + expf(-(s2 + b3[0])));
    }
}

// ---------------- host side ----------------
static void conv_bn(const float* A, const float* W, float* Y, int P, int O, int Kd,
                    bool aff, const float* g, const float* bb,
                    float* statS, float* sc, float* sh) {
    k_gemm_tc<<<dim3(O/TCN, P/TCM), 256>>>(A, W, Y, P, O, Kd,
        aff ? sc : nullptr, aff ? sh : nullptr, statS, statS + 256, 0);
    k_finalize<<<1, 256>>>(statS, statS + 256, g, bb, sc, sh, O, O, 1.f / (float)P);
}

static void conv_bn_dual(const float* A, const float* W, float* Y, int O, int Kd,
                         bool aff, const float* g, const float* bb,
                         float* statS, float* sc, float* sh) {
    k_gemm_tc<<<dim3(O/TCN, (2*PP)/TCM), 256>>>(A, W, Y, 2*PP, O, Kd,
        aff ? sc : nullptr, aff ? sh : nullptr, statS, statS + 256, PP);
    k_finalize<<<1, 256>>>(statS, statS + 256, g, bb, sc, sh, 2*O, O, 1.f / (float)PP);
}

extern "C" void kernel_launch(void* const* d_in, const int* in_sizes, int n_in,
                              void* d_out, int out_size) {
    const float* src_xyz  = (const float*)d_in[0];
    const float* src_desc = (const float*)d_in[1];
    const float* dst_xyz  = (const float*)d_in[2];
    const float* dst_desc = (const float*)d_in[3];
    const float* src_w    = (const float*)d_in[4];
    const float* dst_w    = (const float*)d_in[5];
    const float* c1_W0 = (const float*)d_in[6];
    const float* c1_W  = (const float*)d_in[7];
    const float* c1_g  = (const float*)d_in[8];
    const float* c1_b  = (const float*)d_in[9];
    const float* c2_W0 = (const float*)d_in[10];
    const float* c2_W  = (const float*)d_in[11];
    const float* c2_g  = (const float*)d_in[12];
    const float* c2_b  = (const float*)d_in[13];
    const float* m1_W  = (const float*)d_in[14];
    const float* m1_g  = (const float*)d_in[16];
    const float* m1_b  = (const float*)d_in[17];
    const float* m2_W  = (const float*)d_in[18];
    const float* m2_g  = (const float*)d_in[20];
    const float* m2_b  = (const float*)d_in[21];
    const float* m3_W  = (const float*)d_in[22];
    const float* m3_b  = (const float*)d_in[23];

    float* base = nullptr;
    cudaGetSymbolAddress((void**)&base, g_pool);
    float* srcd   = base + F_SRCD;
    float* dstd   = base + F_DSTD;
    float* nsqS   = base + F_NSQS;
    float* nsqD   = base + F_NSQD;
    float* nrmS   = base + F_NRMS;
    float* nrmD   = base + F_NRMD;
    float* maxDS  = base + F_MAXDS;
    float* maxSD  = base + F_MAXSD;
    float* nrm2S  = base + F_NRM2S;
    float* nrm2D  = base + F_NRM2D;
    float* sdc    = base + F_SDC;
    float* dsc    = base + F_DSC;
    float* sdn    = base + F_SDN;
    float* dsn    = base + F_DSN;
    float* statS  = base + F_STATS;
    float* sc     = base + F_SC;
    float* sh     = base + F_SH;
    float* w2p    = base + F_W2P;
    int*   idx    = (int*)(base + F_IDX);
    int*   sidx   = (int*)(base + F_SIDX);   // [sidx | didx] contiguous 2*PP
    float* att    = base + F_ATT;
    float* mb1    = base + F_MB1;
    float* mb2    = base + F_MB2;
    float* srcnbr = base + F_SRCNBR;         // [srcnbr | dstnbr] contiguous
    float* inner  = base + F_INNER;
    float* fbuf   = base + F_F;
    float* y0     = base + F_Y0;             // viewed as 2PP x 128 in section B
    float* y1     = base + F_Y1;
    float* outC   = (float*)d_out;
    float* outW   = (float*)d_out + (long)BB*NN*3;

    k_fill<<<2, 256>>>(statS, 0.f, 512);
    k_pad_w<<<128, 144>>>(c2_W0, w2p);

    // A: transpose + norms (both clouds in one launch)
    k_transpose_norm<<<dim3(BN, 2), 128>>>(src_desc, dst_desc, srcd, nsqS, nrmS);

    // inner = src . dst (split-tf32 TC, fp32-accurate) with fused cosine maxes
    k_fill<<<32, 256>>>(maxDS, -3.4e38f, 2*BN);
    k_gemm_sim<<<dim3(NN/SGN, NN/SGM, 2), 256>>>(srcd, dstd, inner, nrmS, nrmD, maxDS, maxSD);
    k_knn_desc<<<dim3(NN, BB), 256>>>(inner, nsqS, nsqD, idx);
    k_simgather<<<PP/256, 256>>>(inner, nrmS, nrmD, maxDS, maxSD, idx, sdc, dsc);

    // B: neighborhood descriptors — BOTH clouds batched
    k_knn_xyz<<<dim3(NN, BB, 2), 256>>>(src_xyz, dst_xyz, sidx);
    k_build_nbr_f<<<2*PP, 128>>>(src_xyz, dst_xyz, srcd, sidx, fbuf);
    const float* c2W1 = c2_W;
    const float* c2W2 = c2_W + CC*CC;
    conv_bn_dual(fbuf, w2p,  y0, CC, 144, false, c2_g,        c2_b,        statS, sc, sh);
    conv_bn_dual(y0,   c2W1, y1, CC, CC,  true,  c2_g + CC,   c2_b + CC,   statS, sc, sh);
    conv_bn_dual(y1,   c2W2, y0, CC, CC,  true,  c2_g + 2*CC, c2_b + 2*CC, statS, sc, sh);
    k_nbr_final<<<2*BN, 256>>>(y0, sc, sh, sidx, srcd, srcnbr);

    // nbr cosine sims (split-tf32 TC inner with fused maxes)
    k_rownorm<<<2*BN, 128>>>(srcnbr, nrm2S);
    k_fill<<<32, 256>>>(maxDS, -3.4e38f, 2*BN);
    k_gemm_sim<<<dim3(NN/SGN, NN/SGM, 2), 256>>>(srcnbr, srcnbr + (long)BN*CC, inner,
                                                 nrm2S, nrm2D, maxDS, maxSD);
    k_simgather<<<PP/256, 256>>>(inner, nrm2S, nrm2D, maxDS, maxSD, idx, sdn, dsn);

    // C: main feature conv + attention
    k_build_feats<<<PP, 128>>>(src_xyz, dst_xyz, srcd, dstd, src_w, dst_w,
                               sdc, dsc, sdn, dsn, idx, fbuf);
    const float* c1W1 = c1_W;
    const float* c1W2 = c1_W + 256*256;
    conv_bn(fbuf, c1_W0, y0, PP, 256, 272, false, c1_g,        c1_b,        statS, sc, sh);
    conv_bn(y0,   c1W1,  y1, PP, 256, 256, true,  c1_g + 256,  c1_b + 256,  statS, sc, sh);
    conv_bn(y1,   c1W2,  y0, PP, 256, 256, true,  c1_g + 512,  c1_b + 512,  statS, sc, sh);
    k_attention<<<BN, 256>>>(y0, sc, sh, idx, dst_xyz, outC, att);

    // D: MLP head
    conv_bn(att, m1_W, mb1, BN, 256, 256, false, m1_g, m1_b, statS, sc, sh);
    conv_bn(mb1, m2_W, mb2, BN, 256, 256, true,  m2_g, m2_b, statS, sc, sh);
    k_mlp3<<<BN, 256>>>(mb2, sc, sh, m3_W, m3_b, outW);
}

// round 10
// speedup vs baseline: 1.1763x; 1.0149x over previous
#include <cuda_runtime.h>
#include <mma.h>
#include <math.h>
#include <float.h>

using namespace nvcuda;

#define BB 2
#define NN 2048
#define CC 128
#define KK 16
#define BN (BB*NN)
#define PP (BB*NN*KK)
#define EPSF 1e-6f
#define BNEPS 1e-5f

// ---------------- scratch pool ----------------
constexpr long F_SRCD   = 0;
constexpr long F_DSTD   = F_SRCD   + (long)BN*CC;   // contiguous with SRCD
constexpr long F_NSQS   = F_DSTD   + (long)BN*CC;
constexpr long F_NSQD   = F_NSQS   + BN;
constexpr long F_NRMS   = F_NSQD   + BN;
constexpr long F_NRMD   = F_NRMS   + BN;
constexpr long F_MAXDS  = F_NRMD   + BN;
constexpr long F_MAXSD  = F_MAXDS  + BN;
constexpr long F_NRM2S  = F_MAXSD  + BN;
constexpr long F_NRM2D  = F_NRM2S  + BN;
constexpr long F_SDC    = F_NRM2D  + BN;
constexpr long F_DSC    = F_SDC    + PP;
constexpr long F_SDN    = F_DSC    + PP;
constexpr long F_DSN    = F_SDN    + PP;
constexpr long F_STATS  = F_DSN    + PP;            // 8 slots x 1024 (S at +0, Q at +512)
constexpr long F_W2P    = F_STATS  + 8*1024;        // padded c2_W0 [128][144]
constexpr long F_IDX    = F_W2P    + 128*144;       // int
constexpr long F_SIDX   = F_IDX    + PP;            // sidx then didx contiguous
constexpr long F_DIDX   = F_SIDX   + PP;
constexpr long F_ATT    = F_DIDX   + PP;
constexpr long F_MB1    = F_ATT    + (long)BN*256;
constexpr long F_MB2    = F_MB1    + (long)BN*256;
constexpr long F_SRCNBR = F_MB2    + (long)BN*256;  // srcnbr then dstnbr contiguous
constexpr long F_DSTNBR = F_SRCNBR + (long)BN*CC;
constexpr long F_INNER  = F_DSTNBR + (long)BN*CC;
constexpr long F_F      = F_INNER  + (long)BB*NN*NN;
constexpr long F_FSZ    = (long)2*PP*144;           // max(PP*272, 2PP*144)
constexpr long F_Y0     = F_F      + F_FSZ;
constexpr long F_Y1     = F_Y0     + (long)PP*256;
constexpr long F_END    = F_Y1     + (long)PP*256;

__device__ __align__(128) float g_pool[F_END];

__device__ __forceinline__ void atomicMaxF(float* a, float v) {
    if (!(v < 0.f)) atomicMax((int*)a, __float_as_int(v));
    else            atomicMin((unsigned int*)a, __float_as_uint(v));
}

__global__ void k_fill(float* __restrict__ p, float v, int n) {
    int i = blockIdx.x * blockDim.x + threadIdx.x;
    if (i < n) p[i] = v;
}

__global__ void k_pad_w(const float* __restrict__ W, float* __restrict__ Wp) {
    int o = blockIdx.x; int k = threadIdx.x; // 144 threads
    Wp[o * 144 + k] = (k < 132) ? W[o * 132 + k] : 0.f;
}

// both clouds: [B,C,N] -> [B,N,C] plus |.|^2 and |.|   (grid.y = cloud)
__global__ void k_transpose_norm(const float* __restrict__ descS, const float* __restrict__ descD,
                                 float* __restrict__ dmatAll, float* __restrict__ nsqAll,
                                 float* __restrict__ nrmAll) {
    int cloud = blockIdx.y;
    const float* desc = cloud ? descD : descS;
    float* dmat = dmatAll + (long)cloud*BN*CC;
    float* nsq  = nsqAll  + cloud*BN;
    float* nrm  = nrmAll  + cloud*BN;
    int bn = blockIdx.x; int b = bn >> 11; int n = bn & (NN - 1);
    int c = threadIdx.x;
    float v = desc[((long)b*CC + c)*NN + n];
    dmat[(long)bn*CC + c] = v;
    float s = v * v;
    #pragma unroll
    for (int o = 16; o > 0; o >>= 1) s += __shfl_down_sync(0xffffffffu, s, o);
    __shared__ float ps[4];
    if ((c & 31) == 0) ps[c >> 5] = s;
    __syncthreads();
    if (c == 0) { float t = ps[0]+ps[1]+ps[2]+ps[3]; nsq[bn] = t; nrm[bn] = sqrtf(t); }
}

__global__ void k_rownorm(const float* __restrict__ dmat, float* __restrict__ nrm) {
    int bn = blockIdx.x; int c = threadIdx.x;
    float v = dmat[(long)bn*CC + c];
    float s = v * v;
    #pragma unroll
    for (int o = 16; o > 0; o >>= 1) s += __shfl_down_sync(0xffffffffu, s, o);
    __shared__ float ps[4];
    if ((c & 31) == 0) ps[c >> 5] = s;
    __syncthreads();
    if (c == 0) nrm[bn] = sqrtf(ps[0]+ps[1]+ps[2]+ps[3]);
}

// ---------------- split-tf32 inner GEMM + fused cosine maxes ----------------
#define SGM 128
#define SGN 64
#define SLD 20
#define SCLD 68

__global__ __launch_bounds__(256)
void k_gemm_sim(const float* __restrict__ A, const float* __restrict__ Bm,
                float* __restrict__ Cm,
                const float* __restrict__ nrmA, const float* __restrict__ nrmB,
                float* __restrict__ maxDS, float* __restrict__ maxSD) {
    const int b = blockIdx.z;
    A  += (long)b * NN * CC;
    Bm += (long)b * NN * CC;
    Cm += (long)b * NN * NN;

    __shared__ __align__(16) float smem[SGM * SCLD];
    float* Ahi = smem;
    float* Alo = smem + SGM*SLD;
    float* Bhi = smem + 2*SGM*SLD;
    float* Blo = smem + 2*SGM*SLD + SGN*SLD;
    float* Csm = smem;
    __shared__ float rns[SGM], rnd[SGN], rm[SGM], cmx[SGN];

    const int tid = threadIdx.x;
    const int lane = tid & 31;
    const int wid = tid >> 5;
    const int wm = wid & 3;
    const int wn = wid >> 2;
    const long rowBase = (long)blockIdx.y * SGM;
    const int colBase = blockIdx.x * SGN;

    if (tid < SGM) { rns[tid] = nrmA[b*NN + rowBase + tid]; rm[tid] = -3.4e38f; }
    if (tid < SGN) { rnd[tid] = nrmB[b*NN + colBase + tid]; cmx[tid] = -3.4e38f; }

    const int ma = tid >> 2;
    const int kq = (tid & 3) * 4;

    wmma::fragment<wmma::accumulator, 16, 16, 8, float> c[2][2];
    #pragma unroll
    for (int i = 0; i < 2; i++)
        #pragma unroll
        for (int j = 0; j < 2; j++)
            wmma::fill_fragment(c[i][j], 0.f);

    const int nk = CC / 16;
    for (int kc = 0; kc < nk; kc++) {
        const int k0 = kc * 16;
        #pragma unroll
        for (int e = 0; e < 2; e++) {
            int m = ma + e * 64;
            float4 v = *reinterpret_cast<const float4*>(&A[(rowBase + m) * CC + k0 + kq]);
            float4 h, l;
            h.x = wmma::__float_to_tf32(v.x); l.x = wmma::__float_to_tf32(v.x - h.x);
            h.y = wmma::__float_to_tf32(v.y); l.y = wmma::__float_to_tf32(v.y - h.y);
            h.z = wmma::__float_to_tf32(v.z); l.z = wmma::__float_to_tf32(v.z - h.z);
            h.w = wmma::__float_to_tf32(v.w); l.w = wmma::__float_to_tf32(v.w - h.w);
            *reinterpret_cast<float4*>(&Ahi[m * SLD + kq]) = h;
            *reinterpret_cast<float4*>(&Alo[m * SLD + kq]) = l;
        }
        {
            int m = ma & 63;
            float4 v = *reinterpret_cast<const float4*>(&Bm[(long)(colBase + m) * CC + k0 + kq]);
            float4 h, l;
            h.x = wmma::__float_to_tf32(v.x); l.x = wmma::__float_to_tf32(v.x - h.x);
            h.y = wmma::__float_to_tf32(v.y); l.y = wmma::__float_to_tf32(v.y - h.y);
            h.z = wmma::__float_to_tf32(v.z); l.z = wmma::__float_to_tf32(v.z - h.z);
            h.w = wmma::__float_to_tf32(v.w); l.w = wmma::__float_to_tf32(v.w - h.w);
            *reinterpret_cast<float4*>(&Bhi[m * SLD + kq]) = h;
            *reinterpret_cast<float4*>(&Blo[m * SLD + kq]) = l;
        }
        __syncthreads();
        #pragma unroll
        for (int ks = 0; ks < 2; ks++) {
            wmma::fragment<wmma::matrix_a, 16, 16, 8, wmma::precision::tf32, wmma::row_major> ah[2], al[2];
            wmma::fragment<wmma::matrix_b, 16, 16, 8, wmma::precision::tf32, wmma::col_major> bh[2], bl[2];
            #pragma unroll
            for (int i = 0; i < 2; i++) {
                wmma::load_matrix_sync(ah[i], &Ahi[(wm*32 + i*16) * SLD + ks*8], SLD);
                wmma::load_matrix_sync(al[i], &Alo[(wm*32 + i*16) * SLD + ks*8], SLD);
            }
            #pragma unroll
            for (int j = 0; j < 2; j++) {
                wmma::load_matrix_sync(bh[j], &Bhi[(wn*32 + j*16) * SLD + ks*8], SLD);
                wmma::load_matrix_sync(bl[j], &Blo[(wn*32 + j*16) * SLD + ks*8], SLD);
            }
            #pragma unroll
            for (int i = 0; i < 2; i++)
                #pragma unroll
                for (int j = 0; j < 2; j++) {
                    wmma::mma_sync(c[i][j], ah[i], bh[j], c[i][j]);
                    wmma::mma_sync(c[i][j], ah[i], bl[j], c[i][j]);
                    wmma::mma_sync(c[i][j], al[i], bh[j], c[i][j]);
                }
        }
        __syncthreads();
    }

    #pragma unroll
    for (int i = 0; i < 2; i++)
        #pragma unroll
        for (int j = 0; j < 2; j++)
            wmma::store_matrix_sync(&Csm[(wm*32 + i*16) * SCLD + wn*32 + j*16], c[i][j],
                                    SCLD, wmma::mem_row_major);
    __syncthreads();

    const int ccol = tid & 63;
    const int r0 = tid >> 6;
    const float nd = rnd[ccol];
    float colmax = -3.4e38f;
    #pragma unroll 8
    for (int it = 0; it < 32; it++) {
        int r = r0 + it * 4;
        float v = Csm[r * SCLD + ccol];
        Cm[(rowBase + r) * NN + colBase + ccol] = v;
        float csv = v / (nd * rns[r] + EPSF);
        colmax = fmaxf(colmax, csv);
        float wmx = csv;
        #pragma unroll
        for (int o = 16; o > 0; o >>= 1) wmx = fmaxf(wmx, __shfl_down_sync(0xffffffffu, wmx, o));
        if (lane == 0) atomicMaxF(&rm[r], wmx);
    }
    atomicMaxF(&cmx[ccol], colmax);
    __syncthreads();
    if (tid < SGM) atomicMaxF(&maxDS[b*NN + rowBase + tid], rm[tid]);
    else if (tid < SGM + SGN) atomicMaxF(&maxSD[b*NN + colBase + (tid - SGM)], cmx[tid - SGM]);
}

// ---------------- TF32 TC GEMM: 128x64, in-block BN affine from producer stats ----------------
// affS/affQ: previous layer's stat slot (or null). gP/bP: previous layer BN params.
// splitRows>0: rows >= splitRows are cloud 1 (stats offset O, affine offset Kd).
#define TCM 128
#define TCN 64
#define ALD 20
#define CLD 68

__global__ __launch_bounds__(256)
void k_gemm_tc(const float* __restrict__ A, const float* __restrict__ Bm,
               float* __restrict__ Cm, int P, int O, int Kd,
               const float* __restrict__ affS, const float* __restrict__ affQ,
               const float* __restrict__ gP, const float* __restrict__ bP, float invP,
               float* __restrict__ statS, float* __restrict__ statQ, int splitRows) {
    __shared__ __align__(16) float smem[TCM * CLD];
    float* As = smem;
    float* Bs = smem + TCM * ALD;
    float* Csm = smem;
    __shared__ float cs[TCN], cq[TCN];
    __shared__ float sSc[256], sSh[256];

    const int tid = threadIdx.x;
    const int wid = tid >> 5;
    const int wm = wid & 3;
    const int wn = wid >> 2;
    const int rowBase = blockIdx.y * TCM;
    const int colBase = blockIdx.x * TCN;
    const bool aff = (affS != nullptr);
    const bool stats = (statS != nullptr);
    const int cloudA = (splitRows > 0 && rowBase >= splitRows) ? 1 : 0;
    const int statOff = cloudA * O;

    if (aff && tid < Kd) {
        int so = cloudA * Kd + tid;
        float mu  = affS[so] * invP;
        float var = fmaxf(affQ[so] * invP - mu * mu, 0.f);
        float s   = gP[tid] * rsqrtf(var + BNEPS);
        sSc[tid] = s;
        sSh[tid] = bP[tid] - mu * s;
    }
    if (stats && tid < TCN) { cs[tid] = 0.f; cq[tid] = 0.f; }
    __syncthreads();

    wmma::fragment<wmma::accumulator, 16, 16, 8, float> c[2][2];
    #pragma unroll
    for (int i = 0; i < 2; i++)
        #pragma unroll
        for (int j = 0; j < 2; j++)
            wmma::fill_fragment(c[i][j], 0.f);

    const int nk = Kd / 16;
    for (int kc = 0; kc < nk; kc++) {
        const int k0 = kc * 16;
        #pragma unroll
        for (int e = 0; e < 2; e++) {
            int lin = e * 256 + tid;
            int m = lin >> 2;
            int kq = (lin & 3) * 4;
            float4 v = *reinterpret_cast<const float4*>(&A[(long)(rowBase + m) * Kd + k0 + kq]);
            if (aff) {
                int gk = k0 + kq;
                v.x = fmaxf(v.x * sSc[gk+0] + sSh[gk+0], 0.f);
                v.y = fmaxf(v.y * sSc[gk+1] + sSh[gk+1], 0.f);
                v.z = fmaxf(v.z * sSc[gk+2] + sSh[gk+2], 0.f);
                v.w = fmaxf(v.w * sSc[gk+3] + sSh[gk+3], 0.f);
            }
            *reinterpret_cast<float4*>(&As[m * ALD + kq]) = v;
        }
        {
            int m = tid >> 2;
            int kq = (tid & 3) * 4;
            float4 v = *reinterpret_cast<const float4*>(&Bm[(long)(colBase + m) * Kd + k0 + kq]);
            *reinterpret_cast<float4*>(&Bs[m * ALD + kq]) = v;
        }
        __syncthreads();
        #pragma unroll
        for (int ks = 0; ks < 2; ks++) {
            wmma::fragment<wmma::matrix_a, 16, 16, 8, wmma::precision::tf32, wmma::row_major> a[2];
            wmma::fragment<wmma::matrix_b, 16, 16, 8, wmma::precision::tf32, wmma::col_major> b[2];
            #pragma unroll
            for (int i = 0; i < 2; i++) {
                wmma::load_matrix_sync(a[i], &As[(wm*32 + i*16) * ALD + ks*8], ALD);
                #pragma unroll
                for (int t = 0; t < a[i].num_elements; t++)
                    a[i].x[t] = wmma::__float_to_tf32(a[i].x[t]);
            }
            #pragma unroll
            for (int j = 0; j < 2; j++) {
                wmma::load_matrix_sync(b[j], &Bs[(wn*32 + j*16) * ALD + ks*8], ALD);
                #pragma unroll
                for (int t = 0; t < b[j].num_elements; t++)
                    b[j].x[t] = wmma::__float_to_tf32(b[j].x[t]);
            }
            #pragma unroll
            for (int i = 0; i < 2; i++)
                #pragma unroll
                for (int j = 0; j < 2; j++)
                    wmma::mma_sync(c[i][j], a[i], b[j], c[i][j]);
        }
        __syncthreads();
    }

    #pragma unroll
    for (int i = 0; i < 2; i++)
        #pragma unroll
        for (int j = 0; j < 2; j++)
            wmma::store_matrix_sync(&Csm[(wm*32 + i*16) * CLD + wn*32 + j*16], c[i][j],
                                    CLD, wmma::mem_row_major);
    __syncthreads();

    const int ccol = tid & 63;
    const int r0 = tid >> 6;
    float s = 0.f, q = 0.f;
    #pragma unroll 8
    for (int it = 0; it < 32; it++) {
        int r = r0 + it * 4;
        float v = Csm[r * CLD + ccol];
        Cm[(long)(rowBase + r) * O + colBase + ccol] = v;
        s += v; q += v * v;
    }
    if (stats) {
        atomicAdd(&cs[ccol], s);
        atomicAdd(&cq[ccol], q);
        __syncthreads();
        if (tid < TCN) {
            atomicAdd(&statS[statOff + colBase + tid], cs[tid]);
            atomicAdd(&statQ[statOff + colBase + tid], cq[tid]);
        }
    }
}

// top-16 smallest from shared d2[NN], 256 threads
__device__ void select_topk(float* d2, int* outIdx) {
    __shared__ float rv[8];
    __shared__ int   ri[8];
    int tid = threadIdx.x, lane = tid & 31, w = tid >> 5;
    for (int kk = 0; kk < KK; kk++) {
        float best = 3.4e38f; int bi = 0;
        for (int m = tid; m < NN; m += 256) {
            float v = d2[m];
            if (v < best) { best = v; bi = m; }
        }
        #pragma unroll
        for (int o = 16; o > 0; o >>= 1) {
            float ov = __shfl_down_sync(0xffffffffu, best, o);
            int   oi = __shfl_down_sync(0xffffffffu, bi, o);
            if (ov < best || (ov == best && oi < bi)) { best = ov; bi = oi; }
        }
        if (lane == 0) { rv[w] = best; ri[w] = bi; }
        __syncthreads();
        if (tid == 0) {
            float bv = rv[0]; int bj = ri[0];
            #pragma unroll
            for (int i = 1; i < 8; i++)
                if (rv[i] < bv || (rv[i] == bv && ri[i] < bj)) { bv = rv[i]; bj = ri[i]; }
            outIdx[kk] = bj;
            d2[bj] = 3.4e38f;
        }
        __syncthreads();
    }
}

__global__ void k_knn_desc(const float* __restrict__ inner, const float* __restrict__ nsqS,
                           const float* __restrict__ nsqD, int* __restrict__ idxOut) {
    int n = blockIdx.x, b = blockIdx.y;
    __shared__ float d2[NN];
    const float* row = inner + (long)b*NN*NN + (long)n*NN;
    float q = nsqS[b*NN + n];
    for (int m = threadIdx.x; m < NN; m += 256) d2[m] = q + nsqD[b*NN + m] - 2.f * row[m];
    __syncthreads();
    select_topk(d2, idxOut + ((long)b*NN + n) * KK);
}

// both clouds: grid.z = cloud
__global__ void k_knn_xyz(const float* __restrict__ xyzS, const float* __restrict__ xyzD,
                          int* __restrict__ idxAll) {
    int n = blockIdx.x, b = blockIdx.y, cloud = blockIdx.z;
    const float* xyz = cloud ? xyzD : xyzS;
    int* idxOut = idxAll + (long)cloud*PP;
    __shared__ float d2[NN];
    long base = (long)b * NN * 3;
    float qx = xyz[base + (long)n*3], qy = xyz[base + (long)n*3+1], qz = xyz[base + (long)n*3+2];
    float qq = qx*qx + qy*qy + qz*qz;
    for (int m = threadIdx.x; m < NN; m += 256) {
        float rx = xyz[base + (long)m*3], ry = xyz[base + (long)m*3+1], rz = xyz[base + (long)m*3+2];
        d2[m] = qq + rx*rx + ry*ry + rz*rz - 2.f*(qx*rx + qy*ry + qz*rz);
    }
    __syncthreads();
    select_topk(d2, idxOut + ((long)b*NN + n) * KK);
}

__global__ void k_simgather(const float* __restrict__ inner, const float* __restrict__ nrmS,
                            const float* __restrict__ nrmD, const float* __restrict__ maxDS,
                            const float* __restrict__ maxSD, const int* __restrict__ idx,
                            float* __restrict__ outSD, float* __restrict__ outDS) {
    int t = blockIdx.x * 256 + threadIdx.x;
    if (t >= PP) return;
    int b = t / (NN * KK);
    int n = (t / KK) & (NN - 1);
    int m = idx[t];
    float v  = inner[(long)b*NN*NN + (long)n*NN + m];
    float cs = v / (nrmD[b*NN + m] * nrmS[b*NN + n] + EPSF);
    outSD[t] = cs / (maxDS[b*NN + n] + EPSF);
    outDS[t] = cs / (maxSD[b*NN + m] + EPSF);
}

// both clouds: nbr conv input [knn_feats(C), rela(3), dist(1), pad(8)] stride 144
__global__ void k_build_nbr_f(const float* __restrict__ xyzS, const float* __restrict__ xyzD,
                              const float* __restrict__ dmatAll, const int* __restrict__ idxAll,
                              float* __restrict__ f) {
    int p = blockIdx.x;                 // 0 .. 2PP-1
    int cloud = p >= PP;
    int pl = p - cloud * PP;
    const float* xyz = cloud ? xyzD : xyzS;
    const float* dmatC = dmatAll + (long)cloud*BN*CC;
    int n = (pl / KK) & (NN - 1);
    int b = pl / (NN * KK);
    int m = idxAll[p];
    const float* dr = dmatC + ((long)b*NN + m) * CC;
    float* fo = f + (long)p * 144;
    int tid = threadIdx.x;
    fo[tid] = dr[tid];
    if (tid == 0) {
        long qb = ((long)b*NN + n) * 3, rb = ((long)b*NN + m) * 3;
        float rx = xyz[rb]-xyz[qb], ry = xyz[rb+1]-xyz[qb+1], rz = xyz[rb+2]-xyz[qb+2];
        fo[128] = rx; fo[129] = ry; fo[130] = rz; fo[131] = sqrtf(rx*rx+ry*ry+rz*rz);
        #pragma unroll
        for (int z = 132; z < 144; z++) fo[z] = 0.f;
    }
}

// both clouds: grid 2*BN, in-block affine from producer stats
__global__ void k_nbr_final(const float* __restrict__ yraw,
                            const float* __restrict__ affS, const float* __restrict__ affQ,
                            const float* __restrict__ gP, const float* __restrict__ bP, float invP,
                            const int* __restrict__ idxAll,
                            const float* __restrict__ dmatAll, float* __restrict__ outAll) {
    int gblk = blockIdx.x;
    int cloud = gblk >= BN;
    int bn = gblk - cloud * BN;
    const float* y = yraw + (long)cloud*PP*CC;
    const int* idx = idxAll + (long)cloud*PP;
    const float* dmat = dmatAll + (long)cloud*BN*CC;
    float* outN = outAll + (long)cloud*BN*CC;
    int tid = threadIdx.x; // 256
    __shared__ float fe[KK][CC];
    __shared__ float mk[KK], wgt[KK];
    __shared__ int sid[KK];
    __shared__ float sSc[CC], sSh[CC];
    if (tid < CC) {
        int so = cloud * CC + tid;
        float mu  = affS[so] * invP;
        float var = fmaxf(affQ[so] * invP - mu * mu, 0.f);
        float s   = gP[tid] * rsqrtf(var + BNEPS);
        sSc[tid] = s;
        sSh[tid] = bP[tid] - mu * s;
    }
    if (tid < KK) sid[tid] = idx[(long)bn*KK + tid];
    __syncthreads();
    for (int t = tid; t < KK * CC; t += 256) {
        int k = t >> 7, c = t & 127;
        float v = y[((long)bn*KK + k) * CC + c];
        fe[k][c] = fmaxf(v * sSc[c] + sSh[c], 0.f);
    }
    __syncthreads();
    int w = tid >> 5, lane = tid & 31;
    for (int kk = w; kk < KK; kk += 8) {
        float mx = -3.4e38f;
        for (int c = lane; c < CC; c += 32) mx = fmaxf(mx, fe[kk][c]);
        #pragma unroll
        for (int o = 16; o > 0; o >>= 1) mx = fmaxf(mx, __shfl_down_sync(0xffffffffu, mx, o));
        if (lane == 0) mk[kk] = mx;
    }
    __syncthreads();
    if (tid == 0) {
        float m = -3.4e38f;
        for (int k = 0; k < KK; k++) m = fmaxf(m, mk[k]);
        float s = 0.f;
        for (int k = 0; k < KK; k++) { float e = expf(mk[k]-m); wgt[k] = e; s += e; }
        float r = 1.f / s;
        for (int k = 0; k < KK; k++) wgt[k] *= r;
    }
    __syncthreads();
    if (tid < CC) {
        int b = bn >> 11;
        float a = 0.f;
        #pragma unroll
        for (int k = 0; k < KK; k++) a += wgt[k] * dmat[((long)b*NN + sid[k]) * CC + tid];
        outN[(long)bn*CC + tid] = a;
    }
}

// main feats build (272 ch)
__global__ void k_build_feats(const float* __restrict__ src_xyz, const float* __restrict__ dst_xyz,
                              const float* __restrict__ srcd, const float* __restrict__ dstd,
                              const float* __restrict__ srcw, const float* __restrict__ dstw,
                              const float* __restrict__ sdc, const float* __restrict__ dsc,
                              const float* __restrict__ sdn, const float* __restrict__ dsn,
                              const int* __restrict__ idx, float* __restrict__ feats) {
    int p = blockIdx.x;
    int n = (p / KK) & (NN - 1);
    int b = p / (NN * KK);
    int m = idx[p];
    float* fo = feats + (long)p * 272;
    int tid = threadIdx.x;
    fo[10 + tid]  = srcd[((long)b*NN + n) * CC + tid];
    fo[138 + tid] = dstd[((long)b*NN + m) * CC + tid];
    if (tid == 0) {
        long qb = ((long)b*NN + n) * 3, rb = ((long)b*NN + m) * 3;
        float sx = src_xyz[qb], sy = src_xyz[qb+1], sz = src_xyz[qb+2];
        float kx = dst_xyz[rb], ky = dst_xyz[rb+1], kz = dst_xyz[rb+2];
        float rx = kx-sx, ry = ky-sy, rz = kz-sz;
        fo[0]=rx; fo[1]=ry; fo[2]=rz; fo[3]=sqrtf(rx*rx+ry*ry+rz*rz);
        fo[4]=sx; fo[5]=sy; fo[6]=sz; fo[7]=kx; fo[8]=ky; fo[9]=kz;
        fo[266]=srcw[b*NN+n]; fo[267]=dstw[b*NN+m];
        fo[268]=sdc[p]; fo[269]=dsc[p]; fo[270]=sdn[p]; fo[271]=dsn[p];
    }
}

__global__ void k_attention(const float* __restrict__ yraw,
                            const float* __restrict__ affS, const float* __restrict__ affQ,
                            const float* __restrict__ gP, const float* __restrict__ bP, float invP,
                            const int* __restrict__ idx, const float* __restrict__ dst_xyz,
                            float* __restrict__ outC, float* __restrict__ att) {
    int bn = blockIdx.x, tid = threadIdx.x; // 256
    __shared__ float fe[KK][256];
    __shared__ float mk[KK], wgt[KK];
    __shared__ int sid[KK];
    if (tid < KK) sid[tid] = idx[(long)bn*KK + tid];
    float mu  = affS[tid] * invP;
    float var = fmaxf(affQ[tid] * invP - mu * mu, 0.f);
    float s   = gP[tid] * rsqrtf(var + BNEPS);
    float h   = bP[tid] - mu * s;
    #pragma unroll
    for (int k = 0; k < KK; k++) {
        float v = yraw[((long)bn*KK + k) * 256 + tid];
        fe[k][tid] = fmaxf(v * s + h, 0.f);
    }
    __syncthreads();
    int w = tid >> 5, lane = tid & 31;
    for (int kk = w; kk < KK; kk += 8) {
        float mx = -3.4e38f;
        for (int c = lane; c < 256; c += 32) mx = fmaxf(mx, fe[kk][c]);
        #pragma unroll
        for (int o = 16; o > 0; o >>= 1) mx = fmaxf(mx, __shfl_down_sync(0xffffffffu, mx, o));
        if (lane == 0) mk[kk] = mx;
    }
    __syncthreads();
    if (tid == 0) {
        float m = -3.4e38f;
        for (int k = 0; k < KK; k++) m = fmaxf(m, mk[k]);
        float ssum = 0.f;
        for (int k = 0; k < KK; k++) { float e = expf(mk[k]-m); wgt[k] = e; ssum += e; }
        float r = 1.f / ssum;
        for (int k = 0; k < KK; k++) wgt[k] *= r;
    }
    __syncthreads();
    float a = 0.f;
    #pragma unroll
    for (int k = 0; k < KK; k++) a += wgt[k] * fe[k][tid];
    att[(long)bn * 256 + tid] = a;
    if (tid < 3) {
        int b = bn >> 11;
        float cg = 0.f;
        #pragma unroll
        for (int k = 0; k < KK; k++)
            cg += wgt[k] * dst_xyz[((long)b*NN + sid[k]) * 3 + tid];
        outC[(long)bn * 3 + tid] = cg;
    }
}

__global__ void k_mlp3(const float* __restrict__ yraw,
                       const float* __restrict__ affS, const float* __restrict__ affQ,
                       const float* __restrict__ gP, const float* __restrict__ bP, float invP,
                       const float* __restrict__ w3, const float* __restrict__ b3,
                       float* __restrict__ outw) {
    int bn = blockIdx.x, tid = threadIdx.x; // 256
    float mu  = affS[tid] * invP;
    float var = fmaxf(affQ[tid] * invP - mu * mu, 0.f);
    float s   = gP[tid] * rsqrtf(var + BNEPS);
    float h   = bP[tid] - mu * s;
    float v = fmaxf(yraw[(long)bn*256 + tid] * s + h, 0.f) * w3[tid];
    #pragma unroll
    for (int o = 16; o > 0; o >>= 1) v += __shfl_down_sync(0xffffffffu, v, o);
    __shared__ float ps[8];
    if ((tid & 31) == 0) ps[tid >> 5] = v;
    __syncthreads();
    if (tid == 0) {
        float s2 = 0.f;
        #pragma unroll
        for (int i = 0; i < 8; i++) s2 += ps[i];
        outw[bn] = 1.f / (1.f + expf(-(s2 + b3[0])));
    }
}

extern "C" void kernel_launch(void* const* d_in, const int* in_sizes, int n_in,
                              void* d_out, int out_size) {
    const float* src_xyz  = (const float*)d_in[0];
    const float* src_desc = (const float*)d_in[1];
    const float* dst_xyz  = (const float*)d_in[2];
    const float* dst_desc = (const float*)d_in[3];
    const float* src_w    = (const float*)d_in[4];
    const float* dst_w    = (const float*)d_in[5];
    const float* c1_W0 = (const float*)d_in[6];
    const float* c1_W  = (const float*)d_in[7];
    const float* c1_g  = (const float*)d_in[8];
    const float* c1_b  = (const float*)d_in[9];
    const float* c2_W0 = (const float*)d_in[10];
    const float* c2_W  = (const float*)d_in[11];
    const float* c2_g  = (const float*)d_in[12];
    const float* c2_b  = (const float*)d_in[13];
    const float* m1_W  = (const float*)d_in[14];
    const float* m1_g  = (const float*)d_in[16];
    const float* m1_b  = (const float*)d_in[17];
    const float* m2_W  = (const float*)d_in[18];
    const float* m2_g  = (const float*)d_in[20];
    const float* m2_b  = (const float*)d_in[21];
    const float* m3_W  = (const float*)d_in[22];
    const float* m3_b  = (const float*)d_in[23];

    float* base = nullptr;
    cudaGetSymbolAddress((void**)&base, g_pool);
    float* srcd   = base + F_SRCD;
    float* dstd   = base + F_DSTD;
    float* nsqS   = base + F_NSQS;
    float* nsqD   = base + F_NSQD;
    float* nrmS   = base + F_NRMS;
    float* nrmD   = base + F_NRMD;
    float* maxDS  = base + F_MAXDS;
    float* maxSD  = base + F_MAXSD;
    float* nrm2S  = base + F_NRM2S;
    float* nrm2D  = base + F_NRM2D;
    float* sdc    = base + F_SDC;
    float* dsc    = base + F_DSC;
    float* sdn    = base + F_SDN;
    float* dsn    = base + F_DSN;
    float* stat0  = base + F_STATS;          // 8 slots x 1024 (S at +0, Q at +512)
    float* w2p    = base + F_W2P;
    int*   idx    = (int*)(base + F_IDX);
    int*   sidx   = (int*)(base + F_SIDX);   // [sidx | didx] contiguous 2*PP
    float* att    = base + F_ATT;
    float* mb1    = base + F_MB1;
    float* mb2    = base + F_MB2;
    float* srcnbr = base + F_SRCNBR;         // [srcnbr | dstnbr] contiguous
    float* inner  = base + F_INNER;
    float* fbuf   = base + F_F;
    float* y0     = base + F_Y0;
    float* y1     = base + F_Y1;
    float* outC   = (float*)d_out;
    float* outW   = (float*)d_out + (long)BB*NN*3;

    auto slot = [&](int i) { return stat0 + (long)i * 1024; };
    const float invPP = 1.f / (float)PP;
    const float invBN = 1.f / (float)BN;

    // init: zero ALL stat slots (one launch), pad weight
    k_fill<<<32, 256>>>(stat0, 0.f, 8 * 1024);
    k_pad_w<<<128, 144>>>(c2_W0, w2p);

    // A: transpose + norms (both clouds in one launch)
    k_transpose_norm<<<dim3(BN, 2), 128>>>(src_desc, dst_desc, srcd, nsqS, nrmS);

    // inner = src . dst (split-tf32 TC) with fused cosine maxes
    k_fill<<<32, 256>>>(maxDS, -3.4e38f, 2*BN);
    k_gemm_sim<<<dim3(NN/SGN, NN/SGM, 2), 256>>>(srcd, dstd, inner, nrmS, nrmD, maxDS, maxSD);
    k_knn_desc<<<dim3(NN, BB), 256>>>(inner, nsqS, nsqD, idx);
    k_simgather<<<PP/256, 256>>>(inner, nrmS, nrmD, maxDS, maxSD, idx, sdc, dsc);

    // B: neighborhood descriptors — both clouds batched; no finalize kernels
    k_knn_xyz<<<dim3(NN, BB, 2), 256>>>(src_xyz, dst_xyz, sidx);
    k_build_nbr_f<<<2*PP, 128>>>(src_xyz, dst_xyz, srcd, sidx, fbuf);
    const float* c2W1 = c2_W;
    const float* c2W2 = c2_W + CC*CC;
    k_gemm_tc<<<dim3(CC/TCN, (2*PP)/TCM), 256>>>(fbuf, w2p, y0, 2*PP, CC, 144,
        nullptr, nullptr, nullptr, nullptr, 0.f, slot(0), slot(0)+512, PP);
    k_gemm_tc<<<dim3(CC/TCN, (2*PP)/TCM), 256>>>(y0, c2W1, y1, 2*PP, CC, CC,
        slot(0), slot(0)+512, c2_g, c2_b, invPP, slot(1), slot(1)+512, PP);
    k_gemm_tc<<<dim3(CC/TCN, (2*PP)/TCM), 256>>>(y1, c2W2, y0, 2*PP, CC, CC,
        slot(1), slot(1)+512, c2_g + CC, c2_b + CC, invPP, slot(2), slot(2)+512, PP);
    k_nbr_final<<<2*BN, 256>>>(y0, slot(2), slot(2)+512, c2_g + 2*CC, c2_b + 2*CC, invPP,
                               sidx, srcd, srcnbr);

    // nbr cosine sims
    k_rownorm<<<2*BN, 128>>>(srcnbr, nrm2S);
    k_fill<<<32, 256>>>(maxDS, -3.4e38f, 2*BN);
    k_gemm_sim<<<dim3(NN/SGN, NN/SGM, 2), 256>>>(srcnbr, srcnbr + (long)BN*CC, inner,
                                                 nrm2S, nrm2D, maxDS, maxSD);
    k_simgather<<<PP/256, 256>>>(inner, nrm2S, nrm2D, maxDS, maxSD, idx, sdn, dsn);

    // C: main feature conv + attention
    k_build_feats<<<PP, 128>>>(src_xyz, dst_xyz, srcd, dstd, src_w, dst_w,
                               sdc, dsc, sdn, dsn, idx, fbuf);
    const float* c1W1 = c1_W;
    const float* c1W2 = c1_W + 256*256;
    k_gemm_tc<<<dim3(256/TCN, PP/TCM), 256>>>(fbuf, c1_W0, y0, PP, 256, 272,
        nullptr, nullptr, nullptr, nullptr, 0.f, slot(3), slot(3)+512, 0);
    k_gemm_tc<<<dim3(256/TCN, PP/TCM), 256>>>(y0, c1W1, y1, PP, 256, 256,
        slot(3), slot(3)+512, c1_g, c1_b, invPP, slot(4), slot(4)+512, 0);
    k_gemm_tc<<<dim3(256/TCN, PP/TCM), 256>>>(y1, c1W2, y0, PP, 256, 256,
        slot(4), slot(4)+512, c1_g + 256, c1_b + 256, invPP, slot(5), slot(5)+512, 0);
    k_attention<<<BN, 256>>>(y0, slot(5), slot(5)+512, c1_g + 512, c1_b + 512, invPP,
                             idx, dst_xyz, outC, att);

    // D: MLP head
    k_gemm_tc<<<dim3(256/TCN, BN/TCM), 256>>>(att, m1_W, mb1, BN, 256, 256,
        nullptr, nullptr, nullptr, nullptr, 0.f, slot(6), slot(6)+512, 0);
    k_gemm_tc<<<dim3(256/TCN, BN/TCM), 256>>>(mb1, m2_W, mb2, BN, 256, 256,
        slot(6), slot(6)+512, m1_g, m1_b, invBN, slot(7), slot(7)+512, 0);
    k_mlp3<<<BN, 256>>>(mb2, slot(7), slot(7)+512, m2_g, m2_b, invBN, m3_W, m3_b, outW);
}

// round 11
// speedup vs baseline: 1.3504x; 1.1480x over previous
#include <cuda_runtime.h>
#include <mma.h>
#include <math.h>
#include <float.h>

using namespace nvcuda;

#define BB 2
#define NN 2048
#define CC 128
#define KK 16
#define BN (BB*NN)
#define PP (BB*NN*KK)
#define EPSF 1e-6f
#define BNEPS 1e-5f

// ---------------- scratch pool ----------------
constexpr long F_SRCD   = 0;
constexpr long F_DSTD   = F_SRCD   + (long)BN*CC;
constexpr long F_NSQS   = F_DSTD   + (long)BN*CC;
constexpr long F_NSQD   = F_NSQS   + BN;
constexpr long F_NRMS   = F_NSQD   + BN;
constexpr long F_NRMD   = F_NRMS   + BN;
constexpr long F_MAXDS  = F_NRMD   + BN;
constexpr long F_MAXSD  = F_MAXDS  + BN;
constexpr long F_NRM2S  = F_MAXSD  + BN;
constexpr long F_NRM2D  = F_NRM2S  + BN;
constexpr long F_SDC    = F_NRM2D  + BN;
constexpr long F_DSC    = F_SDC    + PP;
constexpr long F_SDN    = F_DSC    + PP;
constexpr long F_DSN    = F_SDN    + PP;
constexpr long F_STATS  = F_DSN    + PP;            // 8 slots x 1024 (S at +0, Q at +512)
constexpr long F_W2P    = F_STATS  + 8*1024;        // padded c2_W0 [128][144]
constexpr long F_IDX    = F_W2P    + 128*144;       // int
constexpr long F_SIDX   = F_IDX    + PP;
constexpr long F_DIDX   = F_SIDX   + PP;
constexpr long F_ATT    = F_DIDX   + PP;
constexpr long F_MB1    = F_ATT    + (long)BN*256;
constexpr long F_MB2    = F_MB1    + (long)BN*256;
constexpr long F_SRCNBR = F_MB2    + (long)BN*256;
constexpr long F_DSTNBR = F_SRCNBR + (long)BN*CC;
constexpr long F_INNER  = F_DSTNBR + (long)BN*CC;
constexpr long F_F      = F_INNER  + (long)BB*NN*NN;
constexpr long F_FSZ    = (long)2*PP*144;           // max(PP*272, 2PP*144)
constexpr long F_Y0     = F_F      + F_FSZ;
constexpr long F_Y1     = F_Y0     + (long)PP*256;
constexpr long F_END    = F_Y1     + (long)PP*256;

__device__ __align__(128) float g_pool[F_END];

__device__ __forceinline__ void atomicMaxF(float* a, float v) {
    if (!(v < 0.f)) atomicMax((int*)a, __float_as_int(v));
    else            atomicMin((unsigned int*)a, __float_as_uint(v));
}

__device__ __forceinline__ unsigned cvt_tf32(float x) {
    unsigned u;
    asm("cvt.rn.tf32.f32 %0, %1;" : "=r"(u) : "f"(x));
    return u;
}

__device__ __forceinline__ void cp_async16(unsigned saddr, const void* gptr) {
    asm volatile("cp.async.ca.shared.global [%0], [%1], 16;" :: "r"(saddr), "l"(gptr));
}
__device__ __forceinline__ void cp_commit() { asm volatile("cp.async.commit_group;"); }
template<int N> __device__ __forceinline__ void cp_wait() {
    asm volatile("cp.async.wait_group %0;" :: "n"(N));
}

__global__ void k_fill(float* __restrict__ p, float v, int n) {
    int i = blockIdx.x * blockDim.x + threadIdx.x;
    if (i < n) p[i] = v;
}

__global__ void k_pad_w(const float* __restrict__ W, float* __restrict__ Wp) {
    int o = blockIdx.x; int k = threadIdx.x; // 144 threads
    Wp[o * 144 + k] = (k < 132) ? W[o * 132 + k] : 0.f;
}

// both clouds: [B,C,N] -> [B,N,C] plus |.|^2 and |.|
__global__ void k_transpose_norm(const float* __restrict__ descS, const float* __restrict__ descD,
                                 float* __restrict__ dmatAll, float* __restrict__ nsqAll,
                                 float* __restrict__ nrmAll) {
    int cloud = blockIdx.y;
    const float* desc = cloud ? descD : descS;
    float* dmat = dmatAll + (long)cloud*BN*CC;
    float* nsq  = nsqAll  + cloud*BN;
    float* nrm  = nrmAll  + cloud*BN;
    int bn = blockIdx.x; int b = bn >> 11; int n = bn & (NN - 1);
    int c = threadIdx.x;
    float v = desc[((long)b*CC + c)*NN + n];
    dmat[(long)bn*CC + c] = v;
    float s = v * v;
    #pragma unroll
    for (int o = 16; o > 0; o >>= 1) s += __shfl_down_sync(0xffffffffu, s, o);
    __shared__ float ps[4];
    if ((c & 31) == 0) ps[c >> 5] = s;
    __syncthreads();
    if (c == 0) { float t = ps[0]+ps[1]+ps[2]+ps[3]; nsq[bn] = t; nrm[bn] = sqrtf(t); }
}

__global__ void k_rownorm(const float* __restrict__ dmat, float* __restrict__ nrm) {
    int bn = blockIdx.x; int c = threadIdx.x;
    float v = dmat[(long)bn*CC + c];
    float s = v * v;
    #pragma unroll
    for (int o = 16; o > 0; o >>= 1) s += __shfl_down_sync(0xffffffffu, s, o);
    __shared__ float ps[4];
    if ((c & 31) == 0) ps[c >> 5] = s;
    __syncthreads();
    if (c == 0) nrm[bn] = sqrtf(ps[0]+ps[1]+ps[2]+ps[3]);
}

// ---------------- split-tf32 inner GEMM + fused cosine maxes (unchanged, wmma) ------------
#define SGM 128
#define SGN 64
#define SLD 20
#define SCLD 68

__global__ __launch_bounds__(256)
void k_gemm_sim(const float* __restrict__ A, const float* __restrict__ Bm,
                float* __restrict__ Cm,
                const float* __restrict__ nrmA, const float* __restrict__ nrmB,
                float* __restrict__ maxDS, float* __restrict__ maxSD) {
    const int b = blockIdx.z;
    A  += (long)b * NN * CC;
    Bm += (long)b * NN * CC;
    Cm += (long)b * NN * NN;

    __shared__ __align__(16) float smem[SGM * SCLD];
    float* Ahi = smem;
    float* Alo = smem + SGM*SLD;
    float* Bhi = smem + 2*SGM*SLD;
    float* Blo = smem + 2*SGM*SLD + SGN*SLD;
    float* Csm = smem;
    __shared__ float rns[SGM], rnd[SGN], rm[SGM], cmx[SGN];

    const int tid = threadIdx.x;
    const int lane = tid & 31;
    const int wid = tid >> 5;
    const int wm = wid & 3;
    const int wn = wid >> 2;
    const long rowBase = (long)blockIdx.y * SGM;
    const int colBase = blockIdx.x * SGN;

    if (tid < SGM) { rns[tid] = nrmA[b*NN + rowBase + tid]; rm[tid] = -3.4e38f; }
    if (tid < SGN) { rnd[tid] = nrmB[b*NN + colBase + tid]; cmx[tid] = -3.4e38f; }

    const int ma = tid >> 2;
    const int kq = (tid & 3) * 4;

    wmma::fragment<wmma::accumulator, 16, 16, 8, float> c[2][2];
    #pragma unroll
    for (int i = 0; i < 2; i++)
        #pragma unroll
        for (int j = 0; j < 2; j++)
            wmma::fill_fragment(c[i][j], 0.f);

    const int nk = CC / 16;
    for (int kc = 0; kc < nk; kc++) {
        const int k0 = kc * 16;
        #pragma unroll
        for (int e = 0; e < 2; e++) {
            int m = ma + e * 64;
            float4 v = *reinterpret_cast<const float4*>(&A[(rowBase + m) * CC + k0 + kq]);
            float4 h, l;
            h.x = wmma::__float_to_tf32(v.x); l.x = wmma::__float_to_tf32(v.x - h.x);
            h.y = wmma::__float_to_tf32(v.y); l.y = wmma::__float_to_tf32(v.y - h.y);
            h.z = wmma::__float_to_tf32(v.z); l.z = wmma::__float_to_tf32(v.z - h.z);
            h.w = wmma::__float_to_tf32(v.w); l.w = wmma::__float_to_tf32(v.w - h.w);
            *reinterpret_cast<float4*>(&Ahi[m * SLD + kq]) = h;
            *reinterpret_cast<float4*>(&Alo[m * SLD + kq]) = l;
        }
        {
            int m = ma & 63;
            float4 v = *reinterpret_cast<const float4*>(&Bm[(long)(colBase + m) * CC + k0 + kq]);
            float4 h, l;
            h.x = wmma::__float_to_tf32(v.x); l.x = wmma::__float_to_tf32(v.x - h.x);
            h.y = wmma::__float_to_tf32(v.y); l.y = wmma::__float_to_tf32(v.y - h.y);
            h.z = wmma::__float_to_tf32(v.z); l.z = wmma::__float_to_tf32(v.z - h.z);
            h.w = wmma::__float_to_tf32(v.w); l.w = wmma::__float_to_tf32(v.w - h.w);
            *reinterpret_cast<float4*>(&Bhi[m * SLD + kq]) = h;
            *reinterpret_cast<float4*>(&Blo[m * SLD + kq]) = l;
        }
        __syncthreads();
        #pragma unroll
        for (int ks = 0; ks < 2; ks++) {
            wmma::fragment<wmma::matrix_a, 16, 16, 8, wmma::precision::tf32, wmma::row_major> ah[2], al[2];
            wmma::fragment<wmma::matrix_b, 16, 16, 8, wmma::precision::tf32, wmma::col_major> bh[2], bl[2];
            #pragma unroll
            for (int i = 0; i < 2; i++) {
                wmma::load_matrix_sync(ah[i], &Ahi[(wm*32 + i*16) * SLD + ks*8], SLD);
                wmma::load_matrix_sync(al[i], &Alo[(wm*32 + i*16) * SLD + ks*8], SLD);
            }
            #pragma unroll
            for (int j = 0; j < 2; j++) {
                wmma::load_matrix_sync(bh[j], &Bhi[(wn*32 + j*16) * SLD + ks*8], SLD);
                wmma::load_matrix_sync(bl[j], &Blo[(wn*32 + j*16) * SLD + ks*8], SLD);
            }
            #pragma unroll
            for (int i = 0; i < 2; i++)
                #pragma unroll
                for (int j = 0; j < 2; j++) {
                    wmma::mma_sync(c[i][j], ah[i], bh[j], c[i][j]);
                    wmma::mma_sync(c[i][j], ah[i], bl[j], c[i][j]);
                    wmma::mma_sync(c[i][j], al[i], bh[j], c[i][j]);
                }
        }
        __syncthreads();
    }

    #pragma unroll
    for (int i = 0; i < 2; i++)
        #pragma unroll
        for (int j = 0; j < 2; j++)
            wmma::store_matrix_sync(&Csm[(wm*32 + i*16) * SCLD + wn*32 + j*16], c[i][j],
                                    SCLD, wmma::mem_row_major);
    __syncthreads();

    const int ccol = tid & 63;
    const int r0 = tid >> 6;
    const float nd = rnd[ccol];
    float colmax = -3.4e38f;
    #pragma unroll 8
    for (int it = 0; it < 32; it++) {
        int r = r0 + it * 4;
        float v = Csm[r * SCLD + ccol];
        Cm[(rowBase + r) * NN + colBase + ccol] = v;
        float csv = v / (nd * rns[r] + EPSF);
        colmax = fmaxf(colmax, csv);
        float wmx = csv;
        #pragma unroll
        for (int o = 16; o > 0; o >>= 1) wmx = fmaxf(wmx, __shfl_down_sync(0xffffffffu, wmx, o));
        if (lane == 0) atomicMaxF(&rm[r], wmx);
    }
    atomicMaxF(&cmx[ccol], colmax);
    __syncthreads();
    if (tid < SGM) atomicMaxF(&maxDS[b*NN + rowBase + tid], rm[tid]);
    else if (tid < SGM + SGN) atomicMaxF(&maxSD[b*NN + colBase + (tid - SGM)], cmx[tid - SGM]);
}

// ---------------- TF32 TC GEMM v3: PTX mma.m16n8k8 + cp.async double buffering ----------
// Block 128x64, 8 warps 4Mx2N, warp tile 32x32 (2x m16 x 4x n8).
// A staged RAW (affine+ReLU+tf32 applied at fragment build via documented layout).
// smem: double-buffered raw staging (30720B) unioned with C staging (34816B).
#define TCM 128
#define TCN 64
#define ALD 20
#define CLD 68

__global__ __launch_bounds__(256, 3)
void k_gemm_tc(const float* __restrict__ A, const float* __restrict__ Bm,
               float* __restrict__ Cm, int P, int O, int Kd,
               const float* __restrict__ affS, const float* __restrict__ affQ,
               const float* __restrict__ gP, const float* __restrict__ bP, float invP,
               float* __restrict__ statS, float* __restrict__ statQ, int splitRows) {
    __shared__ __align__(16) float smem[TCM * CLD];
    float* Ab[2] = { smem,                    smem + TCM*ALD };
    float* Bb[2] = { smem + 2*TCM*ALD,        smem + 2*TCM*ALD + TCN*ALD };
    float* Csm = smem;
    __shared__ float cs[TCN], cq[TCN];
    __shared__ float sSc[256], sSh[256];

    const int tid = threadIdx.x;
    const int lane = tid & 31;
    const int g   = lane >> 2;         // groupID
    const int tig = lane & 3;          // threadID in group
    const int wid = tid >> 5;
    const int wm = wid & 3;            // 0..3 along M
    const int wn = wid >> 2;           // 0..1 along N
    const int rowBase = blockIdx.y * TCM;
    const int colBase = blockIdx.x * TCN;
    const bool aff = (affS != nullptr);
    const bool stats = (statS != nullptr);
    const int cloudA = (splitRows > 0 && rowBase >= splitRows) ? 1 : 0;
    const int statOff = cloudA * O;

    if (aff && tid < Kd && tid < 256) {
        int so = cloudA * Kd + tid;
        float mu  = affS[so] * invP;
        float var = fmaxf(affQ[so] * invP - mu * mu, 0.f);
        float s   = gP[tid] * rsqrtf(var + BNEPS);
        sSc[tid] = s;
        sSh[tid] = bP[tid] - mu * s;
    }
    if (stats && tid < TCN) { cs[tid] = 0.f; cq[tid] = 0.f; }

    // staging coords: A rows (tid>>2) and +64, kq = (tid&3)*4 ; B row (tid>>2)
    const int srow = tid >> 2;
    const int kq = (tid & 3) * 4;
    unsigned sbase;
    asm("{ .reg .u64 t; cvta.to.shared.u64 t, %1; cvt.u32.u64 %0, t; }"
        : "=r"(sbase) : "l"(smem));

    auto issue = [&](int kc, int buf) {
        int k0 = kc * 16;
        const float* ga0 = &A[(long)(rowBase + srow) * Kd + k0 + kq];
        const float* ga1 = &A[(long)(rowBase + srow + 64) * Kd + k0 + kq];
        const float* gb  = &Bm[(long)(colBase + srow) * Kd + k0 + kq];
        unsigned da0 = sbase + (unsigned)(((Ab[buf] - smem) + srow * ALD + kq) * 4);
        unsigned da1 = da0 + 64u * ALD * 4u;
        unsigned db  = sbase + (unsigned)(((Bb[buf] - smem) + srow * ALD + kq) * 4);
        cp_async16(da0, ga0);
        cp_async16(da1, ga1);
        cp_async16(db, gb);
        cp_commit();
    };

    float acc[2][4][4];
    #pragma unroll
    for (int i = 0; i < 2; i++)
        #pragma unroll
        for (int j = 0; j < 4; j++)
            #pragma unroll
            for (int t = 0; t < 4; t++)
                acc[i][j][t] = 0.f;

    const int nk = Kd / 16;
    issue(0, 0);

    for (int kc = 0; kc < nk; kc++) {
        const int cur = kc & 1;
        const bool more = (kc + 1 < nk);
        if (more) { issue(kc + 1, cur ^ 1); cp_wait<1>(); }
        else      { cp_wait<0>(); }
        __syncthreads();

        const float* As = Ab[cur];
        const float* Bs = Bb[cur];
        const int k0 = kc * 16;
        #pragma unroll
        for (int ks = 0; ks < 2; ks++) {
            const int kb = ks * 8;
            float sc0 = 1.f, sh0 = 0.f, sc4 = 1.f, sh4 = 0.f;
            if (aff) {
                sc0 = sSc[k0 + kb + tig];     sh0 = sSh[k0 + kb + tig];
                sc4 = sSc[k0 + kb + tig + 4]; sh4 = sSh[k0 + kb + tig + 4];
            }
            // B fragments: 4 n8 tiles
            unsigned b0[4], b1[4];
            #pragma unroll
            for (int nj = 0; nj < 4; nj++) {
                int nb = wn * 32 + nj * 8 + g;
                b0[nj] = cvt_tf32(Bs[nb * ALD + kb + tig]);
                b1[nj] = cvt_tf32(Bs[nb * ALD + kb + tig + 4]);
            }
            // A fragments: 2 m16 tiles, affine+relu+cvt
            #pragma unroll
            for (int mi = 0; mi < 2; mi++) {
                int ar = wm * 32 + mi * 16;
                float v0 = As[(ar + g    ) * ALD + kb + tig];
                float v1 = As[(ar + g + 8) * ALD + kb + tig];
                float v2 = As[(ar + g    ) * ALD + kb + tig + 4];
                float v3 = As[(ar + g + 8) * ALD + kb + tig + 4];
                if (aff) {
                    v0 = fmaxf(v0 * sc0 + sh0, 0.f);
                    v1 = fmaxf(v1 * sc0 + sh0, 0.f);
                    v2 = fmaxf(v2 * sc4 + sh4, 0.f);
                    v3 = fmaxf(v3 * sc4 + sh4, 0.f);
                }
                unsigned a0 = cvt_tf32(v0), a1 = cvt_tf32(v1);
                unsigned a2 = cvt_tf32(v2), a3 = cvt_tf32(v3);
                #pragma unroll
                for (int nj = 0; nj < 4; nj++) {
                    asm volatile(
                        "mma.sync.aligned.m16n8k8.row.col.f32.tf32.tf32.f32 "
                        "{%0,%1,%2,%3}, {%4,%5,%6,%7}, {%8,%9}, {%0,%1,%2,%3};"
                        : "+f"(acc[mi][nj][0]), "+f"(acc[mi][nj][1]),
                          "+f"(acc[mi][nj][2]), "+f"(acc[mi][nj][3])
                        : "r"(a0), "r"(a1), "r"(a2), "r"(a3),
                          "r"(b0[nj]), "r"(b1[nj]));
                }
            }
        }
        __syncthreads();
    }

    // epilogue: acc -> C smem (known layout), then coalesced store + stats
    #pragma unroll
    for (int mi = 0; mi < 2; mi++) {
        int r0r = wm * 32 + mi * 16 + g;
        #pragma unroll
        for (int nj = 0; nj < 4; nj++) {
            int c0 = wn * 32 + nj * 8 + 2 * tig;
            Csm[r0r * CLD + c0]           = acc[mi][nj][0];
            Csm[r0r * CLD + c0 + 1]       = acc[mi][nj][1];
            Csm[(r0r + 8) * CLD + c0]     = acc[mi][nj][2];
            Csm[(r0r + 8) * CLD + c0 + 1] = acc[mi][nj][3];
        }
    }
    __syncthreads();

    const int ccol = tid & 63;
    const int r0 = tid >> 6;
    float s = 0.f, q = 0.f;
    #pragma unroll 8
    for (int it = 0; it < 32; it++) {
        int r = r0 + it * 4;
        float v = Csm[r * CLD + ccol];
        Cm[(long)(rowBase + r) * O + colBase + ccol] = v;
        s += v; q += v * v;
    }
    if (stats) {
        atomicAdd(&cs[ccol], s);
        atomicAdd(&cq[ccol], q);
        __syncthreads();
        if (tid < TCN) {
            atomicAdd(&statS[statOff + colBase + tid], cs[tid]);
            atomicAdd(&statQ[statOff + colBase + tid], cq[tid]);
        }
    }
}

// top-16 smallest from shared d2[NN], 256 threads
__device__ void select_topk(float* d2, int* outIdx) {
    __shared__ float rv[8];
    __shared__ int   ri[8];
    int tid = threadIdx.x, lane = tid & 31, w = tid >> 5;
    for (int kk = 0; kk < KK; kk++) {
        float best = 3.4e38f; int bi = 0;
        for (int m = tid; m < NN; m += 256) {
            float v = d2[m];
            if (v < best) { best = v; bi = m; }
        }
        #pragma unroll
        for (int o = 16; o > 0; o >>= 1) {
            float ov = __shfl_down_sync(0xffffffffu, best, o);
            int   oi = __shfl_down_sync(0xffffffffu, bi, o);
            if (ov < best || (ov == best && oi < bi)) { best = ov; bi = oi; }
        }
        if (lane == 0) { rv[w] = best; ri[w] = bi; }
        __syncthreads();
        if (tid == 0) {
            float bv = rv[0]; int bj = ri[0];
            #pragma unroll
            for (int i = 1; i < 8; i++)
                if (rv[i] < bv || (rv[i] == bv && ri[i] < bj)) { bv = rv[i]; bj = ri[i]; }
            outIdx[kk] = bj;
            d2[bj] = 3.4e38f;
        }
        __syncthreads();
    }
}

__global__ void k_knn_desc(const float* __restrict__ inner, const float* __restrict__ nsqS,
                           const float* __restrict__ nsqD, int* __restrict__ idxOut) {
    int n = blockIdx.x, b = blockIdx.y;
    __shared__ float d2[NN];
    const float* row = inner + (long)b*NN*NN + (long)n*NN;
    float q = nsqS[b*NN + n];
    for (int m = threadIdx.x; m < NN; m += 256) d2[m] = q + nsqD[b*NN + m] - 2.f * row[m];
    __syncthreads();
    select_topk(d2, idxOut + ((long)b*NN + n) * KK);
}

__global__ void k_knn_xyz(const float* __restrict__ xyzS, const float* __restrict__ xyzD,
                          int* __restrict__ idxAll) {
    int n = blockIdx.x, b = blockIdx.y, cloud = blockIdx.z;
    const float* xyz = cloud ? xyzD : xyzS;
    int* idxOut = idxAll + (long)cloud*PP;
    __shared__ float d2[NN];
    long base = (long)b * NN * 3;
    float qx = xyz[base + (long)n*3], qy = xyz[base + (long)n*3+1], qz = xyz[base + (long)n*3+2];
    float qq = qx*qx + qy*qy + qz*qz;
    for (int m = threadIdx.x; m < NN; m += 256) {
        float rx = xyz[base + (long)m*3], ry = xyz[base + (long)m*3+1], rz = xyz[base + (long)m*3+2];
        d2[m] = qq + rx*rx + ry*ry + rz*rz - 2.f*(qx*rx + qy*ry + qz*rz);
    }
    __syncthreads();
    select_topk(d2, idxOut + ((long)b*NN + n) * KK);
}

__global__ void k_simgather(const float* __restrict__ inner, const float* __restrict__ nrmS,
                            const float* __restrict__ nrmD, const float* __restrict__ maxDS,
                            const float* __restrict__ maxSD, const int* __restrict__ idx,
                            float* __restrict__ outSD, float* __restrict__ outDS) {
    int t = blockIdx.x * 256 + threadIdx.x;
    if (t >= PP) return;
    int b = t / (NN * KK);
    int n = (t / KK) & (NN - 1);
    int m = idx[t];
    float v  = inner[(long)b*NN*NN + (long)n*NN + m];
    float cs = v / (nrmD[b*NN + m] * nrmS[b*NN + n] + EPSF);
    outSD[t] = cs / (maxDS[b*NN + n] + EPSF);
    outDS[t] = cs / (maxSD[b*NN + m] + EPSF);
}

// both clouds: nbr conv input [knn_feats(C), rela(3), dist(1), pad(8)] stride 144
__global__ void k_build_nbr_f(const float* __restrict__ xyzS, const float* __restrict__ xyzD,
                              const float* __restrict__ dmatAll, const int* __restrict__ idxAll,
                              float* __restrict__ f) {
    int p = blockIdx.x;
    int cloud = p >= PP;
    int pl = p - cloud * PP;
    const float* xyz = cloud ? xyzD : xyzS;
    const float* dmatC = dmatAll + (long)cloud*BN*CC;
    int n = (pl / KK) & (NN - 1);
    int b = pl / (NN * KK);
    int m = idxAll[p];
    const float* dr = dmatC + ((long)b*NN + m) * CC;
    float* fo = f + (long)p * 144;
    int tid = threadIdx.x;
    fo[tid] = dr[tid];
    if (tid == 0) {
        long qb = ((long)b*NN + n) * 3, rb = ((long)b*NN + m) * 3;
        float rx = xyz[rb]-xyz[qb], ry = xyz[rb+1]-xyz[qb+1], rz = xyz[rb+2]-xyz[qb+2];
        fo[128] = rx; fo[129] = ry; fo[130] = rz; fo[131] = sqrtf(rx*rx+ry*ry+rz*rz);
        #pragma unroll
        for (int z = 132; z < 144; z++) fo[z] = 0.f;
    }
}

// both clouds: grid 2*BN, in-block affine from producer stats
__global__ void k_nbr_final(const float* __restrict__ yraw,
                            const float* __restrict__ affS, const float* __restrict__ affQ,
                            const float* __restrict__ gP, const float* __restrict__ bP, float invP,
                            const int* __restrict__ idxAll,
                            const float* __restrict__ dmatAll, float* __restrict__ outAll) {
    int gblk = blockIdx.x;
    int cloud = gblk >= BN;
    int bn = gblk - cloud * BN;
    const float* y = yraw + (long)cloud*PP*CC;
    const int* idx = idxAll + (long)cloud*PP;
    const float* dmat = dmatAll + (long)cloud*BN*CC;
    float* outN = outAll + (long)cloud*BN*CC;
    int tid = threadIdx.x;
    __shared__ float fe[KK][CC];
    __shared__ float mk[KK], wgt[KK];
    __shared__ int sid[KK];
    __shared__ float sSc[CC], sSh[CC];
    if (tid < CC) {
        int so = cloud * CC + tid;
        float mu  = affS[so] * invP;
        float var = fmaxf(affQ[so] * invP - mu * mu, 0.f);
        float s   = gP[tid] * rsqrtf(var + BNEPS);
        sSc[tid] = s;
        sSh[tid] = bP[tid] - mu * s;
    }
    if (tid < KK) sid[tid] = idx[(long)bn*KK + tid];
    __syncthreads();
    for (int t = tid; t < KK * CC; t += 256) {
        int k = t >> 7, c = t & 127;
        float v = y[((long)bn*KK + k) * CC + c];
        fe[k][c] = fmaxf(v * sSc[c] + sSh[c], 0.f);
    }
    __syncthreads();
    int w = tid >> 5, lane = tid & 31;
    for (int kk = w; kk < KK; kk += 8) {
        float mx = -3.4e38f;
        for (int c = lane; c < CC; c += 32) mx = fmaxf(mx, fe[kk][c]);
        #pragma unroll
        for (int o = 16; o > 0; o >>= 1) mx = fmaxf(mx, __shfl_down_sync(0xffffffffu, mx, o));
        if (lane == 0) mk[kk] = mx;
    }
    __syncthreads();
    if (tid == 0) {
        float m = -3.4e38f;
        for (int k = 0; k < KK; k++) m = fmaxf(m, mk[k]);
        float s = 0.f;
        for (int k = 0; k < KK; k++) { float e = expf(mk[k]-m); wgt[k] = e; s += e; }
        float r = 1.f / s;
        for (int k = 0; k < KK; k++) wgt[k] *= r;
    }
    __syncthreads();
    if (tid < CC) {
        int b = bn >> 11;
        float a = 0.f;
        #pragma unroll
        for (int k = 0; k < KK; k++) a += wgt[k] * dmat[((long)b*NN + sid[k]) * CC + tid];
        outN[(long)bn*CC + tid] = a;
    }
}

// main feats build (272 ch)
__global__ void k_build_feats(const float* __restrict__ src_xyz, const float* __restrict__ dst_xyz,
                              const float* __restrict__ srcd, const float* __restrict__ dstd,
                              const float* __restrict__ srcw, const float* __restrict__ dstw,
                              const float* __restrict__ sdc, const float* __restrict__ dsc,
                              const float* __restrict__ sdn, const float* __restrict__ dsn,
                              const int* __restrict__ idx, float* __restrict__ feats) {
    int p = blockIdx.x;
    int n = (p / KK) & (NN - 1);
    int b = p / (NN * KK);
    int m = idx[p];
    float* fo = feats + (long)p * 272;
    int tid = threadIdx.x;
    fo[10 + tid]  = srcd[((long)b*NN + n) * CC + tid];
    fo[138 + tid] = dstd[((long)b*NN + m) * CC + tid];
    if (tid == 0) {
        long qb = ((long)b*NN + n) * 3, rb = ((long)b*NN + m) * 3;
        float sx = src_xyz[qb], sy = src_xyz[qb+1], sz = src_xyz[qb+2];
        float kx = dst_xyz[rb], ky = dst_xyz[rb+1], kz = dst_xyz[rb+2];
        float rx = kx-sx, ry = ky-sy, rz = kz-sz;
        fo[0]=rx; fo[1]=ry; fo[2]=rz; fo[3]=sqrtf(rx*rx+ry*ry+rz*rz);
        fo[4]=sx; fo[5]=sy; fo[6]=sz; fo[7]=kx; fo[8]=ky; fo[9]=kz;
        fo[266]=srcw[b*NN+n]; fo[267]=dstw[b*NN+m];
        fo[268]=sdc[p]; fo[269]=dsc[p]; fo[270]=sdn[p]; fo[271]=dsn[p];
    }
}

__global__ void k_attention(const float* __restrict__ yraw,
                            const float* __restrict__ affS, const float* __restrict__ affQ,
                            const float* __restrict__ gP, const float* __restrict__ bP, float invP,
                            const int* __restrict__ idx, const float* __restrict__ dst_xyz,
                            float* __restrict__ outC, float* __restrict__ att) {
    int bn = blockIdx.x, tid = threadIdx.x;
    __shared__ float fe[KK][256];
    __shared__ float mk[KK], wgt[KK];
    __shared__ int sid[KK];
    if (tid < KK) sid[tid] = idx[(long)bn*KK + tid];
    float mu  = affS[tid] * invP;
    float var = fmaxf(affQ[tid] * invP - mu * mu, 0.f);
    float s   = gP[tid] * rsqrtf(var + BNEPS);
    float h   = bP[tid] - mu * s;
    #pragma unroll
    for (int k = 0; k < KK; k++) {
        float v = yraw[((long)bn*KK + k) * 256 + tid];
        fe[k][tid] = fmaxf(v * s + h, 0.f);
    }
    __syncthreads();
    int w = tid >> 5, lane = tid & 31;
    for (int kk = w; kk < KK; kk += 8) {
        float mx = -3.4e38f;
        for (int c = lane; c < 256; c += 32) mx = fmaxf(mx, fe[kk][c]);
        #pragma unroll
        for (int o = 16; o > 0; o >>= 1) mx = fmaxf(mx, __shfl_down_sync(0xffffffffu, mx, o));
        if (lane == 0) mk[kk] = mx;
    }
    __syncthreads();
    if (tid == 0) {
        float m = -3.4e38f;
        for (int k = 0; k < KK; k++) m = fmaxf(m, mk[k]);
        float ssum = 0.f;
        for (int k = 0; k < KK; k++) { float e = expf(mk[k]-m); wgt[k] = e; ssum += e; }
        float r = 1.f / ssum;
        for (int k = 0; k < KK; k++) wgt[k] *= r;
    }
    __syncthreads();
    float a = 0.f;
    #pragma unroll
    for (int k = 0; k < KK; k++) a += wgt[k] * fe[k][tid];
    att[(long)bn * 256 + tid] = a;
    if (tid < 3) {
        int b = bn >> 11;
        float cg = 0.f;
        #pragma unroll
        for (int k = 0; k < KK; k++)
            cg += wgt[k] * dst_xyz[((long)b*NN + sid[k]) * 3 + tid];
        outC[(long)bn * 3 + tid] = cg;
    }
}

__global__ void k_mlp3(const float* __restrict__ yraw,
                       const float* __restrict__ affS, const float* __restrict__ affQ,
                       const float* __restrict__ gP, const float* __restrict__ bP, float invP,
                       const float* __restrict__ w3, const float* __restrict__ b3,
                       float* __restrict__ outw) {
    int bn = blockIdx.x, tid = threadIdx.x;
    float mu  = affS[tid] * invP;
    float var = fmaxf(affQ[tid] * invP - mu * mu, 0.f);
    float s   = gP[tid] * rsqrtf(var + BNEPS);
    float h   = bP[tid] - mu * s;
    float v = fmaxf(yraw[(long)bn*256 + tid] * s + h, 0.f) * w3[tid];
    #pragma unroll
    for (int o = 16; o > 0; o >>= 1) v += __shfl_down_sync(0xffffffffu, v, o);
    __shared__ float ps[8];
    if ((tid & 31) == 0) ps[tid >> 5] = v;
    __syncthreads();
    if (tid == 0) {
        float s2 = 0.f;
        #pragma unroll
        for (int i = 0; i < 8; i++) s2 += ps[i];
        outw[bn] = 1.f / (1.f + expf(-(s2 + b3[0])));
    }
}

extern "C" void kernel_launch(void* const* d_in, const int* in_sizes, int n_in,
                              void* d_out, int out_size) {
    const float* src_xyz  = (const float*)d_in[0];
    const float* src_desc = (const float*)d_in[1];
    const float* dst_xyz  = (const float*)d_in[2];
    const float* dst_desc = (const float*)d_in[3];
    const float* src_w    = (const float*)d_in[4];
    const float* dst_w    = (const float*)d_in[5];
    const float* c1_W0 = (const float*)d_in[6];
    const float* c1_W  = (const float*)d_in[7];
    const float* c1_g  = (const float*)d_in[8];
    const float* c1_b  = (const float*)d_in[9];
    const float* c2_W0 = (const float*)d_in[10];
    const float* c2_W  = (const float*)d_in[11];
    const float* c2_g  = (const float*)d_in[12];
    const float* c2_b  = (const float*)d_in[13];
    const float* m1_W  = (const float*)d_in[14];
    const float* m1_g  = (const float*)d_in[16];
    const float* m1_b  = (const float*)d_in[17];
    const float* m2_W  = (const float*)d_in[18];
    const float* m2_g  = (const float*)d_in[20];
    const float* m2_b  = (const float*)d_in[21];
    const float* m3_W  = (const float*)d_in[22];
    const float* m3_b  = (const float*)d_in[23];

    float* base = nullptr;
    cudaGetSymbolAddress((void**)&base, g_pool);
    float* srcd   = base + F_SRCD;
    float* dstd   = base + F_DSTD;
    float* nsqS   = base + F_NSQS;
    float* nsqD   = base + F_NSQD;
    float* nrmS   = base + F_NRMS;
    float* nrmD   = base + F_NRMD;
    float* maxDS  = base + F_MAXDS;
    float* maxSD  = base + F_MAXSD;
    float* nrm2S  = base + F_NRM2S;
    float* nrm2D  = base + F_NRM2D;
    float* sdc    = base + F_SDC;
    float* dsc    = base + F_DSC;
    float* sdn    = base + F_SDN;
    float* dsn    = base + F_DSN;
    float* stat0  = base + F_STATS;
    float* w2p    = base + F_W2P;
    int*   idx    = (int*)(base + F_IDX);
    int*   sidx   = (int*)(base + F_SIDX);
    float* att    = base + F_ATT;
    float* mb1    = base + F_MB1;
    float* mb2    = base + F_MB2;
    float* srcnbr = base + F_SRCNBR;
    float* inner  = base + F_INNER;
    float* fbuf   = base + F_F;
    float* y0     = base + F_Y0;
    float* y1     = base + F_Y1;
    float* outC   = (float*)d_out;
    float* outW   = (float*)d_out + (long)BB*NN*3;

    auto slot = [&](int i) { return stat0 + (long)i * 1024; };
    const float invPP = 1.f / (float)PP;
    const float invBN = 1.f / (float)BN;

    k_fill<<<32, 256>>>(stat0, 0.f, 8 * 1024);
    k_pad_w<<<128, 144>>>(c2_W0, w2p);

    // A: transpose + norms
    k_transpose_norm<<<dim3(BN, 2), 128>>>(src_desc, dst_desc, srcd, nsqS, nrmS);

    // inner = src . dst with fused cosine maxes
    k_fill<<<32, 256>>>(maxDS, -3.4e38f, 2*BN);
    k_gemm_sim<<<dim3(NN/SGN, NN/SGM, 2), 256>>>(srcd, dstd, inner, nrmS, nrmD, maxDS, maxSD);
    k_knn_desc<<<dim3(NN, BB), 256>>>(inner, nsqS, nsqD, idx);
    k_simgather<<<PP/256, 256>>>(inner, nrmS, nrmD, maxDS, maxSD, idx, sdc, dsc);

    // B: neighborhood descriptors — both clouds batched
    k_knn_xyz<<<dim3(NN, BB, 2), 256>>>(src_xyz, dst_xyz, sidx);
    k_build_nbr_f<<<2*PP, 128>>>(src_xyz, dst_xyz, srcd, sidx, fbuf);
    const float* c2W1 = c2_W;
    const float* c2W2 = c2_W + CC*CC;
    k_gemm_tc<<<dim3(CC/TCN, (2*PP)/TCM), 256>>>(fbuf, w2p, y0, 2*PP, CC, 144,
        nullptr, nullptr, nullptr, nullptr, 0.f, slot(0), slot(0)+512, PP);
    k_gemm_tc<<<dim3(CC/TCN, (2*PP)/TCM), 256>>>(y0, c2W1, y1, 2*PP, CC, CC,
        slot(0), slot(0)+512, c2_g, c2_b, invPP, slot(1), slot(1)+512, PP);
    k_gemm_tc<<<dim3(CC/TCN, (2*PP)/TCM), 256>>>(y1, c2W2, y0, 2*PP, CC, CC,
        slot(1), slot(1)+512, c2_g + CC, c2_b + CC, invPP, slot(2), slot(2)+512, PP);
    k_nbr_final<<<2*BN, 256>>>(y0, slot(2), slot(2)+512, c2_g + 2*CC, c2_b + 2*CC, invPP,
                               sidx, srcd, srcnbr);

    // nbr cosine sims
    k_rownorm<<<2*BN, 128>>>(srcnbr, nrm2S);
    k_fill<<<32, 256>>>(maxDS, -3.4e38f, 2*BN);
    k_gemm_sim<<<dim3(NN/SGN, NN/SGM, 2), 256>>>(srcnbr, srcnbr + (long)BN*CC, inner,
                                                 nrm2S, nrm2D, maxDS, maxSD);
    k_simgather<<<PP/256, 256>>>(inner, nrm2S, nrm2D, maxDS, maxSD, idx, sdn, dsn);

    // C: main feature conv + attention
    k_build_feats<<<PP, 128>>>(src_xyz, dst_xyz, srcd, dstd, src_w, dst_w,
                               sdc, dsc, sdn, dsn, idx, fbuf);
    const float* c1W1 = c1_W;
    const float* c1W2 = c1_W + 256*256;
    k_gemm_tc<<<dim3(256/TCN, PP/TCM), 256>>>(fbuf, c1_W0, y0, PP, 256, 272,
        nullptr, nullptr, nullptr, nullptr, 0.f, slot(3), slot(3)+512, 0);
    k_gemm_tc<<<dim3(256/TCN, PP/TCM), 256>>>(y0, c1W1, y1, PP, 256, 256,
        slot(3), slot(3)+512, c1_g, c1_b, invPP, slot(4), slot(4)+512, 0);
    k_gemm_tc<<<dim3(256/TCN, PP/TCM), 256>>>(y1, c1W2, y0, PP, 256, 256,
        slot(4), slot(4)+512, c1_g + 256, c1_b + 256, invPP, slot(5), slot(5)+512, 0);
    k_attention<<<BN, 256>>>(y0, slot(5), slot(5)+512, c1_g + 512, c1_b + 512, invPP,
                             idx, dst_xyz, outC, att);

    // D: MLP head
    k_gemm_tc<<<dim3(256/TCN, BN/TCM), 256>>>(att, m1_W, mb1, BN, 256, 256,
        nullptr, nullptr, nullptr, nullptr, 0.f, slot(6), slot(6)+512, 0);
    k_gemm_tc<<<dim3(256/TCN, BN/TCM), 256>>>(mb1, m2_W, mb2, BN, 256, 256,
        slot(6), slot(6)+512, m1_g, m1_b, invBN, slot(7), slot(7)+512, 0);
    k_mlp3<<<BN, 256>>>(mb2, slot(7), slot(7)+512, m2_g, m2_b, invBN, m3_W, m3_b, outW);
}

// round 12
// speedup vs baseline: 1.4494x; 1.0733x over previous
#include <cuda_runtime.h>
#include <mma.h>
#include <math.h>
#include <float.h>

using namespace nvcuda;

#define BB 2
#define NN 2048
#define CC 128
#define KK 16
#define BN (BB*NN)
#define PP (BB*NN*KK)
#define EPSF 1e-6f
#define BNEPS 1e-5f

// ---------------- scratch pool ----------------
constexpr long F_SRCD   = 0;
constexpr long F_DSTD   = F_SRCD   + (long)BN*CC;
constexpr long F_NSQS   = F_DSTD   + (long)BN*CC;
constexpr long F_NSQD   = F_NSQS   + BN;
constexpr long F_NRMS   = F_NSQD   + BN;
constexpr long F_NRMD   = F_NRMS   + BN;
constexpr long F_MAXDS  = F_NRMD   + BN;
constexpr long F_MAXSD  = F_MAXDS  + BN;
constexpr long F_NRM2S  = F_MAXSD  + BN;
constexpr long F_NRM2D  = F_NRM2S  + BN;
constexpr long F_SDC    = F_NRM2D  + BN;
constexpr long F_DSC    = F_SDC    + PP;
constexpr long F_SDN    = F_DSC    + PP;
constexpr long F_DSN    = F_SDN    + PP;
constexpr long F_STATS  = F_DSN    + PP;            // 8 slots x 1024 (S at +0, Q at +512)
constexpr long F_W2P    = F_STATS  + 8*1024;        // padded c2_W0 [128][144]
constexpr long F_IDX    = F_W2P    + 128*144;       // int
constexpr long F_SIDX   = F_IDX    + PP;
constexpr long F_DIDX   = F_SIDX   + PP;
constexpr long F_ATT    = F_DIDX   + PP;
constexpr long F_MB1    = F_ATT    + (long)BN*256;
constexpr long F_MB2    = F_MB1    + (long)BN*256;
constexpr long F_SRCNBR = F_MB2    + (long)BN*256;
constexpr long F_DSTNBR = F_SRCNBR + (long)BN*CC;
constexpr long F_INNER  = F_DSTNBR + (long)BN*CC;
constexpr long F_F      = F_INNER  + (long)BB*NN*NN;
constexpr long F_FSZ    = (long)2*PP*144;           // max(PP*272, 2PP*144)
constexpr long F_Y0     = F_F      + F_FSZ;
constexpr long F_Y1     = F_Y0     + (long)PP*256;
constexpr long F_END    = F_Y1     + (long)PP*256;

__device__ __align__(128) float g_pool[F_END];

__device__ __forceinline__ void atomicMaxF(float* a, float v) {
    if (!(v < 0.f)) atomicMax((int*)a, __float_as_int(v));
    else            atomicMin((unsigned int*)a, __float_as_uint(v));
}

__device__ __forceinline__ unsigned cvt_tf32(float x) {
    unsigned u;
    asm("cvt.rn.tf32.f32 %0, %1;" : "=r"(u) : "f"(x));
    return u;
}

__device__ __forceinline__ void cp_async16(unsigned saddr, const void* gptr) {
    asm volatile("cp.async.ca.shared.global [%0], [%1], 16;" :: "r"(saddr), "l"(gptr));
}
__device__ __forceinline__ void cp_commit() { asm volatile("cp.async.commit_group;"); }
template<int N> __device__ __forceinline__ void cp_wait() {
    asm volatile("cp.async.wait_group %0;" :: "n"(N));
}

__global__ void k_fill(float* __restrict__ p, float v, int n) {
    int i = blockIdx.x * blockDim.x + threadIdx.x;
    if (i < n) p[i] = v;
}

__global__ void k_pad_w(const float* __restrict__ W, float* __restrict__ Wp) {
    int o = blockIdx.x; int k = threadIdx.x; // 144 threads
    Wp[o * 144 + k] = (k < 132) ? W[o * 132 + k] : 0.f;
}

// both clouds: [B,C,N] -> [B,N,C] plus |.|^2 and |.|
__global__ void k_transpose_norm(const float* __restrict__ descS, const float* __restrict__ descD,
                                 float* __restrict__ dmatAll, float* __restrict__ nsqAll,
                                 float* __restrict__ nrmAll) {
    int cloud = blockIdx.y;
    const float* desc = cloud ? descD : descS;
    float* dmat = dmatAll + (long)cloud*BN*CC;
    float* nsq  = nsqAll  + cloud*BN;
    float* nrm  = nrmAll  + cloud*BN;
    int bn = blockIdx.x; int b = bn >> 11; int n = bn & (NN - 1);
    int c = threadIdx.x;
    float v = desc[((long)b*CC + c)*NN + n];
    dmat[(long)bn*CC + c] = v;
    float s = v * v;
    #pragma unroll
    for (int o = 16; o > 0; o >>= 1) s += __shfl_down_sync(0xffffffffu, s, o);
    __shared__ float ps[4];
    if ((c & 31) == 0) ps[c >> 5] = s;
    __syncthreads();
    if (c == 0) { float t = ps[0]+ps[1]+ps[2]+ps[3]; nsq[bn] = t; nrm[bn] = sqrtf(t); }
}

__global__ void k_rownorm(const float* __restrict__ dmat, float* __restrict__ nrm) {
    int bn = blockIdx.x; int c = threadIdx.x;
    float v = dmat[(long)bn*CC + c];
    float s = v * v;
    #pragma unroll
    for (int o = 16; o > 0; o >>= 1) s += __shfl_down_sync(0xffffffffu, s, o);
    __shared__ float ps[4];
    if ((c & 31) == 0) ps[c >> 5] = s;
    __syncthreads();
    if (c == 0) nrm[bn] = sqrtf(ps[0]+ps[1]+ps[2]+ps[3]);
}

// ---------------- split-tf32 sim GEMM v2: PTX mma + cp.async, reg-side hi/lo ----------
// inner[b][n][m] = A(n).B(m); fused maxDS/maxSD. Block 128x64, warp tile 32x32.
#define SGM 128
#define SGN 64
#define SLD 20
#define SCLD 68

__global__ __launch_bounds__(256, 3)
void k_gemm_sim(const float* __restrict__ A, const float* __restrict__ Bm,
                float* __restrict__ Cm,
                const float* __restrict__ nrmA, const float* __restrict__ nrmB,
                float* __restrict__ maxDS, float* __restrict__ maxSD) {
    const int b = blockIdx.z;
    A  += (long)b * NN * CC;
    Bm += (long)b * NN * CC;
    Cm += (long)b * NN * NN;

    __shared__ __align__(16) float smem[SGM * SCLD];   // union staging / C
    float* Ab[2] = { smem,                 smem + SGM*SLD };
    float* Bb[2] = { smem + 2*SGM*SLD,     smem + 2*SGM*SLD + SGN*SLD };
    float* Csm = smem;
    __shared__ float rns[SGM], rnd[SGN], rm[SGM], cmx[SGN];

    const int tid = threadIdx.x;
    const int lane = tid & 31;
    const int g   = lane >> 2;
    const int tig = lane & 3;
    const int wid = tid >> 5;
    const int wm = wid & 3;
    const int wn = wid >> 2;
    const long rowBase = (long)blockIdx.y * SGM;
    const int colBase = blockIdx.x * SGN;

    if (tid < SGM) { rns[tid] = nrmA[b*NN + rowBase + tid]; rm[tid] = -3.4e38f; }
    if (tid < SGN) { rnd[tid] = nrmB[b*NN + colBase + tid]; cmx[tid] = -3.4e38f; }

    const int srow = tid >> 2;
    const int kq = (tid & 3) * 4;
    unsigned sbase;
    asm("{ .reg .u64 t; cvta.to.shared.u64 t, %1; cvt.u32.u64 %0, t; }"
        : "=r"(sbase) : "l"(smem));

    auto issue = [&](int kc, int buf) {
        int k0 = kc * 16;
        const float* ga0 = &A[(rowBase + srow) * CC + k0 + kq];
        const float* ga1 = &A[(rowBase + srow + 64) * CC + k0 + kq];
        const float* gb  = &Bm[(long)(colBase + srow) * CC + k0 + kq];
        unsigned da0 = sbase + (unsigned)(((Ab[buf] - smem) + srow * SLD + kq) * 4);
        unsigned da1 = da0 + 64u * SLD * 4u;
        unsigned db  = sbase + (unsigned)(((Bb[buf] - smem) + srow * SLD + kq) * 4);
        cp_async16(da0, ga0);
        cp_async16(da1, ga1);
        cp_async16(db, gb);
        cp_commit();
    };

    float acc[2][4][4];
    #pragma unroll
    for (int i = 0; i < 2; i++)
        #pragma unroll
        for (int j = 0; j < 4; j++)
            #pragma unroll
            for (int t = 0; t < 4; t++)
                acc[i][j][t] = 0.f;

    const int nk = CC / 16;
    issue(0, 0);

    for (int kc = 0; kc < nk; kc++) {
        const int cur = kc & 1;
        const bool more = (kc + 1 < nk);
        if (more) { issue(kc + 1, cur ^ 1); cp_wait<1>(); }
        else      { cp_wait<0>(); }
        __syncthreads();

        const float* As = Ab[cur];
        const float* Bs = Bb[cur];
        #pragma unroll
        for (int ks = 0; ks < 2; ks++) {
            const int kb = ks * 8;
            // B fragments (raw -> hi/lo in regs): 4 n8 tiles x 2 k-halves
            unsigned bh0[4], bh1[4], bl0[4], bl1[4];
            #pragma unroll
            for (int nj = 0; nj < 4; nj++) {
                int nb = wn * 32 + nj * 8 + g;
                float w0 = Bs[nb * SLD + kb + tig];
                float w1 = Bs[nb * SLD + kb + tig + 4];
                unsigned h0 = cvt_tf32(w0), h1 = cvt_tf32(w1);
                bh0[nj] = h0; bh1[nj] = h1;
                bl0[nj] = cvt_tf32(w0 - __uint_as_float(h0));
                bl1[nj] = cvt_tf32(w1 - __uint_as_float(h1));
            }
            #pragma unroll
            for (int mi = 0; mi < 2; mi++) {
                int ar = wm * 32 + mi * 16;
                float v0 = As[(ar + g    ) * SLD + kb + tig];
                float v1 = As[(ar + g + 8) * SLD + kb + tig];
                float v2 = As[(ar + g    ) * SLD + kb + tig + 4];
                float v3 = As[(ar + g + 8) * SLD + kb + tig + 4];
                unsigned ah0 = cvt_tf32(v0), ah1 = cvt_tf32(v1);
                unsigned ah2 = cvt_tf32(v2), ah3 = cvt_tf32(v3);
                unsigned al0 = cvt_tf32(v0 - __uint_as_float(ah0));
                unsigned al1 = cvt_tf32(v1 - __uint_as_float(ah1));
                unsigned al2 = cvt_tf32(v2 - __uint_as_float(ah2));
                unsigned al3 = cvt_tf32(v3 - __uint_as_float(ah3));
                #pragma unroll
                for (int nj = 0; nj < 4; nj++) {
                    asm volatile(
                        "mma.sync.aligned.m16n8k8.row.col.f32.tf32.tf32.f32 "
                        "{%0,%1,%2,%3}, {%4,%5,%6,%7}, {%8,%9}, {%0,%1,%2,%3};"
                        : "+f"(acc[mi][nj][0]), "+f"(acc[mi][nj][1]),
                          "+f"(acc[mi][nj][2]), "+f"(acc[mi][nj][3])
                        : "r"(ah0), "r"(ah1), "r"(ah2), "r"(ah3),
                          "r"(bh0[nj]), "r"(bh1[nj]));
                    asm volatile(
                        "mma.sync.aligned.m16n8k8.row.col.f32.tf32.tf32.f32 "
                        "{%0,%1,%2,%3}, {%4,%5,%6,%7}, {%8,%9}, {%0,%1,%2,%3};"
                        : "+f"(acc[mi][nj][0]), "+f"(acc[mi][nj][1]),
                          "+f"(acc[mi][nj][2]), "+f"(acc[mi][nj][3])
                        : "r"(ah0), "r"(ah1), "r"(ah2), "r"(ah3),
                          "r"(bl0[nj]), "r"(bl1[nj]));
                    asm volatile(
                        "mma.sync.aligned.m16n8k8.row.col.f32.tf32.tf32.f32 "
                        "{%0,%1,%2,%3}, {%4,%5,%6,%7}, {%8,%9}, {%0,%1,%2,%3};"
                        : "+f"(acc[mi][nj][0]), "+f"(acc[mi][nj][1]),
                          "+f"(acc[mi][nj][2]), "+f"(acc[mi][nj][3])
                        : "r"(al0), "r"(al1), "r"(al2), "r"(al3),
                          "r"(bh0[nj]), "r"(bh1[nj]));
                }
            }
        }
        __syncthreads();
    }

    // acc -> Csm (documented mma layout), then store + fused cosine maxes
    #pragma unroll
    for (int mi = 0; mi < 2; mi++) {
        int r0r = wm * 32 + mi * 16 + g;
        #pragma unroll
        for (int nj = 0; nj < 4; nj++) {
            int c0 = wn * 32 + nj * 8 + 2 * tig;
            Csm[r0r * SCLD + c0]           = acc[mi][nj][0];
            Csm[r0r * SCLD + c0 + 1]       = acc[mi][nj][1];
            Csm[(r0r + 8) * SCLD + c0]     = acc[mi][nj][2];
            Csm[(r0r + 8) * SCLD + c0 + 1] = acc[mi][nj][3];
        }
    }
    __syncthreads();

    const int ccol = tid & 63;
    const int r0 = tid >> 6;
    const float nd = rnd[ccol];
    float colmax = -3.4e38f;
    #pragma unroll 8
    for (int it = 0; it < 32; it++) {
        int r = r0 + it * 4;
        float v = Csm[r * SCLD + ccol];
        Cm[(rowBase + r) * NN + colBase + ccol] = v;
        float csv = v / (nd * rns[r] + EPSF);
        colmax = fmaxf(colmax, csv);
        float wmx = csv;
        #pragma unroll
        for (int o = 16; o > 0; o >>= 1) wmx = fmaxf(wmx, __shfl_down_sync(0xffffffffu, wmx, o));
        if (lane == 0) atomicMaxF(&rm[r], wmx);
    }
    atomicMaxF(&cmx[ccol], colmax);
    __syncthreads();
    if (tid < SGM) atomicMaxF(&maxDS[b*NN + rowBase + tid], rm[tid]);
    else if (tid < SGM + SGN) atomicMaxF(&maxSD[b*NN + colBase + (tid - SGM)], cmx[tid - SGM]);
}

// ---------------- TF32 TC GEMM v3 (unchanged from 1180us kernel) ----------
#define TCM 128
#define TCN 64
#define ALD 20
#define CLD 68

__global__ __launch_bounds__(256, 3)
void k_gemm_tc(const float* __restrict__ A, const float* __restrict__ Bm,
               float* __restrict__ Cm, int P, int O, int Kd,
               const float* __restrict__ affS, const float* __restrict__ affQ,
               const float* __restrict__ gP, const float* __restrict__ bP, float invP,
               float* __restrict__ statS, float* __restrict__ statQ, int splitRows) {
    __shared__ __align__(16) float smem[TCM * CLD];
    float* Ab[2] = { smem,                    smem + TCM*ALD };
    float* Bb[2] = { smem + 2*TCM*ALD,        smem + 2*TCM*ALD + TCN*ALD };
    float* Csm = smem;
    __shared__ float cs[TCN], cq[TCN];
    __shared__ float sSc[256], sSh[256];

    const int tid = threadIdx.x;
    const int lane = tid & 31;
    const int g   = lane >> 2;
    const int tig = lane & 3;
    const int wid = tid >> 5;
    const int wm = wid & 3;
    const int wn = wid >> 2;
    const int rowBase = blockIdx.y * TCM;
    const int colBase = blockIdx.x * TCN;
    const bool aff = (affS != nullptr);
    const bool stats = (statS != nullptr);
    const int cloudA = (splitRows > 0 && rowBase >= splitRows) ? 1 : 0;
    const int statOff = cloudA * O;

    if (aff && tid < Kd && tid < 256) {
        int so = cloudA * Kd + tid;
        float mu  = affS[so] * invP;
        float var = fmaxf(affQ[so] * invP - mu * mu, 0.f);
        float s   = gP[tid] * rsqrtf(var + BNEPS);
        sSc[tid] = s;
        sSh[tid] = bP[tid] - mu * s;
    }
    if (stats && tid < TCN) { cs[tid] = 0.f; cq[tid] = 0.f; }

    const int srow = tid >> 2;
    const int kq = (tid & 3) * 4;
    unsigned sbase;
    asm("{ .reg .u64 t; cvta.to.shared.u64 t, %1; cvt.u32.u64 %0, t; }"
        : "=r"(sbase) : "l"(smem));

    auto issue = [&](int kc, int buf) {
        int k0 = kc * 16;
        const float* ga0 = &A[(long)(rowBase + srow) * Kd + k0 + kq];
        const float* ga1 = &A[(long)(rowBase + srow + 64) * Kd + k0 + kq];
        const float* gb  = &Bm[(long)(colBase + srow) * Kd + k0 + kq];
        unsigned da0 = sbase + (unsigned)(((Ab[buf] - smem) + srow * ALD + kq) * 4);
        unsigned da1 = da0 + 64u * ALD * 4u;
        unsigned db  = sbase + (unsigned)(((Bb[buf] - smem) + srow * ALD + kq) * 4);
        cp_async16(da0, ga0);
        cp_async16(da1, ga1);
        cp_async16(db, gb);
        cp_commit();
    };

    float acc[2][4][4];
    #pragma unroll
    for (int i = 0; i < 2; i++)
        #pragma unroll
        for (int j = 0; j < 4; j++)
            #pragma unroll
            for (int t = 0; t < 4; t++)
                acc[i][j][t] = 0.f;

    const int nk = Kd / 16;
    issue(0, 0);

    for (int kc = 0; kc < nk; kc++) {
        const int cur = kc & 1;
        const bool more = (kc + 1 < nk);
        if (more) { issue(kc + 1, cur ^ 1); cp_wait<1>(); }
        else      { cp_wait<0>(); }
        __syncthreads();

        const float* As = Ab[cur];
        const float* Bs = Bb[cur];
        const int k0 = kc * 16;
        #pragma unroll
        for (int ks = 0; ks < 2; ks++) {
            const int kb = ks * 8;
            float sc0 = 1.f, sh0 = 0.f, sc4 = 1.f, sh4 = 0.f;
            if (aff) {
                sc0 = sSc[k0 + kb + tig];     sh0 = sSh[k0 + kb + tig];
                sc4 = sSc[k0 + kb + tig + 4]; sh4 = sSh[k0 + kb + tig + 4];
            }
            unsigned b0[4], b1[4];
            #pragma unroll
            for (int nj = 0; nj < 4; nj++) {
                int nb = wn * 32 + nj * 8 + g;
                b0[nj] = cvt_tf32(Bs[nb * ALD + kb + tig]);
                b1[nj] = cvt_tf32(Bs[nb * ALD + kb + tig + 4]);
            }
            #pragma unroll
            for (int mi = 0; mi < 2; mi++) {
                int ar = wm * 32 + mi * 16;
                float v0 = As[(ar + g    ) * ALD + kb + tig];
                float v1 = As[(ar + g + 8) * ALD + kb + tig];
                float v2 = As[(ar + g    ) * ALD + kb + tig + 4];
                float v3 = As[(ar + g + 8) * ALD + kb + tig + 4];
                if (aff) {
                    v0 = fmaxf(v0 * sc0 + sh0, 0.f);
                    v1 = fmaxf(v1 * sc0 + sh0, 0.f);
                    v2 = fmaxf(v2 * sc4 + sh4, 0.f);
                    v3 = fmaxf(v3 * sc4 + sh4, 0.f);
                }
                unsigned a0 = cvt_tf32(v0), a1 = cvt_tf32(v1);
                unsigned a2 = cvt_tf32(v2), a3 = cvt_tf32(v3);
                #pragma unroll
                for (int nj = 0; nj < 4; nj++) {
                    asm volatile(
                        "mma.sync.aligned.m16n8k8.row.col.f32.tf32.tf32.f32 "
                        "{%0,%1,%2,%3}, {%4,%5,%6,%7}, {%8,%9}, {%0,%1,%2,%3};"
                        : "+f"(acc[mi][nj][0]), "+f"(acc[mi][nj][1]),
                          "+f"(acc[mi][nj][2]), "+f"(acc[mi][nj][3])
                        : "r"(a0), "r"(a1), "r"(a2), "r"(a3),
                          "r"(b0[nj]), "r"(b1[nj]));
                }
            }
        }
        __syncthreads();
    }

    #pragma unroll
    for (int mi = 0; mi < 2; mi++) {
        int r0r = wm * 32 + mi * 16 + g;
        #pragma unroll
        for (int nj = 0; nj < 4; nj++) {
            int c0 = wn * 32 + nj * 8 + 2 * tig;
            Csm[r0r * CLD + c0]           = acc[mi][nj][0];
            Csm[r0r * CLD + c0 + 1]       = acc[mi][nj][1];
            Csm[(r0r + 8) * CLD + c0]     = acc[mi][nj][2];
            Csm[(r0r + 8) * CLD + c0 + 1] = acc[mi][nj][3];
        }
    }
    __syncthreads();

    const int ccol = tid & 63;
    const int r0 = tid >> 6;
    float s = 0.f, q = 0.f;
    #pragma unroll 8
    for (int it = 0; it < 32; it++) {
        int r = r0 + it * 4;
        float v = Csm[r * CLD + ccol];
        Cm[(long)(rowBase + r) * O + colBase + ccol] = v;
        s += v; q += v * v;
    }
    if (stats) {
        atomicAdd(&cs[ccol], s);
        atomicAdd(&cq[ccol], q);
        __syncthreads();
        if (tid < TCN) {
            atomicAdd(&statS[statOff + colBase + tid], cs[tid]);
            atomicAdd(&statQ[statOff + colBase + tid], cq[tid]);
        }
    }
}

// top-16 smallest from shared d2[NN], 256 threads
__device__ void select_topk(float* d2, int* outIdx) {
    __shared__ float rv[8];
    __shared__ int   ri[8];
    int tid = threadIdx.x, lane = tid & 31, w = tid >> 5;
    for (int kk = 0; kk < KK; kk++) {
        float best = 3.4e38f; int bi = 0;
        for (int m = tid; m < NN; m += 256) {
            float v = d2[m];
            if (v < best) { best = v; bi = m; }
        }
        #pragma unroll
        for (int o = 16; o > 0; o >>= 1) {
            float ov = __shfl_down_sync(0xffffffffu, best, o);
            int   oi = __shfl_down_sync(0xffffffffu, bi, o);
            if (ov < best || (ov == best && oi < bi)) { best = ov; bi = oi; }
        }
        if (lane == 0) { rv[w] = best; ri[w] = bi; }
        __syncthreads();
        if (tid == 0) {
            float bv = rv[0]; int bj = ri[0];
            #pragma unroll
            for (int i = 1; i < 8; i++)
                if (rv[i] < bv || (rv[i] == bv && ri[i] < bj)) { bv = rv[i]; bj = ri[i]; }
            outIdx[kk] = bj;
            d2[bj] = 3.4e38f;
        }
        __syncthreads();
    }
}

__global__ void k_knn_desc(const float* __restrict__ inner, const float* __restrict__ nsqS,
                           const float* __restrict__ nsqD, int* __restrict__ idxOut) {
    int n = blockIdx.x, b = blockIdx.y;
    __shared__ float d2[NN];
    const float* row = inner + (long)b*NN*NN + (long)n*NN;
    float q = nsqS[b*NN + n];
    for (int m = threadIdx.x; m < NN; m += 256) d2[m] = q + nsqD[b*NN + m] - 2.f * row[m];
    __syncthreads();
    select_topk(d2, idxOut + ((long)b*NN + n) * KK);
}

__global__ void k_knn_xyz(const float* __restrict__ xyzS, const float* __restrict__ xyzD,
                          int* __restrict__ idxAll) {
    int n = blockIdx.x, b = blockIdx.y, cloud = blockIdx.z;
    const float* xyz = cloud ? xyzD : xyzS;
    int* idxOut = idxAll + (long)cloud*PP;
    __shared__ float d2[NN];
    long base = (long)b * NN * 3;
    float qx = xyz[base + (long)n*3], qy = xyz[base + (long)n*3+1], qz = xyz[base + (long)n*3+2];
    float qq = qx*qx + qy*qy + qz*qz;
    for (int m = threadIdx.x; m < NN; m += 256) {
        float rx = xyz[base + (long)m*3], ry = xyz[base + (long)m*3+1], rz = xyz[base + (long)m*3+2];
        d2[m] = qq + rx*rx + ry*ry + rz*rz - 2.f*(qx*rx + qy*ry + qz*rz);
    }
    __syncthreads();
    select_topk(d2, idxOut + ((long)b*NN + n) * KK);
}

__global__ void k_simgather(const float* __restrict__ inner, const float* __restrict__ nrmS,
                            const float* __restrict__ nrmD, const float* __restrict__ maxDS,
                            const float* __restrict__ maxSD, const int* __restrict__ idx,
                            float* __restrict__ outSD, float* __restrict__ outDS) {
    int t = blockIdx.x * 256 + threadIdx.x;
    if (t >= PP) return;
    int b = t / (NN * KK);
    int n = (t / KK) & (NN - 1);
    int m = idx[t];
    float v  = inner[(long)b*NN*NN + (long)n*NN + m];
    float cs = v / (nrmD[b*NN + m] * nrmS[b*NN + n] + EPSF);
    outSD[t] = cs / (maxDS[b*NN + n] + EPSF);
    outDS[t] = cs / (maxSD[b*NN + m] + EPSF);
}

// both clouds: nbr conv input [knn_feats(C), rela(3), dist(1), pad(8)] stride 144
__global__ void k_build_nbr_f(const float* __restrict__ xyzS, const float* __restrict__ xyzD,
                              const float* __restrict__ dmatAll, const int* __restrict__ idxAll,
                              float* __restrict__ f) {
    int p = blockIdx.x;
    int cloud = p >= PP;
    int pl = p - cloud * PP;
    const float* xyz = cloud ? xyzD : xyzS;
    const float* dmatC = dmatAll + (long)cloud*BN*CC;
    int n = (pl / KK) & (NN - 1);
    int b = pl / (NN * KK);
    int m = idxAll[p];
    const float* dr = dmatC + ((long)b*NN + m) * CC;
    float* fo = f + (long)p * 144;
    int tid = threadIdx.x;
    fo[tid] = dr[tid];
    if (tid == 0) {
        long qb = ((long)b*NN + n) * 3, rb = ((long)b*NN + m) * 3;
        float rx = xyz[rb]-xyz[qb], ry = xyz[rb+1]-xyz[qb+1], rz = xyz[rb+2]-xyz[qb+2];
        fo[128] = rx; fo[129] = ry; fo[130] = rz; fo[131] = sqrtf(rx*rx+ry*ry+rz*rz);
        #pragma unroll
        for (int z = 132; z < 144; z++) fo[z] = 0.f;
    }
}

// both clouds: grid 2*BN, in-block affine from producer stats
__global__ void k_nbr_final(const float* __restrict__ yraw,
                            const float* __restrict__ affS, const float* __restrict__ affQ,
                            const float* __restrict__ gP, const float* __restrict__ bP, float invP,
                            const int* __restrict__ idxAll,
                            const float* __restrict__ dmatAll, float* __restrict__ outAll) {
    int gblk = blockIdx.x;
    int cloud = gblk >= BN;
    int bn = gblk - cloud * BN;
    const float* y = yraw + (long)cloud*PP*CC;
    const int* idx = idxAll + (long)cloud*PP;
    const float* dmat = dmatAll + (long)cloud*BN*CC;
    float* outN = outAll + (long)cloud*BN*CC;
    int tid = threadIdx.x;
    __shared__ float fe[KK][CC];
    __shared__ float mk[KK], wgt[KK];
    __shared__ int sid[KK];
    __shared__ float sSc[CC], sSh[CC];
    if (tid < CC) {
        int so = cloud * CC + tid;
        float mu  = affS[so] * invP;
        float var = fmaxf(affQ[so] * invP - mu * mu, 0.f);
        float s   = gP[tid] * rsqrtf(var + BNEPS);
        sSc[tid] = s;
        sSh[tid] = bP[tid] - mu * s;
    }
    if (tid < KK) sid[tid] = idx[(long)bn*KK + tid];
    __syncthreads();
    for (int t = tid; t < KK * CC; t += 256) {
        int k = t >> 7, c = t & 127;
        float v = y[((long)bn*KK + k) * CC + c];
        fe[k][c] = fmaxf(v * sSc[c] + sSh[c], 0.f);
    }
    __syncthreads();
    int w = tid >> 5, lane = tid & 31;
    for (int kk = w; kk < KK; kk += 8) {
        float mx = -3.4e38f;
        for (int c = lane; c < CC; c += 32) mx = fmaxf(mx, fe[kk][c]);
        #pragma unroll
        for (int o = 16; o > 0; o >>= 1) mx = fmaxf(mx, __shfl_down_sync(0xffffffffu, mx, o));
        if (lane == 0) mk[kk] = mx;
    }
    __syncthreads();
    if (tid == 0) {
        float m = -3.4e38f;
        for (int k = 0; k < KK; k++) m = fmaxf(m, mk[k]);
        float s = 0.f;
        for (int k = 0; k < KK; k++) { float e = expf(mk[k]-m); wgt[k] = e; s += e; }
        float r = 1.f / s;
        for (int k = 0; k < KK; k++) wgt[k] *= r;
    }
    __syncthreads();
    if (tid < CC) {
        int b = bn >> 11;
        float a = 0.f;
        #pragma unroll
        for (int k = 0; k < KK; k++) a += wgt[k] * dmat[((long)b*NN + sid[k]) * CC + tid];
        outN[(long)bn*CC + tid] = a;
    }
}

// main feats build (272 ch)
__global__ void k_build_feats(const float* __restrict__ src_xyz, const float* __restrict__ dst_xyz,
                              const float* __restrict__ srcd, const float* __restrict__ dstd,
                              const float* __restrict__ srcw, const float* __restrict__ dstw,
                              const float* __restrict__ sdc, const float* __restrict__ dsc,
                              const float* __restrict__ sdn, const float* __restrict__ dsn,
                              const int* __restrict__ idx, float* __restrict__ feats) {
    int p = blockIdx.x;
    int n = (p / KK) & (NN - 1);
    int b = p / (NN * KK);
    int m = idx[p];
    float* fo = feats + (long)p * 272;
    int tid = threadIdx.x;
    fo[10 + tid]  = srcd[((long)b*NN + n) * CC + tid];
    fo[138 + tid] = dstd[((long)b*NN + m) * CC + tid];
    if (tid == 0) {
        long qb = ((long)b*NN + n) * 3, rb = ((long)b*NN + m) * 3;
        float sx = src_xyz[qb], sy = src_xyz[qb+1], sz = src_xyz[qb+2];
        float kx = dst_xyz[rb], ky = dst_xyz[rb+1], kz = dst_xyz[rb+2];
        float rx = kx-sx, ry = ky-sy, rz = kz-sz;
        fo[0]=rx; fo[1]=ry; fo[2]=rz; fo[3]=sqrtf(rx*rx+ry*ry+rz*rz);
        fo[4]=sx; fo[5]=sy; fo[6]=sz; fo[7]=kx; fo[8]=ky; fo[9]=kz;
        fo[266]=srcw[b*NN+n]; fo[267]=dstw[b*NN+m];
        fo[268]=sdc[p]; fo[269]=dsc[p]; fo[270]=sdn[p]; fo[271]=dsn[p];
    }
}

__global__ void k_attention(const float* __restrict__ yraw,
                            const float* __restrict__ affS, const float* __restrict__ affQ,
                            const float* __restrict__ gP, const float* __restrict__ bP, float invP,
                            const int* __restrict__ idx, const float* __restrict__ dst_xyz,
                            float* __restrict__ outC, float* __restrict__ att) {
    int bn = blockIdx.x, tid = threadIdx.x;
    __shared__ float fe[KK][256];
    __shared__ float mk[KK], wgt[KK];
    __shared__ int sid[KK];
    if (tid < KK) sid[tid] = idx[(long)bn*KK + tid];
    float mu  = affS[tid] * invP;
    float var = fmaxf(affQ[tid] * invP - mu * mu, 0.f);
    float s   = gP[tid] * rsqrtf(var + BNEPS);
    float h   = bP[tid] - mu * s;
    #pragma unroll
    for (int k = 0; k < KK; k++) {
        float v = yraw[((long)bn*KK + k) * 256 + tid];
        fe[k][tid] = fmaxf(v * s + h, 0.f);
    }
    __syncthreads();
    int w = tid >> 5, lane = tid & 31;
    for (int kk = w; kk < KK; kk += 8) {
        float mx = -3.4e38f;
        for (int c = lane; c < 256; c += 32) mx = fmaxf(mx, fe[kk][c]);
        #pragma unroll
        for (int o = 16; o > 0; o >>= 1) mx = fmaxf(mx, __shfl_down_sync(0xffffffffu, mx, o));
        if (lane == 0) mk[kk] = mx;
    }
    __syncthreads();
    if (tid == 0) {
        float m = -3.4e38f;
        for (int k = 0; k < KK; k++) m = fmaxf(m, mk[k]);
        float ssum = 0.f;
        for (int k = 0; k < KK; k++) { float e = expf(mk[k]-m); wgt[k] = e; ssum += e; }
        float r = 1.f / ssum;
        for (int k = 0; k < KK; k++) wgt[k] *= r;
    }
    __syncthreads();
    float a = 0.f;
    #pragma unroll
    for (int k = 0; k < KK; k++) a += wgt[k] * fe[k][tid];
    att[(long)bn * 256 + tid] = a;
    if (tid < 3) {
        int b = bn >> 11;
        float cg = 0.f;
        #pragma unroll
        for (int k = 0; k < KK; k++)
            cg += wgt[k] * dst_xyz[((long)b*NN + sid[k]) * 3 + tid];
        outC[(long)bn * 3 + tid] = cg;
    }
}

__global__ void k_mlp3(const float* __restrict__ yraw,
                       const float* __restrict__ affS, const float* __restrict__ affQ,
                       const float* __restrict__ gP, const float* __restrict__ bP, float invP,
                       const float* __restrict__ w3, const float* __restrict__ b3,
                       float* __restrict__ outw) {
    int bn = blockIdx.x, tid = threadIdx.x;
    float mu  = affS[tid] * invP;
    float var = fmaxf(affQ[tid] * invP - mu * mu, 0.f);
    float s   = gP[tid] * rsqrtf(var + BNEPS);
    float h   = bP[tid] - mu * s;
    float v = fmaxf(yraw[(long)bn*256 + tid] * s + h, 0.f) * w3[tid];
    #pragma unroll
    for (int o = 16; o > 0; o >>= 1) v += __shfl_down_sync(0xffffffffu, v, o);
    __shared__ float ps[8];
    if ((tid & 31) == 0) ps[tid >> 5] = v;
    __syncthreads();
    if (tid == 0) {
        float s2 = 0.f;
        #pragma unroll
        for (int i = 0; i < 8; i++) s2 += ps[i];
        outw[bn] = 1.f / (1.f + expf(-(s2 + b3[0])));
    }
}

extern "C" void kernel_launch(void* const* d_in, const int* in_sizes, int n_in,
                              void* d_out, int out_size) {
    const float* src_xyz  = (const float*)d_in[0];
    const float* src_desc = (const float*)d_in[1];
    const float* dst_xyz  = (const float*)d_in[2];
    const float* dst_desc = (const float*)d_in[3];
    const float* src_w    = (const float*)d_in[4];
    const float* dst_w    = (const float*)d_in[5];
    const float* c1_W0 = (const float*)d_in[6];
    const float* c1_W  = (const float*)d_in[7];
    const float* c1_g  = (const float*)d_in[8];
    const float* c1_b  = (const float*)d_in[9];
    const float* c2_W0 = (const float*)d_in[10];
    const float* c2_W  = (const float*)d_in[11];
    const float* c2_g  = (const float*)d_in[12];
    const float* c2_b  = (const float*)d_in[13];
    const float* m1_W  = (const float*)d_in[14];
    const float* m1_g  = (const float*)d_in[16];
    const float* m1_b  = (const float*)d_in[17];
    const float* m2_W  = (const float*)d_in[18];
    const float* m2_g  = (const float*)d_in[20];
    const float* m2_b  = (const float*)d_in[21];
    const float* m3_W  = (const float*)d_in[22];
    const float* m3_b  = (const float*)d_in[23];

    float* base = nullptr;
    cudaGetSymbolAddress((void**)&base, g_pool);
    float* srcd   = base + F_SRCD;
    float* dstd   = base + F_DSTD;
    float* nsqS   = base + F_NSQS;
    float* nsqD   = base + F_NSQD;
    float* nrmS   = base + F_NRMS;
    float* nrmD   = base + F_NRMD;
    float* maxDS  = base + F_MAXDS;
    float* maxSD  = base + F_MAXSD;
    float* nrm2S  = base + F_NRM2S;
    float* nrm2D  = base + F_NRM2D;
    float* sdc    = base + F_SDC;
    float* dsc    = base + F_DSC;
    float* sdn    = base + F_SDN;
    float* dsn    = base + F_DSN;
    float* stat0  = base + F_STATS;
    float* w2p    = base + F_W2P;
    int*   idx    = (int*)(base + F_IDX);
    int*   sidx   = (int*)(base + F_SIDX);
    float* att    = base + F_ATT;
    float* mb1    = base + F_MB1;
    float* mb2    = base + F_MB2;
    float* srcnbr = base + F_SRCNBR;
    float* inner  = base + F_INNER;
    float* fbuf   = base + F_F;
    float* y0     = base + F_Y0;
    float* y1     = base + F_Y1;
    float* outC   = (float*)d_out;
    float* outW   = (float*)d_out + (long)BB*NN*3;

    auto slot = [&](int i) { return stat0 + (long)i * 1024; };
    const float invPP = 1.f / (float)PP;
    const float invBN = 1.f / (float)BN;

    k_fill<<<32, 256>>>(stat0, 0.f, 8 * 1024);
    k_pad_w<<<128, 144>>>(c2_W0, w2p);

    // A: transpose + norms
    k_transpose_norm<<<dim3(BN, 2), 128>>>(src_desc, dst_desc, srcd, nsqS, nrmS);

    // inner = src . dst with fused cosine maxes
    k_fill<<<32, 256>>>(maxDS, -3.4e38f, 2*BN);
    k_gemm_sim<<<dim3(NN/SGN, NN/SGM, 2), 256>>>(srcd, dstd, inner, nrmS, nrmD, maxDS, maxSD);
    k_knn_desc<<<dim3(NN, BB), 256>>>(inner, nsqS, nsqD, idx);
    k_simgather<<<PP/256, 256>>>(inner, nrmS, nrmD, maxDS, maxSD, idx, sdc, dsc);

    // B: neighborhood descriptors — both clouds batched
    k_knn_xyz<<<dim3(NN, BB, 2), 256>>>(src_xyz, dst_xyz, sidx);
    k_build_nbr_f<<<2*PP, 128>>>(src_xyz, dst_xyz, srcd, sidx, fbuf);
    const float* c2W1 = c2_W;
    const float* c2W2 = c2_W + CC*CC;
    k_gemm_tc<<<dim3(CC/TCN, (2*PP)/TCM), 256>>>(fbuf, w2p, y0, 2*PP, CC, 144,
        nullptr, nullptr, nullptr, nullptr, 0.f, slot(0), slot(0)+512, PP);
    k_gemm_tc<<<dim3(CC/TCN, (2*PP)/TCM), 256>>>(y0, c2W1, y1, 2*PP, CC, CC,
        slot(0), slot(0)+512, c2_g, c2_b, invPP, slot(1), slot(1)+512, PP);
    k_gemm_tc<<<dim3(CC/TCN, (2*PP)/TCM), 256>>>(y1, c2W2, y0, 2*PP, CC, CC,
        slot(1), slot(1)+512, c2_g + CC, c2_b + CC, invPP, slot(2), slot(2)+512, PP);
    k_nbr_final<<<2*BN, 256>>>(y0, slot(2), slot(2)+512, c2_g + 2*CC, c2_b + 2*CC, invPP,
                               sidx, srcd, srcnbr);

    // nbr cosine sims
    k_rownorm<<<2*BN, 128>>>(srcnbr, nrm2S);
    k_fill<<<32, 256>>>(maxDS, -3.4e38f, 2*BN);
    k_gemm_sim<<<dim3(NN/SGN, NN/SGM, 2), 256>>>(srcnbr, srcnbr + (long)BN*CC, inner,
                                                 nrm2S, nrm2D, maxDS, maxSD);
    k_simgather<<<PP/256, 256>>>(inner, nrm2S, nrm2D, maxDS, maxSD, idx, sdn, dsn);

    // C: main feature conv + attention
    k_build_feats<<<PP, 128>>>(src_xyz, dst_xyz, srcd, dstd, src_w, dst_w,
                               sdc, dsc, sdn, dsn, idx, fbuf);
    const float* c1W1 = c1_W;
    const float* c1W2 = c1_W + 256*256;
    k_gemm_tc<<<dim3(256/TCN, PP/TCM), 256>>>(fbuf, c1_W0, y0, PP, 256, 272,
        nullptr, nullptr, nullptr, nullptr, 0.f, slot(3), slot(3)+512, 0);
    k_gemm_tc<<<dim3(256/TCN, PP/TCM), 256>>>(y0, c1W1, y1, PP, 256, 256,
        slot(3), slot(3)+512, c1_g, c1_b, invPP, slot(4), slot(4)+512, 0);
    k_gemm_tc<<<dim3(256/TCN, PP/TCM), 256>>>(y1, c1W2, y0, PP, 256, 256,
        slot(4), slot(4)+512, c1_g + 256, c1_b + 256, invPP, slot(5), slot(5)+512, 0);
    k_attention<<<BN, 256>>>(y0, slot(5), slot(5)+512, c1_g + 512, c1_b + 512, invPP,
                             idx, dst_xyz, outC, att);

    // D: MLP head
    k_gemm_tc<<<dim3(256/TCN, BN/TCM), 256>>>(att, m1_W, mb1, BN, 256, 256,
        nullptr, nullptr, nullptr, nullptr, 0.f, slot(6), slot(6)+512, 0);
    k_gemm_tc<<<dim3(256/TCN, BN/TCM), 256>>>(mb1, m2_W, mb2, BN, 256, 256,
        slot(6), slot(6)+512, m1_g, m1_b, invBN, slot(7), slot(7)+512, 0);
    k_mlp3<<<BN, 256>>>(mb2, slot(7), slot(7)+512, m2_g, m2_b, invBN, m3_W, m3_b, outW);
}

// round 13
// speedup vs baseline: 1.5653x; 1.0800x over previous
#include <cuda_runtime.h>
#include <mma.h>
#include <math.h>
#include <float.h>

using namespace nvcuda;

#define BB 2
#define NN 2048
#define CC 128
#define KK 16
#define BN (BB*NN)
#define PP (BB*NN*KK)
#define EPSF 1e-6f
#define BNEPS 1e-5f

// ---------------- scratch pool ----------------
constexpr long F_SRCD   = 0;
constexpr long F_DSTD   = F_SRCD   + (long)BN*CC;
constexpr long F_NSQS   = F_DSTD   + (long)BN*CC;
constexpr long F_NSQD   = F_NSQS   + BN;
constexpr long F_NRMS   = F_NSQD   + BN;
constexpr long F_NRMD   = F_NRMS   + BN;
constexpr long F_MAXDS  = F_NRMD   + BN;
constexpr long F_MAXSD  = F_MAXDS  + BN;
constexpr long F_NRM2S  = F_MAXSD  + BN;
constexpr long F_NRM2D  = F_NRM2S  + BN;
constexpr long F_SDC    = F_NRM2D  + BN;
constexpr long F_DSC    = F_SDC    + PP;
constexpr long F_SDN    = F_DSC    + PP;
constexpr long F_DSN    = F_SDN    + PP;
constexpr long F_STATS  = F_DSN    + PP;            // 8 slots x 1024 (S at +0, Q at +512)
constexpr long F_W2P    = F_STATS  + 8*1024;        // padded+rounded c2_W0 [128][144]
constexpr long F_WC2    = F_W2P    + 128*144;       // rounded c2_W (2 x 128x128)
constexpr long F_WC10   = F_WC2    + 2*CC*CC;       // rounded c1_W0 (256x272)
constexpr long F_WC1    = F_WC10   + 256*272;       // rounded c1_W (2 x 256x256)
constexpr long F_WM1    = F_WC1    + 2*256*256;     // rounded m1_W
constexpr long F_WM2    = F_WM1    + 256*256;       // rounded m2_W
constexpr long F_IDX    = F_WM2    + 256*256;       // int
constexpr long F_SIDX   = F_IDX    + PP;
constexpr long F_DIDX   = F_SIDX   + PP;
constexpr long F_ATT    = F_DIDX   + PP;
constexpr long F_MB1    = F_ATT    + (long)BN*256;
constexpr long F_MB2    = F_MB1    + (long)BN*256;
constexpr long F_SRCNBR = F_MB2    + (long)BN*256;
constexpr long F_DSTNBR = F_SRCNBR + (long)BN*CC;
constexpr long F_INNER  = F_DSTNBR + (long)BN*CC;
constexpr long F_F      = F_INNER  + (long)BB*NN*NN;
constexpr long F_FSZ    = (long)2*PP*144;           // max(PP*272, 2PP*144)
constexpr long F_Y0     = F_F      + F_FSZ;
constexpr long F_Y1     = F_Y0     + (long)PP*256;
constexpr long F_END    = F_Y1     + (long)PP*256;

__device__ __align__(128) float g_pool[F_END];

__device__ __forceinline__ void atomicMaxF(float* a, float v) {
    if (!(v < 0.f)) atomicMax((int*)a, __float_as_int(v));
    else            atomicMin((unsigned int*)a, __float_as_uint(v));
}

__device__ __forceinline__ unsigned cvt_tf32(float x) {
    unsigned u;
    asm("cvt.rn.tf32.f32 %0, %1;" : "=r"(u) : "f"(x));
    return u;
}
__device__ __forceinline__ float round_tf32(float x) {
    return __uint_as_float(cvt_tf32(x));
}

__device__ __forceinline__ void cp_async16(unsigned saddr, const void* gptr) {
    asm volatile("cp.async.ca.shared.global [%0], [%1], 16;" :: "r"(saddr), "l"(gptr));
}
__device__ __forceinline__ void cp_commit() { asm volatile("cp.async.commit_group;"); }
template<int N> __device__ __forceinline__ void cp_wait() {
    asm volatile("cp.async.wait_group %0;" :: "n"(N));
}

__global__ void k_fill(float* __restrict__ p, float v, int n) {
    int i = blockIdx.x * blockDim.x + threadIdx.x;
    if (i < n) p[i] = v;
}

// round-copy weights to tf32
__global__ void k_cvt(const float* __restrict__ in, float* __restrict__ out, int n) {
    int i = blockIdx.x * blockDim.x + threadIdx.x;
    if (i < n) out[i] = round_tf32(in[i]);
}

__global__ void k_pad_w(const float* __restrict__ W, float* __restrict__ Wp) {
    int o = blockIdx.x; int k = threadIdx.x; // 144 threads
    Wp[o * 144 + k] = (k < 132) ? round_tf32(W[o * 132 + k]) : 0.f;
}

// both clouds: [B,C,N] -> [B,N,C] plus |.|^2 and |.|
__global__ void k_transpose_norm(const float* __restrict__ descS, const float* __restrict__ descD,
                                 float* __restrict__ dmatAll, float* __restrict__ nsqAll,
                                 float* __restrict__ nrmAll) {
    int cloud = blockIdx.y;
    const float* desc = cloud ? descD : descS;
    float* dmat = dmatAll + (long)cloud*BN*CC;
    float* nsq  = nsqAll  + cloud*BN;
    float* nrm  = nrmAll  + cloud*BN;
    int bn = blockIdx.x; int b = bn >> 11; int n = bn & (NN - 1);
    int c = threadIdx.x;
    float v = desc[((long)b*CC + c)*NN + n];
    dmat[(long)bn*CC + c] = v;
    float s = v * v;
    #pragma unroll
    for (int o = 16; o > 0; o >>= 1) s += __shfl_down_sync(0xffffffffu, s, o);
    __shared__ float ps[4];
    if ((c & 31) == 0) ps[c >> 5] = s;
    __syncthreads();
    if (c == 0) { float t = ps[0]+ps[1]+ps[2]+ps[3]; nsq[bn] = t; nrm[bn] = sqrtf(t); }
}

__global__ void k_rownorm(const float* __restrict__ dmat, float* __restrict__ nrm) {
    int bn = blockIdx.x; int c = threadIdx.x;
    float v = dmat[(long)bn*CC + c];
    float s = v * v;
    #pragma unroll
    for (int o = 16; o > 0; o >>= 1) s += __shfl_down_sync(0xffffffffu, s, o);
    __shared__ float ps[4];
    if ((c & 31) == 0) ps[c >> 5] = s;
    __syncthreads();
    if (c == 0) nrm[bn] = sqrtf(ps[0]+ps[1]+ps[2]+ps[3]);
}

// ---------------- split-tf32 sim GEMM: 3-stage cp.async, reg-side hi/lo ----------
#define SGM 128
#define SGN 64
#define SLD 20
#define SCLD 68
#define SSTG ((SGM+SGN)*SLD)   // 3840 floats per stage

__global__ __launch_bounds__(256, 3)
void k_gemm_sim(const float* __restrict__ A, const float* __restrict__ Bm,
                float* __restrict__ Cm,
                const float* __restrict__ nrmA, const float* __restrict__ nrmB,
                float* __restrict__ maxDS, float* __restrict__ maxSD) {
    const int b = blockIdx.z;
    A  += (long)b * NN * CC;
    Bm += (long)b * NN * CC;
    Cm += (long)b * NN * NN;

    __shared__ __align__(16) float smem[3 * SSTG];   // 46080B; Csm (34816B) unioned
    float* Csm = smem;
    __shared__ float rns[SGM], rnd[SGN], rm[SGM], cmx[SGN];

    const int tid = threadIdx.x;
    const int lane = tid & 31;
    const int g   = lane >> 2;
    const int tig = lane & 3;
    const int wid = tid >> 5;
    const int wm = wid & 3;
    const int wn = wid >> 2;
    const long rowBase = (long)blockIdx.y * SGM;
    const int colBase = blockIdx.x * SGN;

    if (tid < SGM) { rns[tid] = nrmA[b*NN + rowBase + tid]; rm[tid] = -3.4e38f; }
    if (tid < SGN) { rnd[tid] = nrmB[b*NN + colBase + tid]; cmx[tid] = -3.4e38f; }

    const int srow = tid >> 2;
    const int kq = (tid & 3) * 4;
    unsigned sbase;
    asm("{ .reg .u64 t; cvta.to.shared.u64 t, %1; cvt.u32.u64 %0, t; }"
        : "=r"(sbase) : "l"(smem));

    auto issue = [&](int kc) {
        int buf = kc % 3;
        int k0 = kc * 16;
        const float* ga0 = &A[(rowBase + srow) * CC + k0 + kq];
        const float* ga1 = &A[(rowBase + srow + 64) * CC + k0 + kq];
        const float* gb  = &Bm[(long)(colBase + srow) * CC + k0 + kq];
        unsigned base = sbase + (unsigned)(buf * SSTG * 4);
        unsigned da0 = base + (unsigned)((srow * SLD + kq) * 4);
        unsigned da1 = da0 + 64u * SLD * 4u;
        unsigned db  = base + (unsigned)((SGM * SLD + srow * SLD + kq) * 4);
        cp_async16(da0, ga0);
        cp_async16(da1, ga1);
        cp_async16(db, gb);
        cp_commit();
    };

    float acc[2][4][4];
    #pragma unroll
    for (int i = 0; i < 2; i++)
        #pragma unroll
        for (int j = 0; j < 4; j++)
            #pragma unroll
            for (int t = 0; t < 4; t++)
                acc[i][j][t] = 0.f;

    const int nk = CC / 16;
    issue(0);
    issue(1);

    for (int kc = 0; kc < nk; kc++) {
        cp_wait<1>();
        __syncthreads();
        if (kc + 2 < nk) issue(kc + 2);
        const float* As = smem + (kc % 3) * SSTG;
        const float* Bs = As + SGM * SLD;
        #pragma unroll
        for (int ks = 0; ks < 2; ks++) {
            const int kb = ks * 8;
            unsigned bh0[4], bh1[4], bl0[4], bl1[4];
            #pragma unroll
            for (int nj = 0; nj < 4; nj++) {
                int nb = wn * 32 + nj * 8 + g;
                float w0 = Bs[nb * SLD + kb + tig];
                float w1 = Bs[nb * SLD + kb + tig + 4];
                unsigned h0 = cvt_tf32(w0), h1 = cvt_tf32(w1);
                bh0[nj] = h0; bh1[nj] = h1;
                bl0[nj] = cvt_tf32(w0 - __uint_as_float(h0));
                bl1[nj] = cvt_tf32(w1 - __uint_as_float(h1));
            }
            #pragma unroll
            for (int mi = 0; mi < 2; mi++) {
                int ar = wm * 32 + mi * 16;
                float v0 = As[(ar + g    ) * SLD + kb + tig];
                float v1 = As[(ar + g + 8) * SLD + kb + tig];
                float v2 = As[(ar + g    ) * SLD + kb + tig + 4];
                float v3 = As[(ar + g + 8) * SLD + kb + tig + 4];
                unsigned ah0 = cvt_tf32(v0), ah1 = cvt_tf32(v1);
                unsigned ah2 = cvt_tf32(v2), ah3 = cvt_tf32(v3);
                unsigned al0 = cvt_tf32(v0 - __uint_as_float(ah0));
                unsigned al1 = cvt_tf32(v1 - __uint_as_float(ah1));
                unsigned al2 = cvt_tf32(v2 - __uint_as_float(ah2));
                unsigned al3 = cvt_tf32(v3 - __uint_as_float(ah3));
                #pragma unroll
                for (int nj = 0; nj < 4; nj++) {
                    asm volatile(
                        "mma.sync.aligned.m16n8k8.row.col.f32.tf32.tf32.f32 "
                        "{%0,%1,%2,%3}, {%4,%5,%6,%7}, {%8,%9}, {%0,%1,%2,%3};"
                        : "+f"(acc[mi][nj][0]), "+f"(acc[mi][nj][1]),
                          "+f"(acc[mi][nj][2]), "+f"(acc[mi][nj][3])
                        : "r"(ah0), "r"(ah1), "r"(ah2), "r"(ah3),
                          "r"(bh0[nj]), "r"(bh1[nj]));
                    asm volatile(
                        "mma.sync.aligned.m16n8k8.row.col.f32.tf32.tf32.f32 "
                        "{%0,%1,%2,%3}, {%4,%5,%6,%7}, {%8,%9}, {%0,%1,%2,%3};"
                        : "+f"(acc[mi][nj][0]), "+f"(acc[mi][nj][1]),
                          "+f"(acc[mi][nj][2]), "+f"(acc[mi][nj][3])
                        : "r"(ah0), "r"(ah1), "r"(ah2), "r"(ah3),
                          "r"(bl0[nj]), "r"(bl1[nj]));
                    asm volatile(
                        "mma.sync.aligned.m16n8k8.row.col.f32.tf32.tf32.f32 "
                        "{%0,%1,%2,%3}, {%4,%5,%6,%7}, {%8,%9}, {%0,%1,%2,%3};"
                        : "+f"(acc[mi][nj][0]), "+f"(acc[mi][nj][1]),
                          "+f"(acc[mi][nj][2]), "+f"(acc[mi][nj][3])
                        : "r"(al0), "r"(al1), "r"(al2), "r"(al3),
                          "r"(bh0[nj]), "r"(bh1[nj]));
                }
            }
        }
    }
    __syncthreads();   // staging buffers now alias Csm

    #pragma unroll
    for (int mi = 0; mi < 2; mi++) {
        int r0r = wm * 32 + mi * 16 + g;
        #pragma unroll
        for (int nj = 0; nj < 4; nj++) {
            int c0 = wn * 32 + nj * 8 + 2 * tig;
            Csm[r0r * SCLD + c0]           = acc[mi][nj][0];
            Csm[r0r * SCLD + c0 + 1]       = acc[mi][nj][1];
            Csm[(r0r + 8) * SCLD + c0]     = acc[mi][nj][2];
            Csm[(r0r + 8) * SCLD + c0 + 1] = acc[mi][nj][3];
        }
    }
    __syncthreads();

    const int ccol = tid & 63;
    const int r0 = tid >> 6;
    const float nd = rnd[ccol];
    float colmax = -3.4e38f;
    #pragma unroll 8
    for (int it = 0; it < 32; it++) {
        int r = r0 + it * 4;
        float v = Csm[r * SCLD + ccol];
        Cm[(rowBase + r) * NN + colBase + ccol] = v;
        float csv = v / (nd * rns[r] + EPSF);
        colmax = fmaxf(colmax, csv);
        float wmx = csv;
        #pragma unroll
        for (int o = 16; o > 0; o >>= 1) wmx = fmaxf(wmx, __shfl_down_sync(0xffffffffu, wmx, o));
        if (lane == 0) atomicMaxF(&rm[r], wmx);
    }
    atomicMaxF(&cmx[ccol], colmax);
    __syncthreads();
    if (tid < SGM) atomicMaxF(&maxDS[b*NN + rowBase + tid], rm[tid]);
    else if (tid < SGM + SGN) atomicMaxF(&maxSD[b*NN + colBase + (tid - SGM)], cmx[tid - SGM]);
}

// ---------------- TF32 conv GEMM v4: 3-stage cp.async, pre-rounded B (and A when !aff) ----
// REQUIREMENT: Bm is tf32-pre-rounded. When affS==null, A must be tf32-pre-rounded too.
#define TCM 128
#define TCN 64
#define ALD 20
#define CLD 68
#define TSTG ((TCM+TCN)*ALD)

__global__ __launch_bounds__(256, 3)
void k_gemm_tc(const float* __restrict__ A, const float* __restrict__ Bm,
               float* __restrict__ Cm, int P, int O, int Kd,
               const float* __restrict__ affS, const float* __restrict__ affQ,
               const float* __restrict__ gP, const float* __restrict__ bP, float invP,
               float* __restrict__ statS, float* __restrict__ statQ, int splitRows) {
    __shared__ __align__(16) float smem[3 * TSTG];   // 46080B; Csm unioned
    float* Csm = smem;
    __shared__ float cs[TCN], cq[TCN];
    __shared__ float sSc[256], sSh[256];

    const int tid = threadIdx.x;
    const int lane = tid & 31;
    const int g   = lane >> 2;
    const int tig = lane & 3;
    const int wid = tid >> 5;
    const int wm = wid & 3;
    const int wn = wid >> 2;
    const int rowBase = blockIdx.y * TCM;
    const int colBase = blockIdx.x * TCN;
    const bool aff = (affS != nullptr);
    const bool stats = (statS != nullptr);
    const int cloudA = (splitRows > 0 && rowBase >= splitRows) ? 1 : 0;
    const int statOff = cloudA * O;

    if (aff && tid < Kd && tid < 256) {
        int so = cloudA * Kd + tid;
        float mu  = affS[so] * invP;
        float var = fmaxf(affQ[so] * invP - mu * mu, 0.f);
        float s   = gP[tid] * rsqrtf(var + BNEPS);
        sSc[tid] = s;
        sSh[tid] = bP[tid] - mu * s;
    }
    if (stats && tid < TCN) { cs[tid] = 0.f; cq[tid] = 0.f; }

    const int srow = tid >> 2;
    const int kq = (tid & 3) * 4;
    unsigned sbase;
    asm("{ .reg .u64 t; cvta.to.shared.u64 t, %1; cvt.u32.u64 %0, t; }"
        : "=r"(sbase) : "l"(smem));

    auto issue = [&](int kc) {
        int buf = kc % 3;
        int k0 = kc * 16;
        const float* ga0 = &A[(long)(rowBase + srow) * Kd + k0 + kq];
        const float* ga1 = &A[(long)(rowBase + srow + 64) * Kd + k0 + kq];
        const float* gb  = &Bm[(long)(colBase + srow) * Kd + k0 + kq];
        unsigned base = sbase + (unsigned)(buf * TSTG * 4);
        unsigned da0 = base + (unsigned)((srow * ALD + kq) * 4);
        unsigned da1 = da0 + 64u * ALD * 4u;
        unsigned db  = base + (unsigned)((TCM * ALD + srow * ALD + kq) * 4);
        cp_async16(da0, ga0);
        cp_async16(da1, ga1);
        cp_async16(db, gb);
        cp_commit();
    };

    float acc[2][4][4];
    #pragma unroll
    for (int i = 0; i < 2; i++)
        #pragma unroll
        for (int j = 0; j < 4; j++)
            #pragma unroll
            for (int t = 0; t < 4; t++)
                acc[i][j][t] = 0.f;

    const int nk = Kd / 16;
    issue(0);
    issue(1);

    for (int kc = 0; kc < nk; kc++) {
        cp_wait<1>();
        __syncthreads();
        if (kc + 2 < nk) issue(kc + 2);
        const float* As = smem + (kc % 3) * TSTG;
        const float* Bs = As + TCM * ALD;
        const int k0 = kc * 16;
        #pragma unroll
        for (int ks = 0; ks < 2; ks++) {
            const int kb = ks * 8;
            // B: pre-rounded tf32 -> direct bit reinterpret
            unsigned b0[4], b1[4];
            #pragma unroll
            for (int nj = 0; nj < 4; nj++) {
                int nb = wn * 32 + nj * 8 + g;
                b0[nj] = __float_as_uint(Bs[nb * ALD + kb + tig]);
                b1[nj] = __float_as_uint(Bs[nb * ALD + kb + tig + 4]);
            }
            float sc0 = 1.f, sh0 = 0.f, sc4 = 1.f, sh4 = 0.f;
            if (aff) {
                sc0 = sSc[k0 + kb + tig];     sh0 = sSh[k0 + kb + tig];
                sc4 = sSc[k0 + kb + tig + 4]; sh4 = sSh[k0 + kb + tig + 4];
            }
            #pragma unroll
            for (int mi = 0; mi < 2; mi++) {
                int ar = wm * 32 + mi * 16;
                float v0 = As[(ar + g    ) * ALD + kb + tig];
                float v1 = As[(ar + g + 8) * ALD + kb + tig];
                float v2 = As[(ar + g    ) * ALD + kb + tig + 4];
                float v3 = As[(ar + g + 8) * ALD + kb + tig + 4];
                unsigned a0, a1, a2, a3;
                if (aff) {
                    a0 = cvt_tf32(fmaxf(v0 * sc0 + sh0, 0.f));
                    a1 = cvt_tf32(fmaxf(v1 * sc0 + sh0, 0.f));
                    a2 = cvt_tf32(fmaxf(v2 * sc4 + sh4, 0.f));
                    a3 = cvt_tf32(fmaxf(v3 * sc4 + sh4, 0.f));
                } else {
                    a0 = __float_as_uint(v0);
                    a1 = __float_as_uint(v1);
                    a2 = __float_as_uint(v2);
                    a3 = __float_as_uint(v3);
                }
                #pragma unroll
                for (int nj = 0; nj < 4; nj++) {
                    asm volatile(
                        "mma.sync.aligned.m16n8k8.row.col.f32.tf32.tf32.f32 "
                        "{%0,%1,%2,%3}, {%4,%5,%6,%7}, {%8,%9}, {%0,%1,%2,%3};"
                        : "+f"(acc[mi][nj][0]), "+f"(acc[mi][nj][1]),
                          "+f"(acc[mi][nj][2]), "+f"(acc[mi][nj][3])
                        : "r"(a0), "r"(a1), "r"(a2), "r"(a3),
                          "r"(b0[nj]), "r"(b1[nj]));
                }
            }
        }
    }
    __syncthreads();   // staging aliases Csm

    #pragma unroll
    for (int mi = 0; mi < 2; mi++) {
        int r0r = wm * 32 + mi * 16 + g;
        #pragma unroll
        for (int nj = 0; nj < 4; nj++) {
            int c0 = wn * 32 + nj * 8 + 2 * tig;
            Csm[r0r * CLD + c0]           = acc[mi][nj][0];
            Csm[r0r * CLD + c0 + 1]       = acc[mi][nj][1];
            Csm[(r0r + 8) * CLD + c0]     = acc[mi][nj][2];
            Csm[(r0r + 8) * CLD + c0 + 1] = acc[mi][nj][3];
        }
    }
    __syncthreads();

    const int ccol = tid & 63;
    const int r0 = tid >> 6;
    float s = 0.f, q = 0.f;
    #pragma unroll 8
    for (int it = 0; it < 32; it++) {
        int r = r0 + it * 4;
        float v = Csm[r * CLD + ccol];
        Cm[(long)(rowBase + r) * O + colBase + ccol] = v;
        s += v; q += v * v;
    }
    if (stats) {
        atomicAdd(&cs[ccol], s);
        atomicAdd(&cq[ccol], q);
        __syncthreads();
        if (tid < TCN) {
            atomicAdd(&statS[statOff + colBase + tid], cs[tid]);
            atomicAdd(&statQ[statOff + colBase + tid], cq[tid]);
        }
    }
}

// top-16 smallest from shared d2[NN], 256 threads
__device__ void select_topk(float* d2, int* outIdx) {
    __shared__ float rv[8];
    __shared__ int   ri[8];
    int tid = threadIdx.x, lane = tid & 31, w = tid >> 5;
    for (int kk = 0; kk < KK; kk++) {
        float best = 3.4e38f; int bi = 0;
        for (int m = tid; m < NN; m += 256) {
            float v = d2[m];
            if (v < best) { best = v; bi = m; }
        }
        #pragma unroll
        for (int o = 16; o > 0; o >>= 1) {
            float ov = __shfl_down_sync(0xffffffffu, best, o);
            int   oi = __shfl_down_sync(0xffffffffu, bi, o);
            if (ov < best || (ov == best && oi < bi)) { best = ov; bi = oi; }
        }
        if (lane == 0) { rv[w] = best; ri[w] = bi; }
        __syncthreads();
        if (tid == 0) {
            float bv = rv[0]; int bj = ri[0];
            #pragma unroll
            for (int i = 1; i < 8; i++)
                if (rv[i] < bv || (rv[i] == bv && ri[i] < bj)) { bv = rv[i]; bj = ri[i]; }
            outIdx[kk] = bj;
            d2[bj] = 3.4e38f;
        }
        __syncthreads();
    }
}

__global__ void k_knn_desc(const float* __restrict__ inner, const float* __restrict__ nsqS,
                           const float* __restrict__ nsqD, int* __restrict__ idxOut) {
    int n = blockIdx.x, b = blockIdx.y;
    __shared__ float d2[NN];
    const float* row = inner + (long)b*NN*NN + (long)n*NN;
    float q = nsqS[b*NN + n];
    for (int m = threadIdx.x; m < NN; m += 256) d2[m] = q + nsqD[b*NN + m] - 2.f * row[m];
    __syncthreads();
    select_topk(d2, idxOut + ((long)b*NN + n) * KK);
}

__global__ void k_knn_xyz(const float* __restrict__ xyzS, const float* __restrict__ xyzD,
                          int* __restrict__ idxAll) {
    int n = blockIdx.x, b = blockIdx.y, cloud = blockIdx.z;
    const float* xyz = cloud ? xyzD : xyzS;
    int* idxOut = idxAll + (long)cloud*PP;
    __shared__ float d2[NN];
    long base = (long)b * NN * 3;
    float qx = xyz[base + (long)n*3], qy = xyz[base + (long)n*3+1], qz = xyz[base + (long)n*3+2];
    float qq = qx*qx + qy*qy + qz*qz;
    for (int m = threadIdx.x; m < NN; m += 256) {
        float rx = xyz[base + (long)m*3], ry = xyz[base + (long)m*3+1], rz = xyz[base + (long)m*3+2];
        d2[m] = qq + rx*rx + ry*ry + rz*rz - 2.f*(qx*rx + qy*ry + qz*rz);
    }
    __syncthreads();
    select_topk(d2, idxOut + ((long)b*NN + n) * KK);
}

__global__ void k_simgather(const float* __restrict__ inner, const float* __restrict__ nrmS,
                            const float* __restrict__ nrmD, const float* __restrict__ maxDS,
                            const float* __restrict__ maxSD, const int* __restrict__ idx,
                            float* __restrict__ outSD, float* __restrict__ outDS) {
    int t = blockIdx.x * 256 + threadIdx.x;
    if (t >= PP) return;
    int b = t / (NN * KK);
    int n = (t / KK) & (NN - 1);
    int m = idx[t];
    float v  = inner[(long)b*NN*NN + (long)n*NN + m];
    float cs = v / (nrmD[b*NN + m] * nrmS[b*NN + n] + EPSF);
    outSD[t] = cs / (maxDS[b*NN + n] + EPSF);
    outDS[t] = cs / (maxSD[b*NN + m] + EPSF);
}

// both clouds: nbr conv input, tf32-ROUNDED (feeds non-affine GEMM)
__global__ void k_build_nbr_f(const float* __restrict__ xyzS, const float* __restrict__ xyzD,
                              const float* __restrict__ dmatAll, const int* __restrict__ idxAll,
                              float* __restrict__ f) {
    int p = blockIdx.x;
    int cloud = p >= PP;
    int pl = p - cloud * PP;
    const float* xyz = cloud ? xyzD : xyzS;
    const float* dmatC = dmatAll + (long)cloud*BN*CC;
    int n = (pl / KK) & (NN - 1);
    int b = pl / (NN * KK);
    int m = idxAll[p];
    const float* dr = dmatC + ((long)b*NN + m) * CC;
    float* fo = f + (long)p * 144;
    int tid = threadIdx.x;
    fo[tid] = round_tf32(dr[tid]);
    if (tid == 0) {
        long qb = ((long)b*NN + n) * 3, rb = ((long)b*NN + m) * 3;
        float rx = xyz[rb]-xyz[qb], ry = xyz[rb+1]-xyz[qb+1], rz = xyz[rb+2]-xyz[qb+2];
        fo[128] = round_tf32(rx); fo[129] = round_tf32(ry); fo[130] = round_tf32(rz);
        fo[131] = round_tf32(sqrtf(rx*rx+ry*ry+rz*rz));
        #pragma unroll
        for (int z = 132; z < 144; z++) fo[z] = 0.f;
    }
}

// both clouds: grid 2*BN, in-block affine from producer stats
__global__ void k_nbr_final(const float* __restrict__ yraw,
                            const float* __restrict__ affS, const float* __restrict__ affQ,
                            const float* __restrict__ gP, const float* __restrict__ bP, float invP,
                            const int* __restrict__ idxAll,
                            const float* __restrict__ dmatAll, float* __restrict__ outAll) {
    int gblk = blockIdx.x;
    int cloud = gblk >= BN;
    int bn = gblk - cloud * BN;
    const float* y = yraw + (long)cloud*PP*CC;
    const int* idx = idxAll + (long)cloud*PP;
    const float* dmat = dmatAll + (long)cloud*BN*CC;
    float* outN = outAll + (long)cloud*BN*CC;
    int tid = threadIdx.x;
    __shared__ float fe[KK][CC];
    __shared__ float mk[KK], wgt[KK];
    __shared__ int sid[KK];
    __shared__ float sSc[CC], sSh[CC];
    if (tid < CC) {
        int so = cloud * CC + tid;
        float mu  = affS[so] * invP;
        float var = fmaxf(affQ[so] * invP - mu * mu, 0.f);
        float s   = gP[tid] * rsqrtf(var + BNEPS);
        sSc[tid] = s;
        sSh[tid] = bP[tid] - mu * s;
    }
    if (tid < KK) sid[tid] = idx[(long)bn*KK + tid];
    __syncthreads();
    for (int t = tid; t < KK * CC; t += 256) {
        int k = t >> 7, c = t & 127;
        float v = y[((long)bn*KK + k) * CC + c];
        fe[k][c] = fmaxf(v * sSc[c] + sSh[c], 0.f);
    }
    __syncthreads();
    int w = tid >> 5, lane = tid & 31;
    for (int kk = w; kk < KK; kk += 8) {
        float mx = -3.4e38f;
        for (int c = lane; c < CC; c += 32) mx = fmaxf(mx, fe[kk][c]);
        #pragma unroll
        for (int o = 16; o > 0; o >>= 1) mx = fmaxf(mx, __shfl_down_sync(0xffffffffu, mx, o));
        if (lane == 0) mk[kk] = mx;
    }
    __syncthreads();
    if (tid == 0) {
        float m = -3.4e38f;
        for (int k = 0; k < KK; k++) m = fmaxf(m, mk[k]);
        float s = 0.f;
        for (int k = 0; k < KK; k++) { float e = expf(mk[k]-m); wgt[k] = e; s += e; }
        float r = 1.f / s;
        for (int k = 0; k < KK; k++) wgt[k] *= r;
    }
    __syncthreads();
    if (tid < CC) {
        int b = bn >> 11;
        float a = 0.f;
        #pragma unroll
        for (int k = 0; k < KK; k++) a += wgt[k] * dmat[((long)b*NN + sid[k]) * CC + tid];
        outN[(long)bn*CC + tid] = a;
    }
}

// main feats build (272 ch), tf32-ROUNDED (feeds non-affine GEMM)
__global__ void k_build_feats(const float* __restrict__ src_xyz, const float* __restrict__ dst_xyz,
                              const float* __restrict__ srcd, const float* __restrict__ dstd,
                              const float* __restrict__ srcw, const float* __restrict__ dstw,
                              const float* __restrict__ sdc, const float* __restrict__ dsc,
                              const float* __restrict__ sdn, const float* __restrict__ dsn,
                              const int* __restrict__ idx, float* __restrict__ feats) {
    int p = blockIdx.x;
    int n = (p / KK) & (NN - 1);
    int b = p / (NN * KK);
    int m = idx[p];
    float* fo = feats + (long)p * 272;
    int tid = threadIdx.x;
    fo[10 + tid]  = round_tf32(srcd[((long)b*NN + n) * CC + tid]);
    fo[138 + tid] = round_tf32(dstd[((long)b*NN + m) * CC + tid]);
    if (tid == 0) {
        long qb = ((long)b*NN + n) * 3, rb = ((long)b*NN + m) * 3;
        float sx = src_xyz[qb], sy = src_xyz[qb+1], sz = src_xyz[qb+2];
        float kx = dst_xyz[rb], ky = dst_xyz[rb+1], kz = dst_xyz[rb+2];
        float rx = kx-sx, ry = ky-sy, rz = kz-sz;
        fo[0]=round_tf32(rx); fo[1]=round_tf32(ry); fo[2]=round_tf32(rz);
        fo[3]=round_tf32(sqrtf(rx*rx+ry*ry+rz*rz));
        fo[4]=round_tf32(sx); fo[5]=round_tf32(sy); fo[6]=round_tf32(sz);
        fo[7]=round_tf32(kx); fo[8]=round_tf32(ky); fo[9]=round_tf32(kz);
        fo[266]=round_tf32(srcw[b*NN+n]); fo[267]=round_tf32(dstw[b*NN+m]);
        fo[268]=round_tf32(sdc[p]); fo[269]=round_tf32(dsc[p]);
        fo[270]=round_tf32(sdn[p]); fo[271]=round_tf32(dsn[p]);
    }
}

__global__ void k_attention(const float* __restrict__ yraw,
                            const float* __restrict__ affS, const float* __restrict__ affQ,
                            const float* __restrict__ gP, const float* __restrict__ bP, float invP,
                            const int* __restrict__ idx, const float* __restrict__ dst_xyz,
                            float* __restrict__ outC, float* __restrict__ att) {
    int bn = blockIdx.x, tid = threadIdx.x;
    __shared__ float fe[KK][256];
    __shared__ float mk[KK], wgt[KK];
    __shared__ int sid[KK];
    if (tid < KK) sid[tid] = idx[(long)bn*KK + tid];
    float mu  = affS[tid] * invP;
    float var = fmaxf(affQ[tid] * invP - mu * mu, 0.f);
    float s   = gP[tid] * rsqrtf(var + BNEPS);
    float h   = bP[tid] - mu * s;
    #pragma unroll
    for (int k = 0; k < KK; k++) {
        float v = yraw[((long)bn*KK + k) * 256 + tid];
        fe[k][tid] = fmaxf(v * s + h, 0.f);
    }
    __syncthreads();
    int w = tid >> 5, lane = tid & 31;
    for (int kk = w; kk < KK; kk += 8) {
        float mx = -3.4e38f;
        for (int c = lane; c < 256; c += 32) mx = fmaxf(mx, fe[kk][c]);
        #pragma unroll
        for (int o = 16; o > 0; o >>= 1) mx = fmaxf(mx, __shfl_down_sync(0xffffffffu, mx, o));
        if (lane == 0) mk[kk] = mx;
    }
    __syncthreads();
    if (tid == 0) {
        float m = -3.4e38f;
        for (int k = 0; k < KK; k++) m = fmaxf(m, mk[k]);
        float ssum = 0.f;
        for (int k = 0; k < KK; k++) { float e = expf(mk[k]-m); wgt[k] = e; ssum += e; }
        float r = 1.f / ssum;
        for (int k = 0; k < KK; k++) wgt[k] *= r;
    }
    __syncthreads();
    float a = 0.f;
    #pragma unroll
    for (int k = 0; k < KK; k++) a += wgt[k] * fe[k][tid];
    att[(long)bn * 256 + tid] = round_tf32(a);   // att only feeds non-affine m1 GEMM
    if (tid < 3) {
        int b = bn >> 11;
        float cg = 0.f;
        #pragma unroll
        for (int k = 0; k < KK; k++)
            cg += wgt[k] * dst_xyz[((long)b*NN + sid[k]) * 3 + tid];
        outC[(long)bn * 3 + tid] = cg;           // final output: full precision
    }
}

__global__ void k_mlp3(const float* __restrict__ yraw,
                       const float* __restrict__ affS, const float* __restrict__ affQ,
                       const float* __restrict__ gP, const float* __restrict__ bP, float invP,
                       const float* __restrict__ w3, const float* __restrict__ b3,
                       float* __restrict__ outw) {
    int bn = blockIdx.x, tid = threadIdx.x;
    float mu  = affS[tid] * invP;
    float var = fmaxf(affQ[tid] * invP - mu * mu, 0.f);
    float s   = gP[tid] * rsqrtf(var + BNEPS);
    float h   = bP[tid] - mu * s;
    float v = fmaxf(yraw[(long)bn*256 + tid] * s + h, 0.f) * w3[tid];
    #pragma unroll
    for (int o = 16; o > 0; o >>= 1) v += __shfl_down_sync(0xffffffffu, v, o);
    __shared__ float ps[8];
    if ((tid & 31) == 0) ps[tid >> 5] = v;
    __syncthreads();
    if (tid == 0) {
        float s2 = 0.f;
        #pragma unroll
        for (int i = 0; i < 8; i++) s2 += ps[i];
        outw[bn] = 1.f / (1.f + expf(-(s2 + b3[0])));
    }
}

extern "C" void kernel_launch(void* const* d_in, const int* in_sizes, int n_in,
                              void* d_out, int out_size) {
    const float* src_xyz  = (const float*)d_in[0];
    const float* src_desc = (const float*)d_in[1];
    const float* dst_xyz  = (const float*)d_in[2];
    const float* dst_desc = (const float*)d_in[3];
    const float* src_w    = (const float*)d_in[4];
    const float* dst_w    = (const float*)d_in[5];
    const float* c1_W0 = (const float*)d_in[6];
    const float* c1_W  = (const float*)d_in[7];
    const float* c1_g  = (const float*)d_in[8];
    const float* c1_b  = (const float*)d_in[9];
    const float* c2_W0 = (const float*)d_in[10];
    const float* c2_W  = (const float*)d_in[11];
    const float* c2_g  = (const float*)d_in[12];
    const float* c2_b  = (const float*)d_in[13];
    const float* m1_W  = (const float*)d_in[14];
    const float* m1_g  = (const float*)d_in[16];
    const float* m1_b  = (const float*)d_in[17];
    const float* m2_W  = (const float*)d_in[18];
    const float* m2_g  = (const float*)d_in[20];
    const float* m2_b  = (const float*)d_in[21];
    const float* m3_W  = (const float*)d_in[22];
    const float* m3_b  = (const float*)d_in[23];

    float* base = nullptr;
    cudaGetSymbolAddress((void**)&base, g_pool);
    float* srcd   = base + F_SRCD;
    float* dstd   = base + F_DSTD;
    float* nsqS   = base + F_NSQS;
    float* nsqD   = base + F_NSQD;
    float* nrmS   = base + F_NRMS;
    float* nrmD   = base + F_NRMD;
    float* maxDS  = base + F_MAXDS;
    float* maxSD  = base + F_MAXSD;
    float* nrm2S  = base + F_NRM2S;
    float* nrm2D  = base + F_NRM2D;
    float* sdc    = base + F_SDC;
    float* dsc    = base + F_DSC;
    float* sdn    = base + F_SDN;
    float* dsn    = base + F_DSN;
    float* stat0  = base + F_STATS;
    float* w2p    = base + F_W2P;
    float* wc2    = base + F_WC2;
    float* wc10   = base + F_WC10;
    float* wc1    = base + F_WC1;
    float* wm1    = base + F_WM1;
    float* wm2    = base + F_WM2;
    int*   idx    = (int*)(base + F_IDX);
    int*   sidx   = (int*)(base + F_SIDX);
    float* att    = base + F_ATT;
    float* mb1    = base + F_MB1;
    float* mb2    = base + F_MB2;
    float* srcnbr = base + F_SRCNBR;
    float* inner  = base + F_INNER;
    float* fbuf   = base + F_F;
    float* y0     = base + F_Y0;
    float* y1     = base + F_Y1;
    float* outC   = (float*)d_out;
    float* outW   = (float*)d_out + (long)BB*NN*3;

    auto slot = [&](int i) { return stat0 + (long)i * 1024; };
    const float invPP = 1.f / (float)PP;
    const float invBN = 1.f / (float)BN;

    // setup: stats zero, weights padded/rounded to tf32
    k_fill<<<32, 256>>>(stat0, 0.f, 8 * 1024);
    k_pad_w<<<128, 144>>>(c2_W0, w2p);
    k_cvt<<<(2*CC*CC+255)/256, 256>>>(c2_W, wc2, 2*CC*CC);
    k_cvt<<<(256*272+255)/256, 256>>>(c1_W0, wc10, 256*272);
    k_cvt<<<(2*256*256+255)/256, 256>>>(c1_W, wc1, 2*256*256);
    k_cvt<<<(256*256+255)/256, 256>>>(m1_W, wm1, 256*256);
    k_cvt<<<(256*256+255)/256, 256>>>(m2_W, wm2, 256*256);

    // A: transpose + norms
    k_transpose_norm<<<dim3(BN, 2), 128>>>(src_desc, dst_desc, srcd, nsqS, nrmS);

    // inner = src . dst with fused cosine maxes
    k_fill<<<32, 256>>>(maxDS, -3.4e38f, 2*BN);
    k_gemm_sim<<<dim3(NN/SGN, NN/SGM, 2), 256>>>(srcd, dstd, inner, nrmS, nrmD, maxDS, maxSD);
    k_knn_desc<<<dim3(NN, BB), 256>>>(inner, nsqS, nsqD, idx);
    k_simgather<<<PP/256, 256>>>(inner, nrmS, nrmD, maxDS, maxSD, idx, sdc, dsc);

    // B: neighborhood descriptors — both clouds batched
    k_knn_xyz<<<dim3(NN, BB, 2), 256>>>(src_xyz, dst_xyz, sidx);
    k_build_nbr_f<<<2*PP, 128>>>(src_xyz, dst_xyz, srcd, sidx, fbuf);
    k_gemm_tc<<<dim3(CC/TCN, (2*PP)/TCM), 256>>>(fbuf, w2p, y0, 2*PP, CC, 144,
        nullptr, nullptr, nullptr, nullptr, 0.f, slot(0), slot(0)+512, PP);
    k_gemm_tc<<<dim3(CC/TCN, (2*PP)/TCM), 256>>>(y0, wc2, y1, 2*PP, CC, CC,
        slot(0), slot(0)+512, c2_g, c2_b, invPP, slot(1), slot(1)+512, PP);
    k_gemm_tc<<<dim3(CC/TCN, (2*PP)/TCM), 256>>>(y1, wc2 + CC*CC, y0, 2*PP, CC, CC,
        slot(1), slot(1)+512, c2_g + CC, c2_b + CC, invPP, slot(2), slot(2)+512, PP);
    k_nbr_final<<<2*BN, 256>>>(y0, slot(2), slot(2)+512, c2_g + 2*CC, c2_b + 2*CC, invPP,
                               sidx, srcd, srcnbr);

    // nbr cosine sims
    k_rownorm<<<2*BN, 128>>>(srcnbr, nrm2S);
    k_fill<<<32, 256>>>(maxDS, -3.4e38f, 2*BN);
    k_gemm_sim<<<dim3(NN/SGN, NN/SGM, 2), 256>>>(srcnbr, srcnbr + (long)BN*CC, inner,
                                                 nrm2S, nrm2D, maxDS, maxSD);
    k_simgather<<<PP/256, 256>>>(inner, nrm2S, nrm2D, maxDS, maxSD, idx, sdn, dsn);

    // C: main feature conv + attention
    k_build_feats<<<PP, 128>>>(src_xyz, dst_xyz, srcd, dstd, src_w, dst_w,
                               sdc, dsc, sdn, dsn, idx, fbuf);
    k_gemm_tc<<<dim3(256/TCN, PP/TCM), 256>>>(fbuf, wc10, y0, PP, 256, 272,
        nullptr, nullptr, nullptr, nullptr, 0.f, slot(3), slot(3)+512, 0);
    k_gemm_tc<<<dim3(256/TCN, PP/TCM), 256>>>(y0, wc1, y1, PP, 256, 256,
        slot(3), slot(3)+512, c1_g, c1_b, invPP, slot(4), slot(4)+512, 0);
    k_gemm_tc<<<dim3(256/TCN, PP/TCM), 256>>>(y1, wc1 + 256*256, y0, PP, 256, 256,
        slot(4), slot(4)+512, c1_g + 256, c1_b + 256, invPP, slot(5), slot(5)+512, 0);
    k_attention<<<BN, 256>>>(y0, slot(5), slot(5)+512, c1_g + 512, c1_b + 512, invPP,
                             idx, dst_xyz, outC, att);

    // D: MLP head
    k_gemm_tc<<<dim3(256/TCN, BN/TCM), 256>>>(att, wm1, mb1, BN, 256, 256,
        nullptr, nullptr, nullptr, nullptr, 0.f, slot(6), slot(6)+512, 0);
    k_gemm_tc<<<dim3(256/TCN, BN/TCM), 256>>>(mb1, wm2, mb2, BN, 256, 256,
        slot(6), slot(6)+512, m1_g, m1_b, invBN, slot(7), slot(7)+512, 0);
    k_mlp3<<<BN, 256>>>(mb2, slot(7), slot(7)+512, m2_g, m2_b, invBN, m3_W, m3_b, outW);
}

// round 14
// speedup vs baseline: 1.5664x; 1.0007x over previous
#include <cuda_runtime.h>
#include <mma.h>
#include <math.h>
#include <float.h>

using namespace nvcuda;

#define BB 2
#define NN 2048
#define CC 128
#define KK 16
#define BN (BB*NN)
#define PP (BB*NN*KK)
#define EPSF 1e-6f
#define BNEPS 1e-5f

// ---------------- scratch pool ----------------
constexpr long F_SRCD   = 0;
constexpr long F_DSTD   = F_SRCD   + (long)BN*CC;
constexpr long F_NSQS   = F_DSTD   + (long)BN*CC;
constexpr long F_NSQD   = F_NSQS   + BN;
constexpr long F_NRMS   = F_NSQD   + BN;
constexpr long F_NRMD   = F_NRMS   + BN;
constexpr long F_MAXDS  = F_NRMD   + BN;
constexpr long F_MAXSD  = F_MAXDS  + BN;
constexpr long F_NRM2S  = F_MAXSD  + BN;
constexpr long F_NRM2D  = F_NRM2S  + BN;
constexpr long F_SDC    = F_NRM2D  + BN;
constexpr long F_DSC    = F_SDC    + PP;
constexpr long F_SDN    = F_DSC    + PP;
constexpr long F_DSN    = F_SDN    + PP;
constexpr long F_STATS  = F_DSN    + PP;            // 8 slots x 1024 (S at +0, Q at +512)
constexpr long F_W2P    = F_STATS  + 8*1024;        // padded+rounded c2_W0 [128][144]
constexpr long F_WC2    = F_W2P    + 128*144;       // rounded c2_W (2 x 128x128)
constexpr long F_WC10   = F_WC2    + 2*CC*CC;       // rounded c1_W0 (256x272)
constexpr long F_WC1    = F_WC10   + 256*272;       // rounded c1_W (2 x 256x256)
constexpr long F_WM1    = F_WC1    + 2*256*256;     // rounded m1_W
constexpr long F_WM2    = F_WM1    + 256*256;       // rounded m2_W
constexpr long F_IDX    = F_WM2    + 256*256;       // int
constexpr long F_SIDX   = F_IDX    + PP;
constexpr long F_DIDX   = F_SIDX   + PP;
constexpr long F_ATT    = F_DIDX   + PP;
constexpr long F_MB1    = F_ATT    + (long)BN*256;
constexpr long F_MB2    = F_MB1    + (long)BN*256;
constexpr long F_SRCNBR = F_MB2    + (long)BN*256;
constexpr long F_DSTNBR = F_SRCNBR + (long)BN*CC;
constexpr long F_INNER  = F_DSTNBR + (long)BN*CC;
constexpr long F_F      = F_INNER  + (long)BB*NN*NN;
constexpr long F_FSZ    = (long)2*PP*144;           // max(PP*272, 2PP*144)
constexpr long F_Y0     = F_F      + F_FSZ;
constexpr long F_Y1     = F_Y0     + (long)PP*256;
constexpr long F_END    = F_Y1     + (long)PP*256;

__device__ __align__(128) float g_pool[F_END];

__device__ __forceinline__ void atomicMaxF(float* a, float v) {
    if (!(v < 0.f)) atomicMax((int*)a, __float_as_int(v));
    else            atomicMin((unsigned int*)a, __float_as_uint(v));
}

__device__ __forceinline__ unsigned cvt_tf32(float x) {
    unsigned u;
    asm("cvt.rn.tf32.f32 %0, %1;" : "=r"(u) : "f"(x));
    return u;
}
__device__ __forceinline__ float round_tf32(float x) {
    return __uint_as_float(cvt_tf32(x));
}

__device__ __forceinline__ void cp_async16(unsigned saddr, const void* gptr) {
    asm volatile("cp.async.ca.shared.global [%0], [%1], 16;" :: "r"(saddr), "l"(gptr));
}
__device__ __forceinline__ void cp_commit() { asm volatile("cp.async.commit_group;"); }
template<int N> __device__ __forceinline__ void cp_wait() {
    asm volatile("cp.async.wait_group %0;" :: "n"(N));
}

__global__ void k_fill(float* __restrict__ p, float v, int n) {
    int i = blockIdx.x * blockDim.x + threadIdx.x;
    if (i < n) p[i] = v;
}

// round-copy weights to tf32
__global__ void k_cvt(const float* __restrict__ in, float* __restrict__ out, int n) {
    int i = blockIdx.x * blockDim.x + threadIdx.x;
    if (i < n) out[i] = round_tf32(in[i]);
}

__global__ void k_pad_w(const float* __restrict__ W, float* __restrict__ Wp) {
    int o = blockIdx.x; int k = threadIdx.x; // 144 threads
    Wp[o * 144 + k] = (k < 132) ? round_tf32(W[o * 132 + k]) : 0.f;
}

// both clouds: [B,C,N] -> [B,N,C] plus |.|^2 and |.|
__global__ void k_transpose_norm(const float* __restrict__ descS, const float* __restrict__ descD,
                                 float* __restrict__ dmatAll, float* __restrict__ nsqAll,
                                 float* __restrict__ nrmAll) {
    int cloud = blockIdx.y;
    const float* desc = cloud ? descD : descS;
    float* dmat = dmatAll + (long)cloud*BN*CC;
    float* nsq  = nsqAll  + cloud*BN;
    float* nrm  = nrmAll  + cloud*BN;
    int bn = blockIdx.x; int b = bn >> 11; int n = bn & (NN - 1);
    int c = threadIdx.x;
    float v = desc[((long)b*CC + c)*NN + n];
    dmat[(long)bn*CC + c] = v;
    float s = v * v;
    #pragma unroll
    for (int o = 16; o > 0; o >>= 1) s += __shfl_down_sync(0xffffffffu, s, o);
    __shared__ float ps[4];
    if ((c & 31) == 0) ps[c >> 5] = s;
    __syncthreads();
    if (c == 0) { float t = ps[0]+ps[1]+ps[2]+ps[3]; nsq[bn] = t; nrm[bn] = sqrtf(t); }
}

__global__ void k_rownorm(const float* __restrict__ dmat, float* __restrict__ nrm) {
    int bn = blockIdx.x; int c = threadIdx.x;
    float v = dmat[(long)bn*CC + c];
    float s = v * v;
    #pragma unroll
    for (int o = 16; o > 0; o >>= 1) s += __shfl_down_sync(0xffffffffu, s, o);
    __shared__ float ps[4];
    if ((c & 31) == 0) ps[c >> 5] = s;
    __syncthreads();
    if (c == 0) nrm[bn] = sqrtf(ps[0]+ps[1]+ps[2]+ps[3]);
}

// ---------------- split-tf32 sim GEMM: 3-stage cp.async, reg-side hi/lo ----------
#define SGM 128
#define SGN 64
#define SLD 20
#define SCLD 68
#define SSTG ((SGM+SGN)*SLD)   // 3840 floats per stage

__global__ __launch_bounds__(256, 3)
void k_gemm_sim(const float* __restrict__ A, const float* __restrict__ Bm,
                float* __restrict__ Cm,
                const float* __restrict__ nrmA, const float* __restrict__ nrmB,
                float* __restrict__ maxDS, float* __restrict__ maxSD) {
    const int b = blockIdx.z;
    A  += (long)b * NN * CC;
    Bm += (long)b * NN * CC;
    Cm += (long)b * NN * NN;

    __shared__ __align__(16) float smem[3 * SSTG];   // 46080B; Csm (34816B) unioned
    float* Csm = smem;
    __shared__ float rns[SGM], rnd[SGN], rm[SGM], cmx[SGN];

    const int tid = threadIdx.x;
    const int lane = tid & 31;
    const int g   = lane >> 2;
    const int tig = lane & 3;
    const int wid = tid >> 5;
    const int wm = wid & 3;
    const int wn = wid >> 2;
    const long rowBase = (long)blockIdx.y * SGM;
    const int colBase = blockIdx.x * SGN;

    if (tid < SGM) { rns[tid] = nrmA[b*NN + rowBase + tid]; rm[tid] = -3.4e38f; }
    if (tid < SGN) { rnd[tid] = nrmB[b*NN + colBase + tid]; cmx[tid] = -3.4e38f; }

    const int srow = tid >> 2;
    const int kq = (tid & 3) * 4;
    unsigned sbase;
    asm("{ .reg .u64 t; cvta.to.shared.u64 t, %1; cvt.u32.u64 %0, t; }"
        : "=r"(sbase) : "l"(smem));

    auto issue = [&](int kc) {
        int buf = kc % 3;
        int k0 = kc * 16;
        const float* ga0 = &A[(rowBase + srow) * CC + k0 + kq];
        const float* ga1 = &A[(rowBase + srow + 64) * CC + k0 + kq];
        const float* gb  = &Bm[(long)(colBase + srow) * CC + k0 + kq];
        unsigned base = sbase + (unsigned)(buf * SSTG * 4);
        unsigned da0 = base + (unsigned)((srow * SLD + kq) * 4);
        unsigned da1 = da0 + 64u * SLD * 4u;
        unsigned db  = base + (unsigned)((SGM * SLD + srow * SLD + kq) * 4);
        cp_async16(da0, ga0);
        cp_async16(da1, ga1);
        cp_async16(db, gb);
        cp_commit();
    };

    float acc[2][4][4];
    #pragma unroll
    for (int i = 0; i < 2; i++)
        #pragma unroll
        for (int j = 0; j < 4; j++)
            #pragma unroll
            for (int t = 0; t < 4; t++)
                acc[i][j][t] = 0.f;

    const int nk = CC / 16;
    issue(0);
    issue(1);

    for (int kc = 0; kc < nk; kc++) {
        cp_wait<1>();
        __syncthreads();
        if (kc + 2 < nk) issue(kc + 2);
        const float* As = smem + (kc % 3) * SSTG;
        const float* Bs = As + SGM * SLD;
        #pragma unroll
        for (int ks = 0; ks < 2; ks++) {
            const int kb = ks * 8;
            unsigned bh0[4], bh1[4], bl0[4], bl1[4];
            #pragma unroll
            for (int nj = 0; nj < 4; nj++) {
                int nb = wn * 32 + nj * 8 + g;
                float w0 = Bs[nb * SLD + kb + tig];
                float w1 = Bs[nb * SLD + kb + tig + 4];
                unsigned h0 = cvt_tf32(w0), h1 = cvt_tf32(w1);
                bh0[nj] = h0; bh1[nj] = h1;
                bl0[nj] = cvt_tf32(w0 - __uint_as_float(h0));
                bl1[nj] = cvt_tf32(w1 - __uint_as_float(h1));
            }
            #pragma unroll
            for (int mi = 0; mi < 2; mi++) {
                int ar = wm * 32 + mi * 16;
                float v0 = As[(ar + g    ) * SLD + kb + tig];
                float v1 = As[(ar + g + 8) * SLD + kb + tig];
                float v2 = As[(ar + g    ) * SLD + kb + tig + 4];
                float v3 = As[(ar + g + 8) * SLD + kb + tig + 4];
                unsigned ah0 = cvt_tf32(v0), ah1 = cvt_tf32(v1);
                unsigned ah2 = cvt_tf32(v2), ah3 = cvt_tf32(v3);
                unsigned al0 = cvt_tf32(v0 - __uint_as_float(ah0));
                unsigned al1 = cvt_tf32(v1 - __uint_as_float(ah1));
                unsigned al2 = cvt_tf32(v2 - __uint_as_float(ah2));
                unsigned al3 = cvt_tf32(v3 - __uint_as_float(ah3));
                #pragma unroll
                for (int nj = 0; nj < 4; nj++) {
                    asm volatile(
                        "mma.sync.aligned.m16n8k8.row.col.f32.tf32.tf32.f32 "
                        "{%0,%1,%2,%3}, {%4,%5,%6,%7}, {%8,%9}, {%0,%1,%2,%3};"
                        : "+f"(acc[mi][nj][0]), "+f"(acc[mi][nj][1]),
                          "+f"(acc[mi][nj][2]), "+f"(acc[mi][nj][3])
                        : "r"(ah0), "r"(ah1), "r"(ah2), "r"(ah3),
                          "r"(bh0[nj]), "r"(bh1[nj]));
                    asm volatile(
                        "mma.sync.aligned.m16n8k8.row.col.f32.tf32.tf32.f32 "
                        "{%0,%1,%2,%3}, {%4,%5,%6,%7}, {%8,%9}, {%0,%1,%2,%3};"
                        : "+f"(acc[mi][nj][0]), "+f"(acc[mi][nj][1]),
                          "+f"(acc[mi][nj][2]), "+f"(acc[mi][nj][3])
                        : "r"(ah0), "r"(ah1), "r"(ah2), "r"(ah3),
                          "r"(bl0[nj]), "r"(bl1[nj]));
                    asm volatile(
                        "mma.sync.aligned.m16n8k8.row.col.f32.tf32.tf32.f32 "
                        "{%0,%1,%2,%3}, {%4,%5,%6,%7}, {%8,%9}, {%0,%1,%2,%3};"
                        : "+f"(acc[mi][nj][0]), "+f"(acc[mi][nj][1]),
                          "+f"(acc[mi][nj][2]), "+f"(acc[mi][nj][3])
                        : "r"(al0), "r"(al1), "r"(al2), "r"(al3),
                          "r"(bh0[nj]), "r"(bh1[nj]));
                }
            }
        }
    }
    __syncthreads();   // staging buffers now alias Csm

    #pragma unroll
    for (int mi = 0; mi < 2; mi++) {
        int r0r = wm * 32 + mi * 16 + g;
        #pragma unroll
        for (int nj = 0; nj < 4; nj++) {
            int c0 = wn * 32 + nj * 8 + 2 * tig;
            Csm[r0r * SCLD + c0]           = acc[mi][nj][0];
            Csm[r0r * SCLD + c0 + 1]       = acc[mi][nj][1];
            Csm[(r0r + 8) * SCLD + c0]     = acc[mi][nj][2];
            Csm[(r0r + 8) * SCLD + c0 + 1] = acc[mi][nj][3];
        }
    }
    __syncthreads();

    const int ccol = tid & 63;
    const int r0 = tid >> 6;
    const float nd = rnd[ccol];
    float colmax = -3.4e38f;
    #pragma unroll 8
    for (int it = 0; it < 32; it++) {
        int r = r0 + it * 4;
        float v = Csm[r * SCLD + ccol];
        Cm[(rowBase + r) * NN + colBase + ccol] = v;
        float csv = v / (nd * rns[r] + EPSF);
        colmax = fmaxf(colmax, csv);
        float wmx = csv;
        #pragma unroll
        for (int o = 16; o > 0; o >>= 1) wmx = fmaxf(wmx, __shfl_down_sync(0xffffffffu, wmx, o));
        if (lane == 0) atomicMaxF(&rm[r], wmx);
    }
    atomicMaxF(&cmx[ccol], colmax);
    __syncthreads();
    if (tid < SGM) atomicMaxF(&maxDS[b*NN + rowBase + tid], rm[tid]);
    else if (tid < SGM + SGN) atomicMaxF(&maxSD[b*NN + colBase + (tid - SGM)], cmx[tid - SGM]);
}

// ---------------- TF32 conv GEMM v4: 3-stage cp.async, pre-rounded B (and A when !aff) ----
// REQUIREMENT: Bm is tf32-pre-rounded. When affS==null, A must be tf32-pre-rounded too.
#define TCM 128
#define TCN 64
#define ALD 20
#define CLD 68
#define TSTG ((TCM+TCN)*ALD)

__global__ __launch_bounds__(256, 3)
void k_gemm_tc(const float* __restrict__ A, const float* __restrict__ Bm,
               float* __restrict__ Cm, int P, int O, int Kd,
               const float* __restrict__ affS, const float* __restrict__ affQ,
               const float* __restrict__ gP, const float* __restrict__ bP, float invP,
               float* __restrict__ statS, float* __restrict__ statQ, int splitRows) {
    __shared__ __align__(16) float smem[3 * TSTG];   // 46080B; Csm unioned
    float* Csm = smem;
    __shared__ float cs[TCN], cq[TCN];
    __shared__ float sSc[256], sSh[256];

    const int tid = threadIdx.x;
    const int lane = tid & 31;
    const int g   = lane >> 2;
    const int tig = lane & 3;
    const int wid = tid >> 5;
    const int wm = wid & 3;
    const int wn = wid >> 2;
    const int rowBase = blockIdx.y * TCM;
    const int colBase = blockIdx.x * TCN;
    const bool aff = (affS != nullptr);
    const bool stats = (statS != nullptr);
    const int cloudA = (splitRows > 0 && rowBase >= splitRows) ? 1 : 0;
    const int statOff = cloudA * O;

    if (aff && tid < Kd && tid < 256) {
        int so = cloudA * Kd + tid;
        float mu  = affS[so] * invP;
        float var = fmaxf(affQ[so] * invP - mu * mu, 0.f);
        float s   = gP[tid] * rsqrtf(var + BNEPS);
        sSc[tid] = s;
        sSh[tid] = bP[tid] - mu * s;
    }
    if (stats && tid < TCN) { cs[tid] = 0.f; cq[tid] = 0.f; }

    const int srow = tid >> 2;
    const int kq = (tid & 3) * 4;
    unsigned sbase;
    asm("{ .reg .u64 t; cvta.to.shared.u64 t, %1; cvt.u32.u64 %0, t; }"
        : "=r"(sbase) : "l"(smem));

    auto issue = [&](int kc) {
        int buf = kc % 3;
        int k0 = kc * 16;
        const float* ga0 = &A[(long)(rowBase + srow) * Kd + k0 + kq];
        const float* ga1 = &A[(long)(rowBase + srow + 64) * Kd + k0 + kq];
        const float* gb  = &Bm[(long)(colBase + srow) * Kd + k0 + kq];
        unsigned base = sbase + (unsigned)(buf * TSTG * 4);
        unsigned da0 = base + (unsigned)((srow * ALD + kq) * 4);
        unsigned da1 = da0 + 64u * ALD * 4u;
        unsigned db  = base + (unsigned)((TCM * ALD + srow * ALD + kq) * 4);
        cp_async16(da0, ga0);
        cp_async16(da1, ga1);
        cp_async16(db, gb);
        cp_commit();
    };

    float acc[2][4][4];
    #pragma unroll
    for (int i = 0; i < 2; i++)
        #pragma unroll
        for (int j = 0; j < 4; j++)
            #pragma unroll
            for (int t = 0; t < 4; t++)
                acc[i][j][t] = 0.f;

    const int nk = Kd / 16;
    issue(0);
    issue(1);

    for (int kc = 0; kc < nk; kc++) {
        cp_wait<1>();
        __syncthreads();
        if (kc + 2 < nk) issue(kc + 2);
        const float* As = smem + (kc % 3) * TSTG;
        const float* Bs = As + TCM * ALD;
        const int k0 = kc * 16;
        #pragma unroll
        for (int ks = 0; ks < 2; ks++) {
            const int kb = ks * 8;
            // B: pre-rounded tf32 -> direct bit reinterpret
            unsigned b0[4], b1[4];
            #pragma unroll
            for (int nj = 0; nj < 4; nj++) {
                int nb = wn * 32 + nj * 8 + g;
                b0[nj] = __float_as_uint(Bs[nb * ALD + kb + tig]);
                b1[nj] = __float_as_uint(Bs[nb * ALD + kb + tig + 4]);
            }
            float sc0 = 1.f, sh0 = 0.f, sc4 = 1.f, sh4 = 0.f;
            if (aff) {
                sc0 = sSc[k0 + kb + tig];     sh0 = sSh[k0 + kb + tig];
                sc4 = sSc[k0 + kb + tig + 4]; sh4 = sSh[k0 + kb + tig + 4];
            }
            #pragma unroll
            for (int mi = 0; mi < 2; mi++) {
                int ar = wm * 32 + mi * 16;
                float v0 = As[(ar + g    ) * ALD + kb + tig];
                float v1 = As[(ar + g + 8) * ALD + kb + tig];
                float v2 = As[(ar + g    ) * ALD + kb + tig + 4];
                float v3 = As[(ar + g + 8) * ALD + kb + tig + 4];
                unsigned a0, a1, a2, a3;
                if (aff) {
                    a0 = cvt_tf32(fmaxf(v0 * sc0 + sh0, 0.f));
                    a1 = cvt_tf32(fmaxf(v1 * sc0 + sh0, 0.f));
                    a2 = cvt_tf32(fmaxf(v2 * sc4 + sh4, 0.f));
                    a3 = cvt_tf32(fmaxf(v3 * sc4 + sh4, 0.f));
                } else {
                    a0 = __float_as_uint(v0);
                    a1 = __float_as_uint(v1);
                    a2 = __float_as_uint(v2);
                    a3 = __float_as_uint(v3);
                }
                #pragma unroll
                for (int nj = 0; nj < 4; nj++) {
                    asm volatile(
                        "mma.sync.aligned.m16n8k8.row.col.f32.tf32.tf32.f32 "
                        "{%0,%1,%2,%3}, {%4,%5,%6,%7}, {%8,%9}, {%0,%1,%2,%3};"
                        : "+f"(acc[mi][nj][0]), "+f"(acc[mi][nj][1]),
                          "+f"(acc[mi][nj][2]), "+f"(acc[mi][nj][3])
                        : "r"(a0), "r"(a1), "r"(a2), "r"(a3),
                          "r"(b0[nj]), "r"(b1[nj]));
                }
            }
        }
    }
    __syncthreads();   // staging aliases Csm

    #pragma unroll
    for (int mi = 0; mi < 2; mi++) {
        int r0r = wm * 32 + mi * 16 + g;
        #pragma unroll
        for (int nj = 0; nj < 4; nj++) {
            int c0 = wn * 32 + nj * 8 + 2 * tig;
            Csm[r0r * CLD + c0]           = acc[mi][nj][0];
            Csm[r0r * CLD + c0 + 1]       = acc[mi][nj][1];
            Csm[(r0r + 8) * CLD + c0]     = acc[mi][nj][2];
            Csm[(r0r + 8) * CLD + c0 + 1] = acc[mi][nj][3];
        }
    }
    __syncthreads();

    const int ccol = tid & 63;
    const int r0 = tid >> 6;
    float s = 0.f, q = 0.f;
    #pragma unroll 8
    for (int it = 0; it < 32; it++) {
        int r = r0 + it * 4;
        float v = Csm[r * CLD + ccol];
        Cm[(long)(rowBase + r) * O + colBase + ccol] = v;
        s += v; q += v * v;
    }
    if (stats) {
        atomicAdd(&cs[ccol], s);
        atomicAdd(&cq[ccol], q);
        __syncthreads();
        if (tid < TCN) {
            atomicAdd(&statS[statOff + colBase + tid], cs[tid]);
            atomicAdd(&statQ[statOff + colBase + tid], cq[tid]);
        }
    }
}

// top-16 smallest from shared d2[NN], 256 threads
__device__ void select_topk(float* d2, int* outIdx) {
    __shared__ float rv[8];
    __shared__ int   ri[8];
    int tid = threadIdx.x, lane = tid & 31, w = tid >> 5;
    for (int kk = 0; kk < KK; kk++) {
        float best = 3.4e38f; int bi = 0;
        for (int m = tid; m < NN; m += 256) {
            float v = d2[m];
            if (v < best) { best = v; bi = m; }
        }
        #pragma unroll
        for (int o = 16; o > 0; o >>= 1) {
            float ov = __shfl_down_sync(0xffffffffu, best, o);
            int   oi = __shfl_down_sync(0xffffffffu, bi, o);
            if (ov < best || (ov == best && oi < bi)) { best = ov; bi = oi; }
        }
        if (lane == 0) { rv[w] = best; ri[w] = bi; }
        __syncthreads();
        if (tid == 0) {
            float bv = rv[0]; int bj = ri[0];
            #pragma unroll
            for (int i = 1; i < 8; i++)
                if (rv[i] < bv || (rv[i] == bv && ri[i] < bj)) { bv = rv[i]; bj = ri[i]; }
            outIdx[kk] = bj;
            d2[bj] = 3.4e38f;
        }
        __syncthreads();
    }
}

__global__ void k_knn_desc(const float* __restrict__ inner, const float* __restrict__ nsqS,
                           const float* __restrict__ nsqD, int* __restrict__ idxOut) {
    int n = blockIdx.x, b = blockIdx.y;
    __shared__ float d2[NN];
    const float* row = inner + (long)b*NN*NN + (long)n*NN;
    float q = nsqS[b*NN + n];
    for (int m = threadIdx.x; m < NN; m += 256) d2[m] = q + nsqD[b*NN + m] - 2.f * row[m];
    __syncthreads();
    select_topk(d2, idxOut + ((long)b*NN + n) * KK);
}

__global__ void k_knn_xyz(const float* __restrict__ xyzS, const float* __restrict__ xyzD,
                          int* __restrict__ idxAll) {
    int n = blockIdx.x, b = blockIdx.y, cloud = blockIdx.z;
    const float* xyz = cloud ? xyzD : xyzS;
    int* idxOut = idxAll + (long)cloud*PP;
    __shared__ float d2[NN];
    long base = (long)b * NN * 3;
    float qx = xyz[base + (long)n*3], qy = xyz[base + (long)n*3+1], qz = xyz[base + (long)n*3+2];
    float qq = qx*qx + qy*qy + qz*qz;
    for (int m = threadIdx.x; m < NN; m += 256) {
        float rx = xyz[base + (long)m*3], ry = xyz[base + (long)m*3+1], rz = xyz[base + (long)m*3+2];
        d2[m] = qq + rx*rx + ry*ry + rz*rz - 2.f*(qx*rx + qy*ry + qz*rz);
    }
    __syncthreads();
    select_topk(d2, idxOut + ((long)b*NN + n) * KK);
}

__global__ void k_simgather(const float* __restrict__ inner, const float* __restrict__ nrmS,
                            const float* __restrict__ nrmD, const float* __restrict__ maxDS,
                            const float* __restrict__ maxSD, const int* __restrict__ idx,
                            float* __restrict__ outSD, float* __restrict__ outDS) {
    int t = blockIdx.x * 256 + threadIdx.x;
    if (t >= PP) return;
    int b = t / (NN * KK);
    int n = (t / KK) & (NN - 1);
    int m = idx[t];
    float v  = inner[(long)b*NN*NN + (long)n*NN + m];
    float cs = v / (nrmD[b*NN + m] * nrmS[b*NN + n] + EPSF);
    outSD[t] = cs / (maxDS[b*NN + n] + EPSF);
    outDS[t] = cs / (maxSD[b*NN + m] + EPSF);
}

// both clouds: nbr conv input, tf32-ROUNDED (feeds non-affine GEMM)
__global__ void k_build_nbr_f(const float* __restrict__ xyzS, const float* __restrict__ xyzD,
                              const float* __restrict__ dmatAll, const int* __restrict__ idxAll,
                              float* __restrict__ f) {
    int p = blockIdx.x;
    int cloud = p >= PP;
    int pl = p - cloud * PP;
    const float* xyz = cloud ? xyzD : xyzS;
    const float* dmatC = dmatAll + (long)cloud*BN*CC;
    int n = (pl / KK) & (NN - 1);
    int b = pl / (NN * KK);
    int m = idxAll[p];
    const float* dr = dmatC + ((long)b*NN + m) * CC;
    float* fo = f + (long)p * 144;
    int tid = threadIdx.x;
    fo[tid] = round_tf32(dr[tid]);
    if (tid == 0) {
        long qb = ((long)b*NN + n) * 3, rb = ((long)b*NN + m) * 3;
        float rx = xyz[rb]-xyz[qb], ry = xyz[rb+1]-xyz[qb+1], rz = xyz[rb+2]-xyz[qb+2];
        fo[128] = round_tf32(rx); fo[129] = round_tf32(ry); fo[130] = round_tf32(rz);
        fo[131] = round_tf32(sqrtf(rx*rx+ry*ry+rz*rz));
        #pragma unroll
        for (int z = 132; z < 144; z++) fo[z] = 0.f;
    }
}

// both clouds: grid 2*BN, in-block affine from producer stats
__global__ void k_nbr_final(const float* __restrict__ yraw,
                            const float* __restrict__ affS, const float* __restrict__ affQ,
                            const float* __restrict__ gP, const float* __restrict__ bP, float invP,
                            const int* __restrict__ idxAll,
                            const float* __restrict__ dmatAll, float* __restrict__ outAll) {
    int gblk = blockIdx.x;
    int cloud = gblk >= BN;
    int bn = gblk - cloud * BN;
    const float* y = yraw + (long)cloud*PP*CC;
    const int* idx = idxAll + (long)cloud*PP;
    const float* dmat = dmatAll + (long)cloud*BN*CC;
    float* outN = outAll + (long)cloud*BN*CC;
    int tid = threadIdx.x;
    __shared__ float fe[KK][CC];
    __shared__ float mk[KK], wgt[KK];
    __shared__ int sid[KK];
    __shared__ float sSc[CC], sSh[CC];
    if (tid < CC) {
        int so = cloud * CC + tid;
        float mu  = affS[so] * invP;
        float var = fmaxf(affQ[so] * invP - mu * mu, 0.f);
        float s   = gP[tid] * rsqrtf(var + BNEPS);
        sSc[tid] = s;
        sSh[tid] = bP[tid] - mu * s;
    }
    if (tid < KK) sid[tid] = idx[(long)bn*KK + tid];
    __syncthreads();
    for (int t = tid; t < KK * CC; t += 256) {
        int k = t >> 7, c = t & 127;
        float v = y[((long)bn*KK + k) * CC + c];
        fe[k][c] = fmaxf(v * sSc[c] + sSh[c], 0.f);
    }
    __syncthreads();
    int w = tid >> 5, lane = tid & 31;
    for (int kk = w; kk < KK; kk += 8) {
        float mx = -3.4e38f;
        for (int c = lane; c < CC; c += 32) mx = fmaxf(mx, fe[kk][c]);
        #pragma unroll
        for (int o = 16; o > 0; o >>= 1) mx = fmaxf(mx, __shfl_down_sync(0xffffffffu, mx, o));
        if (lane == 0) mk[kk] = mx;
    }
    __syncthreads();
    if (tid == 0) {
        float m = -3.4e38f;
        for (int k = 0; k < KK; k++) m = fmaxf(m, mk[k]);
        float s = 0.f;
        for (int k = 0; k < KK; k++) { float e = expf(mk[k]-m); wgt[k] = e; s += e; }
        float r = 1.f / s;
        for (int k = 0; k < KK; k++) wgt[k] *= r;
    }
    __syncthreads();
    if (tid < CC) {
        int b = bn >> 11;
        float a = 0.f;
        #pragma unroll
        for (int k = 0; k < KK; k++) a += wgt[k] * dmat[((long)b*NN + sid[k]) * CC + tid];
        outN[(long)bn*CC + tid] = a;
    }
}

// main feats build (272 ch), tf32-ROUNDED (feeds non-affine GEMM)
__global__ void k_build_feats(const float* __restrict__ src_xyz, const float* __restrict__ dst_xyz,
                              const float* __restrict__ srcd, const float* __restrict__ dstd,
                              const float* __restrict__ srcw, const float* __restrict__ dstw,
                              const float* __restrict__ sdc, const float* __restrict__ dsc,
                              const float* __restrict__ sdn, const float* __restrict__ dsn,
                              const int* __restrict__ idx, float* __restrict__ feats) {
    int p = blockIdx.x;
    int n = (p / KK) & (NN - 1);
    int b = p / (NN * KK);
    int m = idx[p];
    float* fo = feats + (long)p * 272;
    int tid = threadIdx.x;
    fo[10 + tid]  = round_tf32(srcd[((long)b*NN + n) * CC + tid]);
    fo[138 + tid] = round_tf32(dstd[((long)b*NN + m) * CC + tid]);
    if (tid == 0) {
        long qb = ((long)b*NN + n) * 3, rb = ((long)b*NN + m) * 3;
        float sx = src_xyz[qb], sy = src_xyz[qb+1], sz = src_xyz[qb+2];
        float kx = dst_xyz[rb], ky = dst_xyz[rb+1], kz = dst_xyz[rb+2];
        float rx = kx-sx, ry = ky-sy, rz = kz-sz;
        fo[0]=round_tf32(rx); fo[1]=round_tf32(ry); fo[2]=round_tf32(rz);
        fo[3]=round_tf32(sqrtf(rx*rx+ry*ry+rz*rz));
        fo[4]=round_tf32(sx); fo[5]=round_tf32(sy); fo[6]=round_tf32(sz);
        fo[7]=round_tf32(kx); fo[8]=round_tf32(ky); fo[9]=round_tf32(kz);
        fo[266]=round_tf32(srcw[b*NN+n]); fo[267]=round_tf32(dstw[b*NN+m]);
        fo[268]=round_tf32(sdc[p]); fo[269]=round_tf32(dsc[p]);
        fo[270]=round_tf32(sdn[p]); fo[271]=round_tf32(dsn[p]);
    }
}

__global__ void k_attention(const float* __restrict__ yraw,
                            const float* __restrict__ affS, const float* __restrict__ affQ,
                            const float* __restrict__ gP, const float* __restrict__ bP, float invP,
                            const int* __restrict__ idx, const float* __restrict__ dst_xyz,
                            float* __restrict__ outC, float* __restrict__ att) {
    int bn = blockIdx.x, tid = threadIdx.x;
    __shared__ float fe[KK][256];
    __shared__ float mk[KK], wgt[KK];
    __shared__ int sid[KK];
    if (tid < KK) sid[tid] = idx[(long)bn*KK + tid];
    float mu  = affS[tid] * invP;
    float var = fmaxf(affQ[tid] * invP - mu * mu, 0.f);
    float s   = gP[tid] * rsqrtf(var + BNEPS);
    float h   = bP[tid] - mu * s;
    #pragma unroll
    for (int k = 0; k < KK; k++) {
        float v = yraw[((long)bn*KK + k) * 256 + tid];
        fe[k][tid] = fmaxf(v * s + h, 0.f);
    }
    __syncthreads();
    int w = tid >> 5, lane = tid & 31;
    for (int kk = w; kk < KK; kk += 8) {
        float mx = -3.4e38f;
        for (int c = lane; c < 256; c += 32) mx = fmaxf(mx, fe[kk][c]);
        #pragma unroll
        for (int o = 16; o > 0; o >>= 1) mx = fmaxf(mx, __shfl_down_sync(0xffffffffu, mx, o));
        if (lane == 0) mk[kk] = mx;
    }
    __syncthreads();
    if (tid == 0) {
        float m = -3.4e38f;
        for (int k = 0; k < KK; k++) m = fmaxf(m, mk[k]);
        float ssum = 0.f;
        for (int k = 0; k < KK; k++) { float e = expf(mk[k]-m); wgt[k] = e; ssum += e; }
        float r = 1.f / ssum;
        for (int k = 0; k < KK; k++) wgt[k] *= r;
    }
    __syncthreads();
    float a = 0.f;
    #pragma unroll
    for (int k = 0; k < KK; k++) a += wgt[k] * fe[k][tid];
    att[(long)bn * 256 + tid] = round_tf32(a);   // att only feeds non-affine m1 GEMM
    if (tid < 3) {
        int b = bn >> 11;
        float cg = 0.f;
        #pragma unroll
        for (int k = 0; k < KK; k++)
            cg += wgt[k] * dst_xyz[((long)b*NN + sid[k]) * 3 + tid];
        outC[(long)bn * 3 + tid] = cg;           // final output: full precision
    }
}

__global__ void k_mlp3(const float* __restrict__ yraw,
                       const float* __restrict__ affS, const float* __restrict__ affQ,
                       const float* __restrict__ gP, const float* __restrict__ bP, float invP,
                       const float* __restrict__ w3, const float* __restrict__ b3,
                       float* __restrict__ outw) {
    int bn = blockIdx.x, tid = threadIdx.x;
    float mu  = affS[tid] * invP;
    float var = fmaxf(affQ[tid] * invP - mu * mu, 0.f);
    float s   = gP[tid] * rsqrtf(var + BNEPS);
    float h   = bP[tid] - mu * s;
    float v = fmaxf(yraw[(long)bn*256 + tid] * s + h, 0.f) * w3[tid];
    #pragma unroll
    for (int o = 16; o > 0; o >>= 1) v += __shfl_down_sync(0xffffffffu, v, o);
    __shared__ float ps[8];
    if ((tid & 31) == 0) ps[tid >> 5] = v;
    __syncthreads();
    if (tid == 0) {
        float s2 = 0.f;
        #pragma unroll
        for (int i = 0; i < 8; i++) s2 += ps[i];
        outw[bn] = 1.f / (1.f + expf(-(s2 + b3[0])));
    }
}

extern "C" void kernel_launch(void* const* d_in, const int* in_sizes, int n_in,
                              void* d_out, int out_size) {
    const float* src_xyz  = (const float*)d_in[0];
    const float* src_desc = (const float*)d_in[1];
    const float* dst_xyz  = (const float*)d_in[2];
    const float* dst_desc = (const float*)d_in[3];
    const float* src_w    = (const float*)d_in[4];
    const float* dst_w    = (const float*)d_in[5];
    const float* c1_W0 = (const float*)d_in[6];
    const float* c1_W  = (const float*)d_in[7];
    const float* c1_g  = (const float*)d_in[8];
    const float* c1_b  = (const float*)d_in[9];
    const float* c2_W0 = (const float*)d_in[10];
    const float* c2_W  = (const float*)d_in[11];
    const float* c2_g  = (const float*)d_in[12];
    const float* c2_b  = (const float*)d_in[13];
    const float* m1_W  = (const float*)d_in[14];
    const float* m1_g  = (const float*)d_in[16];
    const float* m1_b  = (const float*)d_in[17];
    const float* m2_W  = (const float*)d_in[18];
    const float* m2_g  = (const float*)d_in[20];
    const float* m2_b  = (const float*)d_in[21];
    const float* m3_W  = (const float*)d_in[22];
    const float* m3_b  = (const float*)d_in[23];

    float* base = nullptr;
    cudaGetSymbolAddress((void**)&base, g_pool);
    float* srcd   = base + F_SRCD;
    float* dstd   = base + F_DSTD;
    float* nsqS   = base + F_NSQS;
    float* nsqD   = base + F_NSQD;
    float* nrmS   = base + F_NRMS;
    float* nrmD   = base + F_NRMD;
    float* maxDS  = base + F_MAXDS;
    float* maxSD  = base + F_MAXSD;
    float* nrm2S  = base + F_NRM2S;
    float* nrm2D  = base + F_NRM2D;
    float* sdc    = base + F_SDC;
    float* dsc    = base + F_DSC;
    float* sdn    = base + F_SDN;
    float* dsn    = base + F_DSN;
    float* stat0  = base + F_STATS;
    float* w2p    = base + F_W2P;
    float* wc2    = base + F_WC2;
    float* wc10   = base + F_WC10;
    float* wc1    = base + F_WC1;
    float* wm1    = base + F_WM1;
    float* wm2    = base + F_WM2;
    int*   idx    = (int*)(base + F_IDX);
    int*   sidx   = (int*)(base + F_SIDX);
    float* att    = base + F_ATT;
    float* mb1    = base + F_MB1;
    float* mb2    = base + F_MB2;
    float* srcnbr = base + F_SRCNBR;
    float* inner  = base + F_INNER;
    float* fbuf   = base + F_F;
    float* y0     = base + F_Y0;
    float* y1     = base + F_Y1;
    float* outC   = (float*)d_out;
    float* outW   = (float*)d_out + (long)BB*NN*3;

    auto slot = [&](int i) { return stat0 + (long)i * 1024; };
    const float invPP = 1.f / (float)PP;
    const float invBN = 1.f / (float)BN;

    // setup: stats zero, weights padded/rounded to tf32
    k_fill<<<32, 256>>>(stat0, 0.f, 8 * 1024);
    k_pad_w<<<128, 144>>>(c2_W0, w2p);
    k_cvt<<<(2*CC*CC+255)/256, 256>>>(c2_W, wc2, 2*CC*CC);
    k_cvt<<<(256*272+255)/256, 256>>>(c1_W0, wc10, 256*272);
    k_cvt<<<(2*256*256+255)/256, 256>>>(c1_W, wc1, 2*256*256);
    k_cvt<<<(256*256+255)/256, 256>>>(m1_W, wm1, 256*256);
    k_cvt<<<(256*256+255)/256, 256>>>(m2_W, wm2, 256*256);

    // A: transpose + norms
    k_transpose_norm<<<dim3(BN, 2), 128>>>(src_desc, dst_desc, srcd, nsqS, nrmS);

    // inner = src . dst with fused cosine maxes
    k_fill<<<32, 256>>>(maxDS, -3.4e38f, 2*BN);
    k_gemm_sim<<<dim3(NN/SGN, NN/SGM, 2), 256>>>(srcd, dstd, inner, nrmS, nrmD, maxDS, maxSD);
    k_knn_desc<<<dim3(NN, BB), 256>>>(inner, nsqS, nsqD, idx);
    k_simgather<<<PP/256, 256>>>(inner, nrmS, nrmD, maxDS, maxSD, idx, sdc, dsc);

    // B: neighborhood descriptors — both clouds batched
    k_knn_xyz<<<dim3(NN, BB, 2), 256>>>(src_xyz, dst_xyz, sidx);
    k_build_nbr_f<<<2*PP, 128>>>(src_xyz, dst_xyz, srcd, sidx, fbuf);
    k_gemm_tc<<<dim3(CC/TCN, (2*PP)/TCM), 256>>>(fbuf, w2p, y0, 2*PP, CC, 144,
        nullptr, nullptr, nullptr, nullptr, 0.f, slot(0), slot(0)+512, PP);
    k_gemm_tc<<<dim3(CC/TCN, (2*PP)/TCM), 256>>>(y0, wc2, y1, 2*PP, CC, CC,
        slot(0), slot(0)+512, c2_g, c2_b, invPP, slot(1), slot(1)+512, PP);
    k_gemm_tc<<<dim3(CC/TCN, (2*PP)/TCM), 256>>>(y1, wc2 + CC*CC, y0, 2*PP, CC, CC,
        slot(1), slot(1)+512, c2_g + CC, c2_b + CC, invPP, slot(2), slot(2)+512, PP);
    k_nbr_final<<<2*BN, 256>>>(y0, slot(2), slot(2)+512, c2_g + 2*CC, c2_b + 2*CC, invPP,
                               sidx, srcd, srcnbr);

    // nbr cosine sims
    k_rownorm<<<2*BN, 128>>>(srcnbr, nrm2S);
    k_fill<<<32, 256>>>(maxDS, -3.4e38f, 2*BN);
    k_gemm_sim<<<dim3(NN/SGN, NN/SGM, 2), 256>>>(srcnbr, srcnbr + (long)BN*CC, inner,
                                                 nrm2S, nrm2D, maxDS, maxSD);
    k_simgather<<<PP/256, 256>>>(inner, nrm2S, nrm2D, maxDS, maxSD, idx, sdn, dsn);

    // C: main feature conv + attention
    k_build_feats<<<PP, 128>>>(src_xyz, dst_xyz, srcd, dstd, src_w, dst_w,
                               sdc, dsc, sdn, dsn, idx, fbuf);
    k_gemm_tc<<<dim3(256/TCN, PP/TCM), 256>>>(fbuf, wc10, y0, PP, 256, 272,
        nullptr, nullptr, nullptr, nullptr, 0.f, slot(3), slot(3)+512, 0);
    k_gemm_tc<<<dim3(256/TCN, PP/TCM), 256>>>(y0, wc1, y1, PP, 256, 256,
        slot(3), slot(3)+512, c1_g, c1_b, invPP, slot(4), slot(4)+512, 0);
    k_gemm_tc<<<dim3(256/TCN, PP/TCM), 256>>>(y1, wc1 + 256*256, y0, PP, 256, 256,
        slot(4), slot(4)+512, c1_g + 256, c1_b + 256, invPP, slot(5), slot(5)+512, 0);
    k_attention<<<BN, 256>>>(y0, slot(5), slot(5)+512, c1_g + 512, c1_b + 512, invPP,
                             idx, dst_xyz, outC, att);

    // D: MLP head
    k_gemm_tc<<<dim3(256/TCN, BN/TCM), 256>>>(att, wm1, mb1, BN, 256, 256,
        nullptr, nullptr, nullptr, nullptr, 0.f, slot(6), slot(6)+512, 0);
    k_gemm_tc<<<dim3(256/TCN, BN/TCM), 256>>>(mb1, wm2, mb2, BN, 256, 256,
        slot(6), slot(6)+512, m1_g, m1_b, invBN, slot(7), slot(7)+512, 0);
    k_mlp3<<<BN, 256>>>(mb2, slot(7), slot(7)+512, m2_g, m2_b, invBN, m3_W, m3_b, outW);
}